// round 1
// baseline (speedup 1.0000x reference)
#include <cuda_runtime.h>
#include <math.h>

#define B_    16
#define T_    8192
#define F_    256
#define NL_   3
#define KS_   3
#define NB_   10
#define PROJ_ 29
#define BT_   (B_*T_)
#define TBND  5.0f

// Scratch (allocation-free rule: __device__ globals)
__device__ float g_h[(size_t)BT_ * F_];    // 134 MB
__device__ float g_y[(size_t)BT_ * F_];    // 134 MB
__device__ float g_lad[BT_];

// ---------------------------------------------------------------------------
// Kernel 1: h[b,t,f] = x0[b,t] * w_pre[f] + b_pre[f]   (rank-1 expand)
// ---------------------------------------------------------------------------
__global__ void pre_kernel(const float* __restrict__ x,
                           const float* __restrict__ w_pre,
                           const float* __restrict__ b_pre) {
    int tok = blockIdx.x;
    int f   = threadIdx.x;
    float x0 = x[(size_t)tok * 2];
    g_h[(size_t)tok * F_ + f] = x0 * w_pre[f] + b_pre[f];
}

// ---------------------------------------------------------------------------
// Kernel 2: y = gelu(LN1(depthwise_dilated_conv(h * mask))), one block/token
// ---------------------------------------------------------------------------
__global__ void conv_ln_gelu_kernel(const float* __restrict__ mask,
                                    const float* __restrict__ dwk,   // [KS,F]
                                    const float* __restrict__ dwb,   // [F]
                                    const float* __restrict__ g1,
                                    const float* __restrict__ b1,
                                    int dil) {
    int tok = blockIdx.x;
    int t   = tok & (T_ - 1);
    int f   = threadIdx.x;

    float acc = dwb[f];
    float k0 = dwk[f], k1 = dwk[F_ + f], k2 = dwk[2 * F_ + f];
    if (t - dil >= 0)
        acc += g_h[(size_t)(tok - dil) * F_ + f] * mask[tok - dil] * k0;
    acc += g_h[(size_t)tok * F_ + f] * mask[tok] * k1;
    if (t + dil < T_)
        acc += g_h[(size_t)(tok + dil) * F_ + f] * mask[tok + dil] * k2;

    // block LN over 256 features
    float s = acc, ss = acc * acc;
    #pragma unroll
    for (int o = 16; o; o >>= 1) {
        s  += __shfl_down_sync(0xFFFFFFFFu, s,  o);
        ss += __shfl_down_sync(0xFFFFFFFFu, ss, o);
    }
    __shared__ float sh1[8], sh2[8];
    __shared__ float mean_s, rstd_s;
    int wid = f >> 5, lane = f & 31;
    if (!lane) { sh1[wid] = s; sh2[wid] = ss; }
    __syncthreads();
    if (f == 0) {
        float S = 0.f, SS = 0.f;
        #pragma unroll
        for (int i = 0; i < 8; i++) { S += sh1[i]; SS += sh2[i]; }
        float mean = S * (1.0f / F_);
        float var  = SS * (1.0f / F_) - mean * mean;
        mean_s = mean;
        rstd_s = rsqrtf(var + 1e-5f);
    }
    __syncthreads();
    float v = (acc - mean_s) * rstd_s * g1[f] + b1[f];
    v = 0.5f * v * (1.0f + erff(v * 0.7071067811865476f));
    g_y[(size_t)tok * F_ + f] = v;
}

// ---------------------------------------------------------------------------
// Kernel 3: h += gelu(LN2(y @ w11 + b11)).
// Tile: 32 tokens x 256 cols, K tiled by 32. 256 threads, 4x8 per-thread tile.
// Each warp owns 4 complete token rows -> LN via warp shuffles.
// ---------------------------------------------------------------------------
__global__ void gemm_ln_res_kernel(const float* __restrict__ w11,  // [F,F] k-major
                                   const float* __restrict__ b11,
                                   const float* __restrict__ g2,
                                   const float* __restrict__ b2) {
    __shared__ float As[32][33];
    __shared__ float Bs[32][256];

    int tid = threadIdx.x;
    int tx  = tid & 31;      // N-group lane
    int ty  = tid >> 5;      // warp id -> token group
    int m0  = blockIdx.x * 32;

    float acc[4][8];
    #pragma unroll
    for (int mi = 0; mi < 4; mi++)
        #pragma unroll
        for (int ni = 0; ni < 8; ni++) acc[mi][ni] = 0.f;

    for (int kk = 0; kk < F_; kk += 32) {
        // A tile: 32 tokens x 32 k (coalesced along k)
        int ac = tid & 31, ar = tid >> 5;
        #pragma unroll
        for (int j = 0; j < 4; j++) {
            int row = ar + 8 * j;
            As[row][ac] = g_y[(size_t)(m0 + row) * F_ + kk + ac];
        }
        // B tile: 32 k x 256 n, float4 loads
        const float4* wp = reinterpret_cast<const float4*>(w11 + (size_t)kk * F_);
        #pragma unroll
        for (int j = 0; j < 8; j++) {
            int i = tid + 256 * j;
            int r = i >> 6, c = i & 63;
            reinterpret_cast<float4*>(&Bs[r][0])[c] = wp[r * 64 + c];
        }
        __syncthreads();

        #pragma unroll
        for (int k = 0; k < 32; k++) {
            float a[4], bb[8];
            #pragma unroll
            for (int mi = 0; mi < 4; mi++) a[mi] = As[ty + 8 * mi][k];
            #pragma unroll
            for (int ni = 0; ni < 8; ni++) bb[ni] = Bs[k][tx + 32 * ni];
            #pragma unroll
            for (int mi = 0; mi < 4; mi++)
                #pragma unroll
                for (int ni = 0; ni < 8; ni++) acc[mi][ni] += a[mi] * bb[ni];
        }
        __syncthreads();
    }

    // Epilogue: bias -> LN (warp-level, per token row) -> gelu -> residual add
    #pragma unroll
    for (int mi = 0; mi < 4; mi++) {
        int tok = m0 + ty + 8 * mi;
        float v[8];
        float s = 0.f, ss = 0.f;
        #pragma unroll
        for (int ni = 0; ni < 8; ni++) {
            v[ni] = acc[mi][ni] + b11[tx + 32 * ni];
            s  += v[ni];
            ss += v[ni] * v[ni];
        }
        #pragma unroll
        for (int o = 16; o; o >>= 1) {
            s  += __shfl_xor_sync(0xFFFFFFFFu, s,  o);
            ss += __shfl_xor_sync(0xFFFFFFFFu, ss, o);
        }
        float mean = s * (1.0f / F_);
        float rstd = rsqrtf(ss * (1.0f / F_) - mean * mean + 1e-5f);
        #pragma unroll
        for (int ni = 0; ni < 8; ni++) {
            int n = tx + 32 * ni;
            float z = (v[ni] - mean) * rstd * g2[n] + b2[n];
            z = 0.5f * z * (1.0f + erff(z * 0.7071067811865476f));
            g_h[(size_t)tok * F_ + n] += z;
        }
    }
}

// ---------------------------------------------------------------------------
// Kernel 4: per-token projection (256 -> 29) + RQ spline. One warp per token.
// ---------------------------------------------------------------------------
__device__ __forceinline__ float softplus_f(float v) {
    return fmaxf(v, 0.f) + log1pf(expf(-fabsf(v)));
}

__global__ void proj_spline_kernel(const float* __restrict__ x,
                                   const float* __restrict__ mask,
                                   const float* __restrict__ w_proj, // [F, 29]
                                   const float* __restrict__ b_proj,
                                   float* __restrict__ out) {
    int wrp  = threadIdx.x >> 5;
    int lane = threadIdx.x & 31;
    int tok  = blockIdx.x * 8 + wrp;

    float m = mask[tok];
    float hv[8];
    #pragma unroll
    for (int j = 0; j < 8; j++)
        hv[j] = g_h[(size_t)tok * F_ + lane + 32 * j] * m;

    float proj[PROJ_];
    #pragma unroll
    for (int p = 0; p < PROJ_; p++) {
        float s = 0.f;
        #pragma unroll
        for (int j = 0; j < 8; j++)
            s += hv[j] * w_proj[(lane + 32 * j) * PROJ_ + p];
        #pragma unroll
        for (int o = 16; o; o >>= 1) s += __shfl_xor_sync(0xFFFFFFFFu, s, o);
        proj[p] = s;
    }

    if (lane == 0) {
        #pragma unroll
        for (int p = 0; p < PROJ_; p++) proj[p] = (proj[p] + b_proj[p]) * m;

        const float scale = 0.0625f;  // 1/sqrt(256)

        // widths
        float cw[NB_ + 1], ww[NB_];
        {
            float mx = proj[0] * scale;
            #pragma unroll
            for (int j = 1; j < NB_; j++) mx = fmaxf(mx, proj[j] * scale);
            float e[NB_], sum = 0.f;
            #pragma unroll
            for (int j = 0; j < NB_; j++) { e[j] = expf(proj[j] * scale - mx); sum += e[j]; }
            float inv = 1.0f / sum;
            float cum = 0.f;
            cw[0] = -TBND;
            #pragma unroll
            for (int j = 0; j < NB_; j++) {
                float wj = 0.001f + (1.0f - 0.001f * NB_) * (e[j] * inv);
                cum += wj;
                cw[j + 1] = 2.0f * TBND * cum - TBND;
            }
            cw[NB_] = TBND;
            #pragma unroll
            for (int j = 0; j < NB_; j++) ww[j] = cw[j + 1] - cw[j];
        }
        // heights
        float ch[NB_ + 1], hh[NB_];
        {
            float mx = proj[NB_] * scale;
            #pragma unroll
            for (int j = 1; j < NB_; j++) mx = fmaxf(mx, proj[NB_ + j] * scale);
            float e[NB_], sum = 0.f;
            #pragma unroll
            for (int j = 0; j < NB_; j++) { e[j] = expf(proj[NB_ + j] * scale - mx); sum += e[j]; }
            float inv = 1.0f / sum;
            float cum = 0.f;
            ch[0] = -TBND;
            #pragma unroll
            for (int j = 0; j < NB_; j++) {
                float hj = 0.001f + (1.0f - 0.001f * NB_) * (e[j] * inv);
                cum += hj;
                ch[j + 1] = 2.0f * TBND * cum - TBND;
            }
            ch[NB_] = TBND;
            #pragma unroll
            for (int j = 0; j < NB_; j++) hh[j] = ch[j + 1] - ch[j];
        }
        // derivatives (K+1 = 11), boundary padded with log(expm1(1-md))
        float d[NB_ + 1];
        float cst = logf(expm1f(1.0f - 0.001f));
        d[0]   = 0.001f + softplus_f(cst);
        d[NB_] = d[0];
        #pragma unroll
        for (int k = 1; k < NB_; k++) d[k] = 0.001f + softplus_f(proj[2 * NB_ + k - 1]);

        float x1 = x[(size_t)tok * 2 + 1];
        float xc = fminf(fmaxf(x1, -TBND), TBND);
        int idx = 0;
        #pragma unroll
        for (int j = 1; j <= NB_; j++) idx += (xc >= cw[j]) ? 1 : 0;
        if (idx > NB_ - 1) idx = NB_ - 1;

        float icw = cw[idx], ibw = ww[idx];
        float ich = ch[idx], ibh = hh[idx];
        float delta = ibh / ibw;
        float dk = d[idx], dk1 = d[idx + 1];
        float th   = (xc - icw) / ibw;
        float th1m = th * (1.0f - th);
        float denom = delta + (dk + dk1 - 2.0f * delta) * th1m;
        float num   = ibh * (delta * th * th + dk * th1m);
        float yv    = ich + num / denom;
        float omth  = 1.0f - th;
        float dnum  = delta * delta * (dk1 * th * th + 2.0f * delta * th1m + dk * omth * omth);
        float lad   = logf(dnum) - 2.0f * logf(denom);

        bool inside = (x1 >= -TBND) && (x1 <= TBND);
        float y1 = inside ? yv : x1;
        lad = inside ? lad : 0.0f;

        out[(size_t)tok * 2]     = x[(size_t)tok * 2] * m;
        out[(size_t)tok * 2 + 1] = y1 * m;
        g_lad[tok] = lad * m;
    }
}

// ---------------------------------------------------------------------------
// Kernel 5: deterministic per-batch logdet reduction
// ---------------------------------------------------------------------------
__global__ void logdet_kernel(float* __restrict__ out) {
    int b = blockIdx.x, tid = threadIdx.x;
    float s = 0.f;
    for (int j = tid; j < T_; j += 256) s += g_lad[b * T_ + j];
    __shared__ float sh[256];
    sh[tid] = s;
    __syncthreads();
    #pragma unroll
    for (int o = 128; o; o >>= 1) {
        if (tid < o) sh[tid] += sh[tid + o];
        __syncthreads();
    }
    if (tid == 0) out[(size_t)BT_ * 2 + b] = sh[0];
}

// ---------------------------------------------------------------------------
extern "C" void kernel_launch(void* const* d_in, const int* in_sizes, int n_in,
                              void* d_out, int out_size) {
    const float* x      = (const float*)d_in[0];
    const float* mask   = (const float*)d_in[1];
    const float* w_pre  = (const float*)d_in[2];
    const float* b_pre  = (const float*)d_in[3];
    const float* dw_k   = (const float*)d_in[4];
    const float* dw_b   = (const float*)d_in[5];
    const float* w11    = (const float*)d_in[6];
    const float* b11    = (const float*)d_in[7];
    const float* ln1g   = (const float*)d_in[8];
    const float* ln1b   = (const float*)d_in[9];
    const float* ln2g   = (const float*)d_in[10];
    const float* ln2b   = (const float*)d_in[11];
    const float* w_proj = (const float*)d_in[12];
    const float* b_proj = (const float*)d_in[13];
    float* out = (float*)d_out;

    pre_kernel<<<BT_, 256>>>(x, w_pre, b_pre);

    int dil = 1;
    for (int i = 0; i < NL_; i++) {
        conv_ln_gelu_kernel<<<BT_, 256>>>(mask,
                                          dw_k + (size_t)i * KS_ * F_,
                                          dw_b + (size_t)i * F_,
                                          ln1g + (size_t)i * F_,
                                          ln1b + (size_t)i * F_,
                                          dil);
        gemm_ln_res_kernel<<<BT_ / 32, 256>>>(w11 + (size_t)i * F_ * F_,
                                              b11 + (size_t)i * F_,
                                              ln2g + (size_t)i * F_,
                                              ln2b + (size_t)i * F_);
        dil *= KS_;
    }

    proj_spline_kernel<<<BT_ / 8, 256>>>(x, mask, w_proj, b_proj, out);
    logdet_kernel<<<B_, 256>>>(out);
}

// round 4
// speedup vs baseline: 1.6848x; 1.6848x over previous
#include <cuda_runtime.h>
#include <cuda_bf16.h>
#include <math.h>
#include <stdint.h>
#include <cstdint>

#define B_    16
#define T_    8192
#define F_    256
#define NL_   3
#define KS_   3
#define NB_   10
#define PROJ_ 29
#define BT_   (B_*T_)
#define TBND  5.0f

// Scratch (allocation-free rule: __device__ globals)
__device__ float g_h[(size_t)BT_ * F_];    // 134 MB
__device__ float g_y[(size_t)BT_ * F_];    // 134 MB
__device__ float g_lad[BT_];
// B fragments, mma-ordered: [l][nt(32)][ks(16)][lane(32)] uint4 = (b0_hi,b1_hi,b0_lo,b1_lo)
__device__ uint4 g_Bfrag[NL_ * 32 * 16 * 32];

__device__ __forceinline__ float gelu_f(float v) {
    return 0.5f * v * (1.0f + erff(v * 0.7071067811865476f));
}

__device__ __forceinline__ void mma16816(float* d, const uint32_t* a,
                                         uint32_t b0, uint32_t b1) {
    asm volatile(
        "mma.sync.aligned.m16n8k16.row.col.f32.bf16.bf16.f32 "
        "{%0,%1,%2,%3}, {%4,%5,%6,%7}, {%8,%9}, {%0,%1,%2,%3};"
        : "+f"(d[0]), "+f"(d[1]), "+f"(d[2]), "+f"(d[3])
        : "r"(a[0]), "r"(a[1]), "r"(a[2]), "r"(a[3]), "r"(b0), "r"(b1));
}

__device__ __forceinline__ uint32_t pack_bf16x2(float x, float y) {
    __nv_bfloat162 p = __halves2bfloat162(__float2bfloat16(x), __float2bfloat16(y));
    return *reinterpret_cast<uint32_t*>(&p);
}

// ---------------------------------------------------------------------------
// Kernel 0: pack w11 into mma B fragments (hi/lo split)
// grid = NL*32*16 blocks of 32 threads; one uint4 per thread
// ---------------------------------------------------------------------------
__global__ void prep_bfrag_kernel(const float* __restrict__ w11) {
    int blk  = blockIdx.x;              // (l*32 + nt)*16 + ks
    int lane = threadIdx.x;
    int ks   = blk & 15;
    int nt   = (blk >> 4) & 31;
    int l    = blk >> 9;
    int tg   = lane >> 2, tid = lane & 3;
    int n    = nt * 8 + tg;
    int k0   = ks * 16 + tid * 2;

    const float* w = w11 + (size_t)l * F_ * F_;
    float v00 = w[(size_t)(k0    ) * F_ + n];
    float v01 = w[(size_t)(k0 + 1) * F_ + n];
    float v10 = w[(size_t)(k0 + 8) * F_ + n];
    float v11 = w[(size_t)(k0 + 9) * F_ + n];

    float h00 = __bfloat162float(__float2bfloat16(v00));
    float h01 = __bfloat162float(__float2bfloat16(v01));
    float h10 = __bfloat162float(__float2bfloat16(v10));
    float h11 = __bfloat162float(__float2bfloat16(v11));

    uint4 o;
    o.x = pack_bf16x2(v00, v01);                // b0_hi
    o.y = pack_bf16x2(v10, v11);                // b1_hi
    o.z = pack_bf16x2(v00 - h00, v01 - h01);    // b0_lo
    o.w = pack_bf16x2(v10 - h10, v11 - h11);    // b1_lo
    g_Bfrag[(size_t)blk * 32 + lane] = o;
}

// ---------------------------------------------------------------------------
// Kernel 1: h[b,t,f] = x0[b,t] * w_pre[f] + b_pre[f]
// ---------------------------------------------------------------------------
__global__ void pre_kernel(const float* __restrict__ x,
                           const float* __restrict__ w_pre,
                           const float* __restrict__ b_pre) {
    int gid = blockIdx.x * 256 + threadIdx.x;   // BT*64 total float4s
    int tok = gid >> 6;
    int c4  = gid & 63;
    float x0 = __ldg(&x[(size_t)tok * 2]);
    float4 w = reinterpret_cast<const float4*>(w_pre)[c4];
    float4 b = reinterpret_cast<const float4*>(b_pre)[c4];
    float4 o;
    o.x = x0 * w.x + b.x; o.y = x0 * w.y + b.y;
    o.z = x0 * w.z + b.z; o.w = x0 * w.w + b.w;
    reinterpret_cast<float4*>(g_h)[gid] = o;
}

// ---------------------------------------------------------------------------
// Kernel 2: y = gelu(LN1(depthwise dilated conv(h * mask))); warp per token
// ---------------------------------------------------------------------------
__global__ void conv_ln_gelu_kernel(const float* __restrict__ mask,
                                    const float* __restrict__ dwk,   // [KS,F]
                                    const float* __restrict__ dwb,
                                    const float* __restrict__ g1,
                                    const float* __restrict__ b1,
                                    int dil) {
    int wid  = threadIdx.x >> 5;
    int lane = threadIdx.x & 31;
    int tok  = blockIdx.x * 8 + wid;
    int t    = tok & (T_ - 1);

    float a[8];
    {
        float4 b0 = reinterpret_cast<const float4*>(dwb)[lane];
        float4 b1v = reinterpret_cast<const float4*>(dwb)[lane + 32];
        a[0] = b0.x; a[1] = b0.y; a[2] = b0.z; a[3] = b0.w;
        a[4] = b1v.x; a[5] = b1v.y; a[6] = b1v.z; a[7] = b1v.w;
    }
    const float4* dk4 = reinterpret_cast<const float4*>(dwk);

    #pragma unroll
    for (int tap = 0; tap < 3; tap++) {
        int off = (tap - 1) * dil;
        int tt = t + off;
        if (tt >= 0 && tt < T_) {
            float mm = __ldg(&mask[tok + off]);
            const float4* hr = reinterpret_cast<const float4*>(g_h + (size_t)(tok + off) * F_);
            float4 h0 = hr[lane], h1 = hr[lane + 32];
            float4 k0 = dk4[tap * 64 + lane], k1 = dk4[tap * 64 + lane + 32];
            a[0] += h0.x * mm * k0.x; a[1] += h0.y * mm * k0.y;
            a[2] += h0.z * mm * k0.z; a[3] += h0.w * mm * k0.w;
            a[4] += h1.x * mm * k1.x; a[5] += h1.y * mm * k1.y;
            a[6] += h1.z * mm * k1.z; a[7] += h1.w * mm * k1.w;
        }
    }

    float s = 0.f, ss = 0.f;
    #pragma unroll
    for (int j = 0; j < 8; j++) { s += a[j]; ss += a[j] * a[j]; }
    #pragma unroll
    for (int o = 16; o; o >>= 1) {
        s  += __shfl_xor_sync(0xFFFFFFFFu, s,  o);
        ss += __shfl_xor_sync(0xFFFFFFFFu, ss, o);
    }
    float mean = s * (1.0f / F_);
    float rstd = rsqrtf(ss * (1.0f / F_) - mean * mean + 1e-5f);

    float4 gg0 = reinterpret_cast<const float4*>(g1)[lane];
    float4 gg1 = reinterpret_cast<const float4*>(g1)[lane + 32];
    float4 bb0 = reinterpret_cast<const float4*>(b1)[lane];
    float4 bb1 = reinterpret_cast<const float4*>(b1)[lane + 32];
    float garr[8] = {gg0.x, gg0.y, gg0.z, gg0.w, gg1.x, gg1.y, gg1.z, gg1.w};
    float barr[8] = {bb0.x, bb0.y, bb0.z, bb0.w, bb1.x, bb1.y, bb1.z, bb1.w};

    float4 o0, o1;
    float r[8];
    #pragma unroll
    for (int j = 0; j < 8; j++) {
        float v = (a[j] - mean) * rstd * garr[j] + barr[j];
        r[j] = gelu_f(v);
    }
    o0.x = r[0]; o0.y = r[1]; o0.z = r[2]; o0.w = r[3];
    o1.x = r[4]; o1.y = r[5]; o1.z = r[6]; o1.w = r[7];
    float4* yr = reinterpret_cast<float4*>(g_y + (size_t)tok * F_);
    yr[lane] = o0;
    yr[lane + 32] = o1;
}

// ---------------------------------------------------------------------------
// Kernel 3: mma.sync GEMM  h += gelu(LN2(y @ w11 + b11))
// CTA: 128 tokens x 256 cols, K=256. 512 threads = 16 warps (2 M x 8 N),
// warp tile 64x32. A converted fp32->bf16 hi/lo into SMEM; B from g_Bfrag (L2).
// ---------------------------------------------------------------------------
#define AROW   264                     // bf16 row stride (528B -> conflict-free)
#define GSMEM  (2 * 128 * AROW * 2 + 256)   // A hi + lo + align slack

__global__ void __launch_bounds__(512, 1)
gemm_mma_kernel(int layer,
                const float* __restrict__ b11,
                const float* __restrict__ g2,
                const float* __restrict__ b2) {
    extern __shared__ char dyn[];
    // 16B-align base
    char* basep = (char*)(((uintptr_t)dyn + 15) & ~(uintptr_t)15);
    __nv_bfloat16* Ahi = reinterpret_cast<__nv_bfloat16*>(basep);
    __nv_bfloat16* Alo = Ahi + 128 * AROW;
    float* stag = reinterpret_cast<float*>(basep);   // reused post-mainloop [128][260]
    const int SROW = 260;

    const int tid  = threadIdx.x;
    const int wid  = tid >> 5;
    const int lane = tid & 31;
    const int tg   = lane >> 2, tq = lane & 3;
    const int wm   = wid >> 3;          // 0..1  -> m_base
    const int wn   = wid & 7;           // 0..7  -> n group
    const int m0   = blockIdx.x * 128;

    // ---- load A (128 x 256 fp32) -> bf16 hi/lo SMEM ----
    {
        int row = tid >> 2;
        int kq  = (tid & 3) * 64;
        const float4* src = reinterpret_cast<const float4*>(
            g_y + (size_t)(m0 + row) * F_ + kq);
        #pragma unroll
        for (int j = 0; j < 16; j++) {
            float4 v = src[j];
            float hx = __bfloat162float(__float2bfloat16(v.x));
            float hy = __bfloat162float(__float2bfloat16(v.y));
            float hz = __bfloat162float(__float2bfloat16(v.z));
            float hw = __bfloat162float(__float2bfloat16(v.w));
            uint2 hp, lp;
            hp.x = pack_bf16x2(v.x, v.y);
            hp.y = pack_bf16x2(v.z, v.w);
            lp.x = pack_bf16x2(v.x - hx, v.y - hy);
            lp.y = pack_bf16x2(v.z - hz, v.w - hw);
            int c = kq + j * 4;
            *reinterpret_cast<uint2*>(Ahi + row * AROW + c) = hp;
            *reinterpret_cast<uint2*>(Alo + row * AROW + c) = lp;
        }
    }
    __syncthreads();

    // ---- mainloop ----
    float d[4][4][4];
    #pragma unroll
    for (int mt = 0; mt < 4; mt++)
        #pragma unroll
        for (int nt = 0; nt < 4; nt++)
            #pragma unroll
            for (int q = 0; q < 4; q++) d[mt][nt][q] = 0.f;

    const uint4* Bbase = g_Bfrag + ((size_t)(layer * 32 + wn * 4) * 16) * 32 + lane;
    uint4 bcur[4], bnxt[4];
    #pragma unroll
    for (int nt = 0; nt < 4; nt++) bcur[nt] = __ldg(&Bbase[(nt * 16 + 0) * 32]);

    const int m_base = wm * 64;
    #pragma unroll 1
    for (int ks = 0; ks < 16; ks++) {
        if (ks < 15) {
            #pragma unroll
            for (int nt = 0; nt < 4; nt++)
                bnxt[nt] = __ldg(&Bbase[(nt * 16 + ks + 1) * 32]);
        }
        const int c0 = ks * 16 + tq * 2;
        #pragma unroll
        for (int mt = 0; mt < 4; mt++) {
            const int r0 = m_base + mt * 16 + tg;
            uint32_t ah[4], al[4];
            ah[0] = *reinterpret_cast<const uint32_t*>(Ahi + r0 * AROW + c0);
            ah[1] = *reinterpret_cast<const uint32_t*>(Ahi + (r0 + 8) * AROW + c0);
            ah[2] = *reinterpret_cast<const uint32_t*>(Ahi + r0 * AROW + c0 + 8);
            ah[3] = *reinterpret_cast<const uint32_t*>(Ahi + (r0 + 8) * AROW + c0 + 8);
            al[0] = *reinterpret_cast<const uint32_t*>(Alo + r0 * AROW + c0);
            al[1] = *reinterpret_cast<const uint32_t*>(Alo + (r0 + 8) * AROW + c0);
            al[2] = *reinterpret_cast<const uint32_t*>(Alo + r0 * AROW + c0 + 8);
            al[3] = *reinterpret_cast<const uint32_t*>(Alo + (r0 + 8) * AROW + c0 + 8);
            #pragma unroll
            for (int nt = 0; nt < 4; nt++) {
                mma16816(d[mt][nt], ah, bcur[nt].x, bcur[nt].y);  // Ah*Bh
                mma16816(d[mt][nt], ah, bcur[nt].z, bcur[nt].w);  // Ah*Bl
                mma16816(d[mt][nt], al, bcur[nt].x, bcur[nt].y);  // Al*Bh
            }
        }
        #pragma unroll
        for (int nt = 0; nt < 4; nt++) bcur[nt] = bnxt[nt];
    }

    // ---- stage accum to SMEM (reuse A region) ----
    __syncthreads();
    #pragma unroll
    for (int mt = 0; mt < 4; mt++) {
        int r0 = m_base + mt * 16 + tg;
        #pragma unroll
        for (int nt = 0; nt < 4; nt++) {
            int col = wn * 32 + nt * 8 + tq * 2;
            *reinterpret_cast<float2*>(&stag[r0 * SROW + col]) =
                make_float2(d[mt][nt][0], d[mt][nt][1]);
            *reinterpret_cast<float2*>(&stag[(r0 + 8) * SROW + col]) =
                make_float2(d[mt][nt][2], d[mt][nt][3]);
        }
    }
    __syncthreads();

    // ---- LN2 + gelu + residual: each warp 8 rows, lane covers 8 cols ----
    #pragma unroll 1
    for (int i = 0; i < 8; i++) {
        int row = wid * 8 + i;
        float4 f0 = *reinterpret_cast<const float4*>(&stag[row * SROW + lane * 8]);
        float4 f1 = *reinterpret_cast<const float4*>(&stag[row * SROW + lane * 8 + 4]);
        float4 bb0 = reinterpret_cast<const float4*>(b11)[lane * 2];
        float4 bb1 = reinterpret_cast<const float4*>(b11)[lane * 2 + 1];
        float v[8] = {f0.x + bb0.x, f0.y + bb0.y, f0.z + bb0.z, f0.w + bb0.w,
                      f1.x + bb1.x, f1.y + bb1.y, f1.z + bb1.z, f1.w + bb1.w};
        float s = 0.f, ss = 0.f;
        #pragma unroll
        for (int j = 0; j < 8; j++) { s += v[j]; ss += v[j] * v[j]; }
        #pragma unroll
        for (int o = 16; o; o >>= 1) {
            s  += __shfl_xor_sync(0xFFFFFFFFu, s,  o);
            ss += __shfl_xor_sync(0xFFFFFFFFu, ss, o);
        }
        float mean = s * (1.0f / F_);
        float rstd = rsqrtf(ss * (1.0f / F_) - mean * mean + 1e-5f);

        float4 gg0 = reinterpret_cast<const float4*>(g2)[lane * 2];
        float4 gg1 = reinterpret_cast<const float4*>(g2)[lane * 2 + 1];
        float4 zb0 = reinterpret_cast<const float4*>(b2)[lane * 2];
        float4 zb1 = reinterpret_cast<const float4*>(b2)[lane * 2 + 1];
        float garr[8] = {gg0.x, gg0.y, gg0.z, gg0.w, gg1.x, gg1.y, gg1.z, gg1.w};
        float barr[8] = {zb0.x, zb0.y, zb0.z, zb0.w, zb1.x, zb1.y, zb1.z, zb1.w};

        float4* hp = reinterpret_cast<float4*>(g_h + (size_t)(m0 + row) * F_ + lane * 8);
        float4 h0 = hp[0], h1 = hp[1];
        float hv[8] = {h0.x, h0.y, h0.z, h0.w, h1.x, h1.y, h1.z, h1.w};
        #pragma unroll
        for (int j = 0; j < 8; j++) {
            float z = (v[j] - mean) * rstd * garr[j] + barr[j];
            hv[j] += gelu_f(z);
        }
        hp[0] = make_float4(hv[0], hv[1], hv[2], hv[3]);
        hp[1] = make_float4(hv[4], hv[5], hv[6], hv[7]);
    }
}

// ---------------------------------------------------------------------------
// Kernel 4: per-token projection (256 -> 29) + RQ spline. One warp per token.
// ---------------------------------------------------------------------------
__device__ __forceinline__ float softplus_f(float v) {
    return fmaxf(v, 0.f) + log1pf(expf(-fabsf(v)));
}

__global__ void proj_spline_kernel(const float* __restrict__ x,
                                   const float* __restrict__ mask,
                                   const float* __restrict__ w_proj, // [F, 29]
                                   const float* __restrict__ b_proj,
                                   float* __restrict__ out) {
    int wrp  = threadIdx.x >> 5;
    int lane = threadIdx.x & 31;
    int tok  = blockIdx.x * 8 + wrp;

    float m = mask[tok];
    float hv[8];
    #pragma unroll
    for (int j = 0; j < 8; j++)
        hv[j] = g_h[(size_t)tok * F_ + lane + 32 * j] * m;

    float proj[PROJ_];
    #pragma unroll
    for (int p = 0; p < PROJ_; p++) {
        float s = 0.f;
        #pragma unroll
        for (int j = 0; j < 8; j++)
            s += hv[j] * w_proj[(lane + 32 * j) * PROJ_ + p];
        #pragma unroll
        for (int o = 16; o; o >>= 1) s += __shfl_xor_sync(0xFFFFFFFFu, s, o);
        proj[p] = s;
    }

    if (lane == 0) {
        #pragma unroll
        for (int p = 0; p < PROJ_; p++) proj[p] = (proj[p] + b_proj[p]) * m;

        const float scale = 0.0625f;  // 1/sqrt(256)

        float cw[NB_ + 1], ww[NB_];
        {
            float mx = proj[0] * scale;
            #pragma unroll
            for (int j = 1; j < NB_; j++) mx = fmaxf(mx, proj[j] * scale);
            float e[NB_], sum = 0.f;
            #pragma unroll
            for (int j = 0; j < NB_; j++) { e[j] = expf(proj[j] * scale - mx); sum += e[j]; }
            float inv = 1.0f / sum;
            float cum = 0.f;
            cw[0] = -TBND;
            #pragma unroll
            for (int j = 0; j < NB_; j++) {
                float wj = 0.001f + (1.0f - 0.001f * NB_) * (e[j] * inv);
                cum += wj;
                cw[j + 1] = 2.0f * TBND * cum - TBND;
            }
            cw[NB_] = TBND;
            #pragma unroll
            for (int j = 0; j < NB_; j++) ww[j] = cw[j + 1] - cw[j];
        }
        float ch[NB_ + 1], hh[NB_];
        {
            float mx = proj[NB_] * scale;
            #pragma unroll
            for (int j = 1; j < NB_; j++) mx = fmaxf(mx, proj[NB_ + j] * scale);
            float e[NB_], sum = 0.f;
            #pragma unroll
            for (int j = 0; j < NB_; j++) { e[j] = expf(proj[NB_ + j] * scale - mx); sum += e[j]; }
            float inv = 1.0f / sum;
            float cum = 0.f;
            ch[0] = -TBND;
            #pragma unroll
            for (int j = 0; j < NB_; j++) {
                float hj = 0.001f + (1.0f - 0.001f * NB_) * (e[j] * inv);
                cum += hj;
                ch[j + 1] = 2.0f * TBND * cum - TBND;
            }
            ch[NB_] = TBND;
            #pragma unroll
            for (int j = 0; j < NB_; j++) hh[j] = ch[j + 1] - ch[j];
        }
        float d[NB_ + 1];
        float cst = logf(expm1f(1.0f - 0.001f));
        d[0]   = 0.001f + softplus_f(cst);
        d[NB_] = d[0];
        #pragma unroll
        for (int k = 1; k < NB_; k++) d[k] = 0.001f + softplus_f(proj[2 * NB_ + k - 1]);

        float x1 = x[(size_t)tok * 2 + 1];
        float xc = fminf(fmaxf(x1, -TBND), TBND);
        int idx = 0;
        #pragma unroll
        for (int j = 1; j <= NB_; j++) idx += (xc >= cw[j]) ? 1 : 0;
        if (idx > NB_ - 1) idx = NB_ - 1;

        float icw = cw[idx], ibw = ww[idx];
        float ich = ch[idx], ibh = hh[idx];
        float delta = ibh / ibw;
        float dk = d[idx], dk1 = d[idx + 1];
        float th   = (xc - icw) / ibw;
        float th1m = th * (1.0f - th);
        float denom = delta + (dk + dk1 - 2.0f * delta) * th1m;
        float num   = ibh * (delta * th * th + dk * th1m);
        float yv    = ich + num / denom;
        float omth  = 1.0f - th;
        float dnum  = delta * delta * (dk1 * th * th + 2.0f * delta * th1m + dk * omth * omth);
        float lad   = logf(dnum) - 2.0f * logf(denom);

        bool inside = (x1 >= -TBND) && (x1 <= TBND);
        float y1 = inside ? yv : x1;
        lad = inside ? lad : 0.0f;

        out[(size_t)tok * 2]     = x[(size_t)tok * 2] * m;
        out[(size_t)tok * 2 + 1] = y1 * m;
        g_lad[tok] = lad * m;
    }
}

// ---------------------------------------------------------------------------
// Kernel 5: deterministic per-batch logdet reduction
// ---------------------------------------------------------------------------
__global__ void logdet_kernel(float* __restrict__ out) {
    int b = blockIdx.x, tid = threadIdx.x;
    float s = 0.f;
    for (int j = tid; j < T_; j += 256) s += g_lad[b * T_ + j];
    __shared__ float sh[256];
    sh[tid] = s;
    __syncthreads();
    #pragma unroll
    for (int o = 128; o; o >>= 1) {
        if (tid < o) sh[tid] += sh[tid + o];
        __syncthreads();
    }
    if (tid == 0) out[(size_t)BT_ * 2 + b] = sh[0];
}

// ---------------------------------------------------------------------------
extern "C" void kernel_launch(void* const* d_in, const int* in_sizes, int n_in,
                              void* d_out, int out_size) {
    const float* x      = (const float*)d_in[0];
    const float* mask   = (const float*)d_in[1];
    const float* w_pre  = (const float*)d_in[2];
    const float* b_pre  = (const float*)d_in[3];
    const float* dw_k   = (const float*)d_in[4];
    const float* dw_b   = (const float*)d_in[5];
    const float* w11    = (const float*)d_in[6];
    const float* b11    = (const float*)d_in[7];
    const float* ln1g   = (const float*)d_in[8];
    const float* ln1b   = (const float*)d_in[9];
    const float* ln2g   = (const float*)d_in[10];
    const float* ln2b   = (const float*)d_in[11];
    const float* w_proj = (const float*)d_in[12];
    const float* b_proj = (const float*)d_in[13];
    float* out = (float*)d_out;

    cudaFuncSetAttribute(gemm_mma_kernel,
                         cudaFuncAttributeMaxDynamicSharedMemorySize, GSMEM);

    prep_bfrag_kernel<<<NL_ * 32 * 16, 32>>>(w11);
    pre_kernel<<<BT_ * 64 / 256, 256>>>(x, w_pre, b_pre);

    int dil = 1;
    for (int i = 0; i < NL_; i++) {
        conv_ln_gelu_kernel<<<BT_ / 8, 256>>>(mask,
                                              dw_k + (size_t)i * KS_ * F_,
                                              dw_b + (size_t)i * F_,
                                              ln1g + (size_t)i * F_,
                                              ln1b + (size_t)i * F_,
                                              dil);
        gemm_mma_kernel<<<BT_ / 128, 512, GSMEM>>>(i,
                                                   b11 + (size_t)i * F_,
                                                   ln2g + (size_t)i * F_,
                                                   ln2b + (size_t)i * F_);
        dil *= KS_;
    }

    proj_spline_kernel<<<BT_ / 8, 256>>>(x, mask, w_proj, b_proj, out);
    logdet_kernel<<<B_, 256>>>(out);
}

// round 5
// speedup vs baseline: 1.7062x; 1.0127x over previous
#include <cuda_runtime.h>
#include <cuda_bf16.h>
#include <math.h>
#include <stdint.h>
#include <cstdint>

#define B_    16
#define T_    8192
#define F_    256
#define NL_   3
#define KS_   3
#define NB_   10
#define PROJ_ 29
#define BT_   (B_*T_)
#define TBND  5.0f

// Scratch (allocation-free rule: __device__ globals)
__device__ float g_h[(size_t)BT_ * F_];    // 134 MB
__device__ float g_y[(size_t)BT_ * F_];    // 134 MB
__device__ float g_lad[BT_];
// B fragments, mma-ordered: [l][nt(32)][ks(16)][lane(32)] uint4 = (b0_hi,b1_hi,b0_lo,b1_lo)
__device__ uint4 g_Bfrag[NL_ * 32 * 16 * 32];

__device__ __forceinline__ float gelu_f(float v) {
    return 0.5f * v * (1.0f + erff(v * 0.7071067811865476f));
}

__device__ __forceinline__ void mma16816(float* d, const uint32_t* a,
                                         uint32_t b0, uint32_t b1) {
    asm volatile(
        "mma.sync.aligned.m16n8k16.row.col.f32.bf16.bf16.f32 "
        "{%0,%1,%2,%3}, {%4,%5,%6,%7}, {%8,%9}, {%0,%1,%2,%3};"
        : "+f"(d[0]), "+f"(d[1]), "+f"(d[2]), "+f"(d[3])
        : "r"(a[0]), "r"(a[1]), "r"(a[2]), "r"(a[3]), "r"(b0), "r"(b1));
}

__device__ __forceinline__ void ldmx4(uint32_t* r, uint32_t addr) {
    asm volatile("ldmatrix.sync.aligned.m8n8.x4.shared.b16 {%0,%1,%2,%3}, [%4];"
        : "=r"(r[0]), "=r"(r[1]), "=r"(r[2]), "=r"(r[3]) : "r"(addr));
}

__device__ __forceinline__ uint32_t pack_bf16x2(float x, float y) {
    __nv_bfloat162 p = __halves2bfloat162(__float2bfloat16(x), __float2bfloat16(y));
    return *reinterpret_cast<uint32_t*>(&p);
}

// ---------------------------------------------------------------------------
// Kernel 0: pack w11 into mma B fragments (hi/lo split)
// launched in two halves (blk_off) so ncu capture slot lands on conv
// ---------------------------------------------------------------------------
__global__ void prep_bfrag_kernel(const float* __restrict__ w11, int blk_off) {
    int blk  = blockIdx.x + blk_off;    // (l*32 + nt)*16 + ks
    int lane = threadIdx.x;
    int ks   = blk & 15;
    int nt   = (blk >> 4) & 31;
    int l    = blk >> 9;
    int tg   = lane >> 2, tid = lane & 3;
    int n    = nt * 8 + tg;
    int k0   = ks * 16 + tid * 2;

    const float* w = w11 + (size_t)l * F_ * F_;
    float v00 = w[(size_t)(k0    ) * F_ + n];
    float v01 = w[(size_t)(k0 + 1) * F_ + n];
    float v10 = w[(size_t)(k0 + 8) * F_ + n];
    float v11 = w[(size_t)(k0 + 9) * F_ + n];

    float h00 = __bfloat162float(__float2bfloat16(v00));
    float h01 = __bfloat162float(__float2bfloat16(v01));
    float h10 = __bfloat162float(__float2bfloat16(v10));
    float h11 = __bfloat162float(__float2bfloat16(v11));

    uint4 o;
    o.x = pack_bf16x2(v00, v01);                // b0_hi
    o.y = pack_bf16x2(v10, v11);                // b1_hi
    o.z = pack_bf16x2(v00 - h00, v01 - h01);    // b0_lo
    o.w = pack_bf16x2(v10 - h10, v11 - h11);    // b1_lo
    g_Bfrag[(size_t)blk * 32 + lane] = o;
}

// ---------------------------------------------------------------------------
// Kernel 1: h[b,t,f] = x0[b,t] * w_pre[f] + b_pre[f]
// ---------------------------------------------------------------------------
__global__ void pre_kernel(const float* __restrict__ x,
                           const float* __restrict__ w_pre,
                           const float* __restrict__ b_pre) {
    int gid = blockIdx.x * 256 + threadIdx.x;   // BT*64 total float4s
    int tok = gid >> 6;
    int c4  = gid & 63;
    float x0 = __ldg(&x[(size_t)tok * 2]);
    float4 w = reinterpret_cast<const float4*>(w_pre)[c4];
    float4 b = reinterpret_cast<const float4*>(b_pre)[c4];
    float4 o;
    o.x = x0 * w.x + b.x; o.y = x0 * w.y + b.y;
    o.z = x0 * w.z + b.z; o.w = x0 * w.w + b.w;
    reinterpret_cast<float4*>(g_h)[gid] = o;
}

// ---------------------------------------------------------------------------
// Kernel 2: y = gelu(LN1(depthwise dilated conv(h * mask))); warp per token
// params staged through SMEM once per block
// ---------------------------------------------------------------------------
__global__ void conv_ln_gelu_kernel(const float* __restrict__ mask,
                                    const float* __restrict__ dwk,   // [KS,F]
                                    const float* __restrict__ dwb,
                                    const float* __restrict__ g1,
                                    const float* __restrict__ b1,
                                    int dil) {
    __shared__ float4 s_k[3][64], s_b[64], s_g[64], s_bb[64];
    int tidx = threadIdx.x;
    if (tidx < 64) {
        s_k[0][tidx] = reinterpret_cast<const float4*>(dwk)[tidx];
        s_k[1][tidx] = reinterpret_cast<const float4*>(dwk)[64 + tidx];
        s_k[2][tidx] = reinterpret_cast<const float4*>(dwk)[128 + tidx];
    } else if (tidx < 128) {
        s_b[tidx - 64] = reinterpret_cast<const float4*>(dwb)[tidx - 64];
    } else if (tidx < 192) {
        s_g[tidx - 128] = reinterpret_cast<const float4*>(g1)[tidx - 128];
    } else {
        s_bb[tidx - 192] = reinterpret_cast<const float4*>(b1)[tidx - 192];
    }
    __syncthreads();

    int wid  = tidx >> 5;
    int lane = tidx & 31;
    int tok  = blockIdx.x * 8 + wid;
    int t    = tok & (T_ - 1);

    float a[8];
    {
        float4 b0 = s_b[lane], b1v = s_b[lane + 32];
        a[0] = b0.x; a[1] = b0.y; a[2] = b0.z; a[3] = b0.w;
        a[4] = b1v.x; a[5] = b1v.y; a[6] = b1v.z; a[7] = b1v.w;
    }

    #pragma unroll
    for (int tap = 0; tap < 3; tap++) {
        int off = (tap - 1) * dil;
        int tt = t + off;
        if (tt >= 0 && tt < T_) {
            float mm = __ldg(&mask[tok + off]);
            const float4* hr = reinterpret_cast<const float4*>(g_h + (size_t)(tok + off) * F_);
            float4 h0 = hr[lane], h1 = hr[lane + 32];
            float4 k0 = s_k[tap][lane], k1 = s_k[tap][lane + 32];
            a[0] += h0.x * mm * k0.x; a[1] += h0.y * mm * k0.y;
            a[2] += h0.z * mm * k0.z; a[3] += h0.w * mm * k0.w;
            a[4] += h1.x * mm * k1.x; a[5] += h1.y * mm * k1.y;
            a[6] += h1.z * mm * k1.z; a[7] += h1.w * mm * k1.w;
        }
    }

    float s = 0.f, ss = 0.f;
    #pragma unroll
    for (int j = 0; j < 8; j++) { s += a[j]; ss += a[j] * a[j]; }
    #pragma unroll
    for (int o = 16; o; o >>= 1) {
        s  += __shfl_xor_sync(0xFFFFFFFFu, s,  o);
        ss += __shfl_xor_sync(0xFFFFFFFFu, ss, o);
    }
    float mean = s * (1.0f / F_);
    float rstd = rsqrtf(ss * (1.0f / F_) - mean * mean + 1e-5f);

    float4 gg0 = s_g[lane], gg1 = s_g[lane + 32];
    float4 bb0 = s_bb[lane], bb1 = s_bb[lane + 32];
    float garr[8] = {gg0.x, gg0.y, gg0.z, gg0.w, gg1.x, gg1.y, gg1.z, gg1.w};
    float barr[8] = {bb0.x, bb0.y, bb0.z, bb0.w, bb1.x, bb1.y, bb1.z, bb1.w};

    float4 o0, o1;
    float r[8];
    #pragma unroll
    for (int j = 0; j < 8; j++) {
        float v = (a[j] - mean) * rstd * garr[j] + barr[j];
        r[j] = gelu_f(v);
    }
    o0.x = r[0]; o0.y = r[1]; o0.z = r[2]; o0.w = r[3];
    o1.x = r[4]; o1.y = r[5]; o1.z = r[6]; o1.w = r[7];
    float4* yr = reinterpret_cast<float4*>(g_y + (size_t)tok * F_);
    yr[lane] = o0;
    yr[lane + 32] = o1;
}

// ---------------------------------------------------------------------------
// Kernel 3: mma.sync GEMM  h += gelu(LN2(y @ w11 + b11))
// CTA: 128 tokens x 256 cols, K=256. 512 threads = 16 warps (2 M x 8 N),
// warp tile 64x32. A in SMEM bf16 hi/lo, loaded via ldmatrix.x4.
// ---------------------------------------------------------------------------
#define AROW   264                     // bf16 row stride (528B -> conflict-free)
#define GSMEM  (2 * 128 * AROW * 2 + 256)   // A hi + lo + align slack

__global__ void __launch_bounds__(512, 1)
gemm_mma_kernel(int layer,
                const float* __restrict__ b11,
                const float* __restrict__ g2,
                const float* __restrict__ b2) {
    extern __shared__ char dyn[];
    char* basep = (char*)(((uintptr_t)dyn + 15) & ~(uintptr_t)15);
    __nv_bfloat16* Ahi = reinterpret_cast<__nv_bfloat16*>(basep);
    __nv_bfloat16* Alo = Ahi + 128 * AROW;
    float* stag = reinterpret_cast<float*>(basep);   // reused post-mainloop [128][260]
    const int SROW = 260;

    const int tid  = threadIdx.x;
    const int wid  = tid >> 5;
    const int lane = tid & 31;
    const int tg   = lane >> 2, tq = lane & 3;
    const int wm   = wid >> 3;          // 0..1  -> m_base
    const int wn   = wid & 7;           // 0..7  -> n group
    const int m0   = blockIdx.x * 128;

    // ---- load A (128 x 256 fp32) -> bf16 hi/lo SMEM ----
    {
        int row = tid >> 2;
        int kq  = (tid & 3) * 64;
        const float4* src = reinterpret_cast<const float4*>(
            g_y + (size_t)(m0 + row) * F_ + kq);
        #pragma unroll
        for (int j = 0; j < 16; j++) {
            float4 v = src[j];
            float hx = __bfloat162float(__float2bfloat16(v.x));
            float hy = __bfloat162float(__float2bfloat16(v.y));
            float hz = __bfloat162float(__float2bfloat16(v.z));
            float hw = __bfloat162float(__float2bfloat16(v.w));
            uint2 hp, lp;
            hp.x = pack_bf16x2(v.x, v.y);
            hp.y = pack_bf16x2(v.z, v.w);
            lp.x = pack_bf16x2(v.x - hx, v.y - hy);
            lp.y = pack_bf16x2(v.z - hz, v.w - hw);
            int c = kq + j * 4;
            *reinterpret_cast<uint2*>(Ahi + row * AROW + c) = hp;
            *reinterpret_cast<uint2*>(Alo + row * AROW + c) = lp;
        }
    }
    __syncthreads();

    // ---- mainloop ----
    float d[4][4][4];
    #pragma unroll
    for (int mt = 0; mt < 4; mt++)
        #pragma unroll
        for (int nt = 0; nt < 4; nt++)
            #pragma unroll
            for (int q = 0; q < 4; q++) d[mt][nt][q] = 0.f;

    const uint4* Bbase = g_Bfrag + ((size_t)(layer * 32 + wn * 4) * 16) * 32 + lane;
    uint4 bcur[4], bnxt[4];
    #pragma unroll
    for (int nt = 0; nt < 4; nt++) bcur[nt] = __ldg(&Bbase[(nt * 16 + 0) * 32]);

    const int m_base = wm * 64;
    // ldmatrix base addresses (per mt), hi and lo
    uint32_t a_hi_addr[4], a_lo_addr[4];
    {
        int r = lane & 15;
        int cb = (lane >> 4) * 16;      // 16-byte column offset
        #pragma unroll
        for (int mt = 0; mt < 4; mt++) {
            int row = m_base + mt * 16 + r;
            a_hi_addr[mt] = (uint32_t)__cvta_generic_to_shared(Ahi + row * AROW) + cb;
            a_lo_addr[mt] = (uint32_t)__cvta_generic_to_shared(Alo + row * AROW) + cb;
        }
    }

    #pragma unroll 1
    for (int ks = 0; ks < 16; ks++) {
        if (ks < 15) {
            #pragma unroll
            for (int nt = 0; nt < 4; nt++)
                bnxt[nt] = __ldg(&Bbase[(nt * 16 + ks + 1) * 32]);
        }
        const uint32_t koff = ks * 32;  // 16 bf16 = 32 bytes per k-step
        #pragma unroll
        for (int mt = 0; mt < 4; mt++) {
            uint32_t ah[4], al[4];
            ldmx4(ah, a_hi_addr[mt] + koff);
            ldmx4(al, a_lo_addr[mt] + koff);
            #pragma unroll
            for (int nt = 0; nt < 4; nt++) {
                mma16816(d[mt][nt], ah, bcur[nt].x, bcur[nt].y);  // Ah*Bh
                mma16816(d[mt][nt], ah, bcur[nt].z, bcur[nt].w);  // Ah*Bl
                mma16816(d[mt][nt], al, bcur[nt].x, bcur[nt].y);  // Al*Bh
            }
        }
        #pragma unroll
        for (int nt = 0; nt < 4; nt++) bcur[nt] = bnxt[nt];
    }

    // ---- stage accum to SMEM (reuse A region) ----
    __syncthreads();
    #pragma unroll
    for (int mt = 0; mt < 4; mt++) {
        int r0 = m_base + mt * 16 + tg;
        #pragma unroll
        for (int nt = 0; nt < 4; nt++) {
            int col = wn * 32 + nt * 8 + tq * 2;
            *reinterpret_cast<float2*>(&stag[r0 * SROW + col]) =
                make_float2(d[mt][nt][0], d[mt][nt][1]);
            *reinterpret_cast<float2*>(&stag[(r0 + 8) * SROW + col]) =
                make_float2(d[mt][nt][2], d[mt][nt][3]);
        }
    }
    __syncthreads();

    // ---- LN2 + gelu + residual: each warp 8 rows, lane covers 8 cols ----
    #pragma unroll 1
    for (int i = 0; i < 8; i++) {
        int row = wid * 8 + i;
        float4 f0 = *reinterpret_cast<const float4*>(&stag[row * SROW + lane * 8]);
        float4 f1 = *reinterpret_cast<const float4*>(&stag[row * SROW + lane * 8 + 4]);
        float4 bb0 = reinterpret_cast<const float4*>(b11)[lane * 2];
        float4 bb1 = reinterpret_cast<const float4*>(b11)[lane * 2 + 1];
        float v[8] = {f0.x + bb0.x, f0.y + bb0.y, f0.z + bb0.z, f0.w + bb0.w,
                      f1.x + bb1.x, f1.y + bb1.y, f1.z + bb1.z, f1.w + bb1.w};
        float s = 0.f, ss = 0.f;
        #pragma unroll
        for (int j = 0; j < 8; j++) { s += v[j]; ss += v[j] * v[j]; }
        #pragma unroll
        for (int o = 16; o; o >>= 1) {
            s  += __shfl_xor_sync(0xFFFFFFFFu, s,  o);
            ss += __shfl_xor_sync(0xFFFFFFFFu, ss, o);
        }
        float mean = s * (1.0f / F_);
        float rstd = rsqrtf(ss * (1.0f / F_) - mean * mean + 1e-5f);

        float4 gg0 = reinterpret_cast<const float4*>(g2)[lane * 2];
        float4 gg1 = reinterpret_cast<const float4*>(g2)[lane * 2 + 1];
        float4 zb0 = reinterpret_cast<const float4*>(b2)[lane * 2];
        float4 zb1 = reinterpret_cast<const float4*>(b2)[lane * 2 + 1];
        float garr[8] = {gg0.x, gg0.y, gg0.z, gg0.w, gg1.x, gg1.y, gg1.z, gg1.w};
        float barr[8] = {zb0.x, zb0.y, zb0.z, zb0.w, zb1.x, zb1.y, zb1.z, zb1.w};

        float4* hp = reinterpret_cast<float4*>(g_h + (size_t)(m0 + row) * F_ + lane * 8);
        float4 h0 = hp[0], h1 = hp[1];
        float hv[8] = {h0.x, h0.y, h0.z, h0.w, h1.x, h1.y, h1.z, h1.w};
        #pragma unroll
        for (int j = 0; j < 8; j++) {
            float z = (v[j] - mean) * rstd * garr[j] + barr[j];
            hv[j] += gelu_f(z);
        }
        hp[0] = make_float4(hv[0], hv[1], hv[2], hv[3]);
        hp[1] = make_float4(hv[4], hv[5], hv[6], hv[7]);
    }
}

// ---------------------------------------------------------------------------
// Kernel 4: per-token projection (256 -> 29) + RQ spline. One warp per token.
// ---------------------------------------------------------------------------
__device__ __forceinline__ float softplus_f(float v) {
    return fmaxf(v, 0.f) + log1pf(expf(-fabsf(v)));
}

__global__ void proj_spline_kernel(const float* __restrict__ x,
                                   const float* __restrict__ mask,
                                   const float* __restrict__ w_proj, // [F, 29]
                                   const float* __restrict__ b_proj,
                                   float* __restrict__ out) {
    int wrp  = threadIdx.x >> 5;
    int lane = threadIdx.x & 31;
    int tok  = blockIdx.x * 8 + wrp;

    float m = mask[tok];
    float hv[8];
    #pragma unroll
    for (int j = 0; j < 8; j++)
        hv[j] = g_h[(size_t)tok * F_ + lane + 32 * j] * m;

    float proj[PROJ_];
    #pragma unroll
    for (int p = 0; p < PROJ_; p++) {
        float s = 0.f;
        #pragma unroll
        for (int j = 0; j < 8; j++)
            s += hv[j] * w_proj[(lane + 32 * j) * PROJ_ + p];
        #pragma unroll
        for (int o = 16; o; o >>= 1) s += __shfl_xor_sync(0xFFFFFFFFu, s, o);
        proj[p] = s;
    }

    if (lane == 0) {
        #pragma unroll
        for (int p = 0; p < PROJ_; p++) proj[p] = (proj[p] + b_proj[p]) * m;

        const float scale = 0.0625f;  // 1/sqrt(256)

        float cw[NB_ + 1], ww[NB_];
        {
            float mx = proj[0] * scale;
            #pragma unroll
            for (int j = 1; j < NB_; j++) mx = fmaxf(mx, proj[j] * scale);
            float e[NB_], sum = 0.f;
            #pragma unroll
            for (int j = 0; j < NB_; j++) { e[j] = expf(proj[j] * scale - mx); sum += e[j]; }
            float inv = 1.0f / sum;
            float cum = 0.f;
            cw[0] = -TBND;
            #pragma unroll
            for (int j = 0; j < NB_; j++) {
                float wj = 0.001f + (1.0f - 0.001f * NB_) * (e[j] * inv);
                cum += wj;
                cw[j + 1] = 2.0f * TBND * cum - TBND;
            }
            cw[NB_] = TBND;
            #pragma unroll
            for (int j = 0; j < NB_; j++) ww[j] = cw[j + 1] - cw[j];
        }
        float ch[NB_ + 1], hh[NB_];
        {
            float mx = proj[NB_] * scale;
            #pragma unroll
            for (int j = 1; j < NB_; j++) mx = fmaxf(mx, proj[NB_ + j] * scale);
            float e[NB_], sum = 0.f;
            #pragma unroll
            for (int j = 0; j < NB_; j++) { e[j] = expf(proj[NB_ + j] * scale - mx); sum += e[j]; }
            float inv = 1.0f / sum;
            float cum = 0.f;
            ch[0] = -TBND;
            #pragma unroll
            for (int j = 0; j < NB_; j++) {
                float hj = 0.001f + (1.0f - 0.001f * NB_) * (e[j] * inv);
                cum += hj;
                ch[j + 1] = 2.0f * TBND * cum - TBND;
            }
            ch[NB_] = TBND;
            #pragma unroll
            for (int j = 0; j < NB_; j++) hh[j] = ch[j + 1] - ch[j];
        }
        float d[NB_ + 1];
        float cst = logf(expm1f(1.0f - 0.001f));
        d[0]   = 0.001f + softplus_f(cst);
        d[NB_] = d[0];
        #pragma unroll
        for (int k = 1; k < NB_; k++) d[k] = 0.001f + softplus_f(proj[2 * NB_ + k - 1]);

        float x1 = x[(size_t)tok * 2 + 1];
        float xc = fminf(fmaxf(x1, -TBND), TBND);
        int idx = 0;
        #pragma unroll
        for (int j = 1; j <= NB_; j++) idx += (xc >= cw[j]) ? 1 : 0;
        if (idx > NB_ - 1) idx = NB_ - 1;

        float icw = cw[idx], ibw = ww[idx];
        float ich = ch[idx], ibh = hh[idx];
        float delta = ibh / ibw;
        float dk = d[idx], dk1 = d[idx + 1];
        float th   = (xc - icw) / ibw;
        float th1m = th * (1.0f - th);
        float denom = delta + (dk + dk1 - 2.0f * delta) * th1m;
        float num   = ibh * (delta * th * th + dk * th1m);
        float yv    = ich + num / denom;
        float omth  = 1.0f - th;
        float dnum  = delta * delta * (dk1 * th * th + 2.0f * delta * th1m + dk * omth * omth);
        float lad   = logf(dnum) - 2.0f * logf(denom);

        bool inside = (x1 >= -TBND) && (x1 <= TBND);
        float y1 = inside ? yv : x1;
        lad = inside ? lad : 0.0f;

        out[(size_t)tok * 2]     = x[(size_t)tok * 2] * m;
        out[(size_t)tok * 2 + 1] = y1 * m;
        g_lad[tok] = lad * m;
    }
}

// ---------------------------------------------------------------------------
// Kernel 5: deterministic per-batch logdet reduction
// ---------------------------------------------------------------------------
__global__ void logdet_kernel(float* __restrict__ out) {
    int b = blockIdx.x, tid = threadIdx.x;
    float s = 0.f;
    for (int j = tid; j < T_; j += 256) s += g_lad[b * T_ + j];
    __shared__ float sh[256];
    sh[tid] = s;
    __syncthreads();
    #pragma unroll
    for (int o = 128; o; o >>= 1) {
        if (tid < o) sh[tid] += sh[tid + o];
        __syncthreads();
    }
    if (tid == 0) out[(size_t)BT_ * 2 + b] = sh[0];
}

// ---------------------------------------------------------------------------
extern "C" void kernel_launch(void* const* d_in, const int* in_sizes, int n_in,
                              void* d_out, int out_size) {
    const float* x      = (const float*)d_in[0];
    const float* mask   = (const float*)d_in[1];
    const float* w_pre  = (const float*)d_in[2];
    const float* b_pre  = (const float*)d_in[3];
    const float* dw_k   = (const float*)d_in[4];
    const float* dw_b   = (const float*)d_in[5];
    const float* w11    = (const float*)d_in[6];
    const float* b11    = (const float*)d_in[7];
    const float* ln1g   = (const float*)d_in[8];
    const float* ln1b   = (const float*)d_in[9];
    const float* ln2g   = (const float*)d_in[10];
    const float* ln2b   = (const float*)d_in[11];
    const float* w_proj = (const float*)d_in[12];
    const float* b_proj = (const float*)d_in[13];
    float* out = (float*)d_out;

    cudaFuncSetAttribute(gemm_mma_kernel,
                         cudaFuncAttributeMaxDynamicSharedMemorySize, GSMEM);

    // split prep into two launches so ncu (-s 5 -c 1) captures conv layer 1
    prep_bfrag_kernel<<<NL_ * 32 * 8, 32>>>(w11, 0);
    prep_bfrag_kernel<<<NL_ * 32 * 8, 32>>>(w11, NL_ * 32 * 8);
    pre_kernel<<<BT_ * 64 / 256, 256>>>(x, w_pre, b_pre);

    int dil = 1;
    for (int i = 0; i < NL_; i++) {
        conv_ln_gelu_kernel<<<BT_ / 8, 256>>>(mask,
                                              dw_k + (size_t)i * KS_ * F_,
                                              dw_b + (size_t)i * F_,
                                              ln1g + (size_t)i * F_,
                                              ln1b + (size_t)i * F_,
                                              dil);
        gemm_mma_kernel<<<BT_ / 128, 512, GSMEM>>>(i,
                                                   b11 + (size_t)i * F_,
                                                   ln2g + (size_t)i * F_,
                                                   ln2b + (size_t)i * F_);
        dil *= KS_;
    }

    proj_spline_kernel<<<BT_ / 8, 256>>>(x, mask, w_proj, b_proj, out);
    logdet_kernel<<<B_, 256>>>(out);
}

// round 6
// speedup vs baseline: 2.7044x; 1.5851x over previous
#include <cuda_runtime.h>
#include <cuda_bf16.h>
#include <math.h>
#include <stdint.h>
#include <cstdint>

#define B_    16
#define T_    8192
#define F_    256
#define NL_   3
#define KS_   3
#define NB_   10
#define PROJ_ 29
#define BT_   (B_*T_)
#define TBND  5.0f

// Scratch (allocation-free rule: __device__ globals)
__device__ float g_h[(size_t)BT_ * F_];    // 134 MB
__device__ float g_y[(size_t)BT_ * F_];    // 134 MB
__device__ float g_lad[BT_];
__device__ float g_proj[(size_t)BT_ * 32]; // 16.8 MB (29 used, stride 32)
// B fragments, mma-ordered: [l][nt(32)][ks(16)][lane(32)] uint4 = (b0_hi,b1_hi,b0_lo,b1_lo)
__device__ uint4 g_Bfrag[NL_ * 32 * 16 * 32];

__device__ __forceinline__ float gelu_f(float v) {
    return 0.5f * v * (1.0f + erff(v * 0.7071067811865476f));
}

__device__ __forceinline__ void mma16816(float* d, const uint32_t* a,
                                         uint32_t b0, uint32_t b1) {
    asm volatile(
        "mma.sync.aligned.m16n8k16.row.col.f32.bf16.bf16.f32 "
        "{%0,%1,%2,%3}, {%4,%5,%6,%7}, {%8,%9}, {%0,%1,%2,%3};"
        : "+f"(d[0]), "+f"(d[1]), "+f"(d[2]), "+f"(d[3])
        : "r"(a[0]), "r"(a[1]), "r"(a[2]), "r"(a[3]), "r"(b0), "r"(b1));
}

__device__ __forceinline__ void ldmx4(uint32_t* r, uint32_t addr) {
    asm volatile("ldmatrix.sync.aligned.m8n8.x4.shared.b16 {%0,%1,%2,%3}, [%4];"
        : "=r"(r[0]), "=r"(r[1]), "=r"(r[2]), "=r"(r[3]) : "r"(addr));
}

__device__ __forceinline__ uint32_t pack_bf16x2(float x, float y) {
    __nv_bfloat162 p = __halves2bfloat162(__float2bfloat16(x), __float2bfloat16(y));
    return *reinterpret_cast<uint32_t*>(&p);
}

// ---------------------------------------------------------------------------
// Kernel 0: pack w11 into mma B fragments (hi/lo split)
// ---------------------------------------------------------------------------
__global__ void prep_bfrag_kernel(const float* __restrict__ w11) {
    int blk  = blockIdx.x;              // (l*32 + nt)*16 + ks
    int lane = threadIdx.x;
    int ks   = blk & 15;
    int nt   = (blk >> 4) & 31;
    int l    = blk >> 9;
    int tg   = lane >> 2, tid = lane & 3;
    int n    = nt * 8 + tg;
    int k0   = ks * 16 + tid * 2;

    const float* w = w11 + (size_t)l * F_ * F_;
    float v00 = w[(size_t)(k0    ) * F_ + n];
    float v01 = w[(size_t)(k0 + 1) * F_ + n];
    float v10 = w[(size_t)(k0 + 8) * F_ + n];
    float v11 = w[(size_t)(k0 + 9) * F_ + n];

    float h00 = __bfloat162float(__float2bfloat16(v00));
    float h01 = __bfloat162float(__float2bfloat16(v01));
    float h10 = __bfloat162float(__float2bfloat16(v10));
    float h11 = __bfloat162float(__float2bfloat16(v11));

    uint4 o;
    o.x = pack_bf16x2(v00, v01);                // b0_hi
    o.y = pack_bf16x2(v10, v11);                // b1_hi
    o.z = pack_bf16x2(v00 - h00, v01 - h01);    // b0_lo
    o.w = pack_bf16x2(v10 - h10, v11 - h11);    // b1_lo
    g_Bfrag[(size_t)blk * 32 + lane] = o;
}

// ---------------------------------------------------------------------------
// Kernel 1: h[b,t,f] = x0[b,t] * w_pre[f] + b_pre[f]
// ---------------------------------------------------------------------------
__global__ void pre_kernel(const float* __restrict__ x,
                           const float* __restrict__ w_pre,
                           const float* __restrict__ b_pre) {
    int gid = blockIdx.x * 256 + threadIdx.x;   // BT*64 total float4s
    int tok = gid >> 6;
    int c4  = gid & 63;
    float x0 = __ldg(&x[(size_t)tok * 2]);
    float4 w = reinterpret_cast<const float4*>(w_pre)[c4];
    float4 b = reinterpret_cast<const float4*>(b_pre)[c4];
    float4 o;
    o.x = x0 * w.x + b.x; o.y = x0 * w.y + b.y;
    o.z = x0 * w.z + b.z; o.w = x0 * w.w + b.w;
    reinterpret_cast<float4*>(g_h)[gid] = o;
}

// ---------------------------------------------------------------------------
// Kernel 2: y = gelu(LN1(depthwise dilated conv(h * mask))); warp per token
// ---------------------------------------------------------------------------
__global__ void conv_ln_gelu_kernel(const float* __restrict__ mask,
                                    const float* __restrict__ dwk,   // [KS,F]
                                    const float* __restrict__ dwb,
                                    const float* __restrict__ g1,
                                    const float* __restrict__ b1,
                                    int dil) {
    __shared__ float4 s_k[3][64], s_b[64], s_g[64], s_bb[64];
    int tidx = threadIdx.x;
    if (tidx < 64) {
        s_k[0][tidx] = reinterpret_cast<const float4*>(dwk)[tidx];
        s_k[1][tidx] = reinterpret_cast<const float4*>(dwk)[64 + tidx];
        s_k[2][tidx] = reinterpret_cast<const float4*>(dwk)[128 + tidx];
    } else if (tidx < 128) {
        s_b[tidx - 64] = reinterpret_cast<const float4*>(dwb)[tidx - 64];
    } else if (tidx < 192) {
        s_g[tidx - 128] = reinterpret_cast<const float4*>(g1)[tidx - 128];
    } else {
        s_bb[tidx - 192] = reinterpret_cast<const float4*>(b1)[tidx - 192];
    }
    __syncthreads();

    int wid  = tidx >> 5;
    int lane = tidx & 31;
    int tok  = blockIdx.x * 8 + wid;
    int t    = tok & (T_ - 1);

    float a[8];
    {
        float4 b0 = s_b[lane], b1v = s_b[lane + 32];
        a[0] = b0.x; a[1] = b0.y; a[2] = b0.z; a[3] = b0.w;
        a[4] = b1v.x; a[5] = b1v.y; a[6] = b1v.z; a[7] = b1v.w;
    }

    #pragma unroll
    for (int tap = 0; tap < 3; tap++) {
        int off = (tap - 1) * dil;
        int tt = t + off;
        if (tt >= 0 && tt < T_) {
            float mm = __ldg(&mask[tok + off]);
            const float4* hr = reinterpret_cast<const float4*>(g_h + (size_t)(tok + off) * F_);
            float4 h0 = hr[lane], h1 = hr[lane + 32];
            float4 k0 = s_k[tap][lane], k1 = s_k[tap][lane + 32];
            a[0] += h0.x * mm * k0.x; a[1] += h0.y * mm * k0.y;
            a[2] += h0.z * mm * k0.z; a[3] += h0.w * mm * k0.w;
            a[4] += h1.x * mm * k1.x; a[5] += h1.y * mm * k1.y;
            a[6] += h1.z * mm * k1.z; a[7] += h1.w * mm * k1.w;
        }
    }

    float s = 0.f, ss = 0.f;
    #pragma unroll
    for (int j = 0; j < 8; j++) { s += a[j]; ss += a[j] * a[j]; }
    #pragma unroll
    for (int o = 16; o; o >>= 1) {
        s  += __shfl_xor_sync(0xFFFFFFFFu, s,  o);
        ss += __shfl_xor_sync(0xFFFFFFFFu, ss, o);
    }
    float mean = s * (1.0f / F_);
    float rstd = rsqrtf(ss * (1.0f / F_) - mean * mean + 1e-5f);

    float4 gg0 = s_g[lane], gg1 = s_g[lane + 32];
    float4 bb0 = s_bb[lane], bb1 = s_bb[lane + 32];
    float garr[8] = {gg0.x, gg0.y, gg0.z, gg0.w, gg1.x, gg1.y, gg1.z, gg1.w};
    float barr[8] = {bb0.x, bb0.y, bb0.z, bb0.w, bb1.x, bb1.y, bb1.z, bb1.w};

    float4 o0, o1;
    float r[8];
    #pragma unroll
    for (int j = 0; j < 8; j++) {
        float v = (a[j] - mean) * rstd * garr[j] + barr[j];
        r[j] = gelu_f(v);
    }
    o0.x = r[0]; o0.y = r[1]; o0.z = r[2]; o0.w = r[3];
    o1.x = r[4]; o1.y = r[5]; o1.z = r[6]; o1.w = r[7];
    float4* yr = reinterpret_cast<float4*>(g_y + (size_t)tok * F_);
    yr[lane] = o0;
    yr[lane + 32] = o1;
}

// ---------------------------------------------------------------------------
// Kernel 3: mma.sync GEMM  h += gelu(LN2(y @ w11 + b11))
// ---------------------------------------------------------------------------
#define AROW   264                     // bf16 row stride (528B -> conflict-free)
#define GSMEM  (2 * 128 * AROW * 2 + 256)   // A hi + lo + align slack

__global__ void __launch_bounds__(512, 1)
gemm_mma_kernel(int layer,
                const float* __restrict__ b11,
                const float* __restrict__ g2,
                const float* __restrict__ b2) {
    extern __shared__ char dyn[];
    char* basep = (char*)(((uintptr_t)dyn + 15) & ~(uintptr_t)15);
    __nv_bfloat16* Ahi = reinterpret_cast<__nv_bfloat16*>(basep);
    __nv_bfloat16* Alo = Ahi + 128 * AROW;
    float* stag = reinterpret_cast<float*>(basep);   // reused post-mainloop [128][260]
    const int SROW = 260;

    const int tid  = threadIdx.x;
    const int wid  = tid >> 5;
    const int lane = tid & 31;
    const int tg   = lane >> 2, tq = lane & 3;
    const int wm   = wid >> 3;          // 0..1  -> m_base
    const int wn   = wid & 7;           // 0..7  -> n group
    const int m0   = blockIdx.x * 128;

    // ---- load A (128 x 256 fp32) -> bf16 hi/lo SMEM ----
    {
        int row = tid >> 2;
        int kq  = (tid & 3) * 64;
        const float4* src = reinterpret_cast<const float4*>(
            g_y + (size_t)(m0 + row) * F_ + kq);
        #pragma unroll
        for (int j = 0; j < 16; j++) {
            float4 v = src[j];
            float hx = __bfloat162float(__float2bfloat16(v.x));
            float hy = __bfloat162float(__float2bfloat16(v.y));
            float hz = __bfloat162float(__float2bfloat16(v.z));
            float hw = __bfloat162float(__float2bfloat16(v.w));
            uint2 hp, lp;
            hp.x = pack_bf16x2(v.x, v.y);
            hp.y = pack_bf16x2(v.z, v.w);
            lp.x = pack_bf16x2(v.x - hx, v.y - hy);
            lp.y = pack_bf16x2(v.z - hz, v.w - hw);
            int c = kq + j * 4;
            *reinterpret_cast<uint2*>(Ahi + row * AROW + c) = hp;
            *reinterpret_cast<uint2*>(Alo + row * AROW + c) = lp;
        }
    }
    __syncthreads();

    // ---- mainloop ----
    float d[4][4][4];
    #pragma unroll
    for (int mt = 0; mt < 4; mt++)
        #pragma unroll
        for (int nt = 0; nt < 4; nt++)
            #pragma unroll
            for (int q = 0; q < 4; q++) d[mt][nt][q] = 0.f;

    const uint4* Bbase = g_Bfrag + ((size_t)(layer * 32 + wn * 4) * 16) * 32 + lane;
    uint4 bcur[4], bnxt[4];
    #pragma unroll
    for (int nt = 0; nt < 4; nt++) bcur[nt] = __ldg(&Bbase[(nt * 16 + 0) * 32]);

    const int m_base = wm * 64;
    uint32_t a_hi_addr[4], a_lo_addr[4];
    {
        int r = lane & 15;
        int cb = (lane >> 4) * 16;      // 16-byte column offset
        #pragma unroll
        for (int mt = 0; mt < 4; mt++) {
            int row = m_base + mt * 16 + r;
            a_hi_addr[mt] = (uint32_t)__cvta_generic_to_shared(Ahi + row * AROW) + cb;
            a_lo_addr[mt] = (uint32_t)__cvta_generic_to_shared(Alo + row * AROW) + cb;
        }
    }

    #pragma unroll 1
    for (int ks = 0; ks < 16; ks++) {
        if (ks < 15) {
            #pragma unroll
            for (int nt = 0; nt < 4; nt++)
                bnxt[nt] = __ldg(&Bbase[(nt * 16 + ks + 1) * 32]);
        }
        const uint32_t koff = ks * 32;  // 16 bf16 = 32 bytes per k-step
        #pragma unroll
        for (int mt = 0; mt < 4; mt++) {
            uint32_t ah[4], al[4];
            ldmx4(ah, a_hi_addr[mt] + koff);
            ldmx4(al, a_lo_addr[mt] + koff);
            #pragma unroll
            for (int nt = 0; nt < 4; nt++) {
                mma16816(d[mt][nt], ah, bcur[nt].x, bcur[nt].y);  // Ah*Bh
                mma16816(d[mt][nt], ah, bcur[nt].z, bcur[nt].w);  // Ah*Bl
                mma16816(d[mt][nt], al, bcur[nt].x, bcur[nt].y);  // Al*Bh
            }
        }
        #pragma unroll
        for (int nt = 0; nt < 4; nt++) bcur[nt] = bnxt[nt];
    }

    // ---- stage accum to SMEM (reuse A region) ----
    __syncthreads();
    #pragma unroll
    for (int mt = 0; mt < 4; mt++) {
        int r0 = m_base + mt * 16 + tg;
        #pragma unroll
        for (int nt = 0; nt < 4; nt++) {
            int col = wn * 32 + nt * 8 + tq * 2;
            *reinterpret_cast<float2*>(&stag[r0 * SROW + col]) =
                make_float2(d[mt][nt][0], d[mt][nt][1]);
            *reinterpret_cast<float2*>(&stag[(r0 + 8) * SROW + col]) =
                make_float2(d[mt][nt][2], d[mt][nt][3]);
        }
    }
    __syncthreads();

    // ---- LN2 + gelu + residual: each warp 8 rows, lane covers 8 cols ----
    #pragma unroll 1
    for (int i = 0; i < 8; i++) {
        int row = wid * 8 + i;
        float4 f0 = *reinterpret_cast<const float4*>(&stag[row * SROW + lane * 8]);
        float4 f1 = *reinterpret_cast<const float4*>(&stag[row * SROW + lane * 8 + 4]);
        float4 bb0 = reinterpret_cast<const float4*>(b11)[lane * 2];
        float4 bb1 = reinterpret_cast<const float4*>(b11)[lane * 2 + 1];
        float v[8] = {f0.x + bb0.x, f0.y + bb0.y, f0.z + bb0.z, f0.w + bb0.w,
                      f1.x + bb1.x, f1.y + bb1.y, f1.z + bb1.z, f1.w + bb1.w};
        float s = 0.f, ss = 0.f;
        #pragma unroll
        for (int j = 0; j < 8; j++) { s += v[j]; ss += v[j] * v[j]; }
        #pragma unroll
        for (int o = 16; o; o >>= 1) {
            s  += __shfl_xor_sync(0xFFFFFFFFu, s,  o);
            ss += __shfl_xor_sync(0xFFFFFFFFu, ss, o);
        }
        float mean = s * (1.0f / F_);
        float rstd = rsqrtf(ss * (1.0f / F_) - mean * mean + 1e-5f);

        float4 gg0 = reinterpret_cast<const float4*>(g2)[lane * 2];
        float4 gg1 = reinterpret_cast<const float4*>(g2)[lane * 2 + 1];
        float4 zb0 = reinterpret_cast<const float4*>(b2)[lane * 2];
        float4 zb1 = reinterpret_cast<const float4*>(b2)[lane * 2 + 1];
        float garr[8] = {gg0.x, gg0.y, gg0.z, gg0.w, gg1.x, gg1.y, gg1.z, gg1.w};
        float barr[8] = {zb0.x, zb0.y, zb0.z, zb0.w, zb1.x, zb1.y, zb1.z, zb1.w};

        float4* hp = reinterpret_cast<float4*>(g_h + (size_t)(m0 + row) * F_ + lane * 8);
        float4 h0 = hp[0], h1 = hp[1];
        float hv[8] = {h0.x, h0.y, h0.z, h0.w, h1.x, h1.y, h1.z, h1.w};
        #pragma unroll
        for (int j = 0; j < 8; j++) {
            float z = (v[j] - mean) * rstd * garr[j] + barr[j];
            hv[j] += gelu_f(z);
        }
        hp[0] = make_float4(hv[0], hv[1], hv[2], hv[3]);
        hp[1] = make_float4(hv[4], hv[5], hv[6], hv[7]);
    }
}

// ---------------------------------------------------------------------------
// Kernel 4a: projection h[tok]@w_proj -> g_proj[tok][29] (stride 32)
// 8 warps/block, 8 tokens/warp (register-blocked), w_proj in SMEM
// ---------------------------------------------------------------------------
__global__ void __launch_bounds__(256)
proj_kernel(const float* __restrict__ mask, const float* __restrict__ w_proj) {
    __shared__ float s_w[PROJ_][256];   // [p][f], conflict-free lane access
    int tid = threadIdx.x;
    for (int i = tid; i < PROJ_ * 256; i += 256) {
        int f = i / PROJ_;
        int p = i - f * PROJ_;
        s_w[p][f] = w_proj[i];
    }
    __syncthreads();

    int wrp  = tid >> 5;
    int lane = tid & 31;
    int tokbase = blockIdx.x * 64 + wrp * 8;

    float hv[8][8];
    #pragma unroll
    for (int t = 0; t < 8; t++) {
        float mm = __ldg(&mask[tokbase + t]);
        const float* hr = g_h + (size_t)(tokbase + t) * F_;
        #pragma unroll
        for (int j = 0; j < 8; j++) hv[t][j] = hr[lane + 32 * j] * mm;
    }

    #pragma unroll 1
    for (int p = 0; p < PROJ_; p++) {
        float w[8];
        #pragma unroll
        for (int j = 0; j < 8; j++) w[j] = s_w[p][lane + 32 * j];
        float part[8];
        #pragma unroll
        for (int t = 0; t < 8; t++) {
            float s = 0.f;
            #pragma unroll
            for (int j = 0; j < 8; j++) s += hv[t][j] * w[j];
            part[t] = s;
        }
        #pragma unroll
        for (int o = 16; o; o >>= 1) {
            #pragma unroll
            for (int t = 0; t < 8; t++)
                part[t] += __shfl_xor_sync(0xFFFFFFFFu, part[t], o);
        }
        if (lane < 8) {
            float v = part[0];
            #pragma unroll
            for (int t = 1; t < 8; t++) if (lane == t) v = part[t];
            g_proj[(size_t)(tokbase + lane) * 32 + p] = v;
        }
    }
}

// ---------------------------------------------------------------------------
// Kernel 4b: RQ spline, one THREAD per token
// ---------------------------------------------------------------------------
__device__ __forceinline__ float softplus_f(float v) {
    return fmaxf(v, 0.f) + log1pf(expf(-fabsf(v)));
}

__global__ void __launch_bounds__(256)
spline_kernel(const float* __restrict__ x,
              const float* __restrict__ mask,
              const float* __restrict__ b_proj,
              float* __restrict__ out) {
    int tok = blockIdx.x * 256 + threadIdx.x;
    float m = mask[tok];

    float proj[PROJ_];
    #pragma unroll
    for (int p = 0; p < PROJ_; p++)
        proj[p] = (g_proj[(size_t)tok * 32 + p] + __ldg(&b_proj[p])) * m;

    const float scale = 0.0625f;  // 1/sqrt(256)

    float cw[NB_ + 1], ww[NB_];
    {
        float mx = proj[0] * scale;
        #pragma unroll
        for (int j = 1; j < NB_; j++) mx = fmaxf(mx, proj[j] * scale);
        float e[NB_], sum = 0.f;
        #pragma unroll
        for (int j = 0; j < NB_; j++) { e[j] = expf(proj[j] * scale - mx); sum += e[j]; }
        float inv = 1.0f / sum;
        float cum = 0.f;
        cw[0] = -TBND;
        #pragma unroll
        for (int j = 0; j < NB_; j++) {
            float wj = 0.001f + (1.0f - 0.001f * NB_) * (e[j] * inv);
            cum += wj;
            cw[j + 1] = 2.0f * TBND * cum - TBND;
        }
        cw[NB_] = TBND;
        #pragma unroll
        for (int j = 0; j < NB_; j++) ww[j] = cw[j + 1] - cw[j];
    }
    float ch[NB_ + 1], hh[NB_];
    {
        float mx = proj[NB_] * scale;
        #pragma unroll
        for (int j = 1; j < NB_; j++) mx = fmaxf(mx, proj[NB_ + j] * scale);
        float e[NB_], sum = 0.f;
        #pragma unroll
        for (int j = 0; j < NB_; j++) { e[j] = expf(proj[NB_ + j] * scale - mx); sum += e[j]; }
        float inv = 1.0f / sum;
        float cum = 0.f;
        ch[0] = -TBND;
        #pragma unroll
        for (int j = 0; j < NB_; j++) {
            float hj = 0.001f + (1.0f - 0.001f * NB_) * (e[j] * inv);
            cum += hj;
            ch[j + 1] = 2.0f * TBND * cum - TBND;
        }
        ch[NB_] = TBND;
        #pragma unroll
        for (int j = 0; j < NB_; j++) hh[j] = ch[j + 1] - ch[j];
    }
    float d[NB_ + 1];
    float cst = logf(expm1f(1.0f - 0.001f));
    d[0]   = 0.001f + softplus_f(cst);
    d[NB_] = d[0];
    #pragma unroll
    for (int k = 1; k < NB_; k++) d[k] = 0.001f + softplus_f(proj[2 * NB_ + k - 1]);

    float x1 = x[(size_t)tok * 2 + 1];
    float xc = fminf(fmaxf(x1, -TBND), TBND);
    int idx = 0;
    #pragma unroll
    for (int j = 1; j <= NB_; j++) idx += (xc >= cw[j]) ? 1 : 0;
    if (idx > NB_ - 1) idx = NB_ - 1;

    float icw = cw[idx], ibw = ww[idx];
    float ich = ch[idx], ibh = hh[idx];
    float delta = ibh / ibw;
    float dk = d[idx], dk1 = d[idx + 1];
    float th   = (xc - icw) / ibw;
    float th1m = th * (1.0f - th);
    float denom = delta + (dk + dk1 - 2.0f * delta) * th1m;
    float num   = ibh * (delta * th * th + dk * th1m);
    float yv    = ich + num / denom;
    float omth  = 1.0f - th;
    float dnum  = delta * delta * (dk1 * th * th + 2.0f * delta * th1m + dk * omth * omth);
    float lad   = logf(dnum) - 2.0f * logf(denom);

    bool inside = (x1 >= -TBND) && (x1 <= TBND);
    float y1 = inside ? yv : x1;
    lad = inside ? lad : 0.0f;

    out[(size_t)tok * 2]     = x[(size_t)tok * 2] * m;
    out[(size_t)tok * 2 + 1] = y1 * m;
    g_lad[tok] = lad * m;
}

// ---------------------------------------------------------------------------
// Kernel 5: deterministic per-batch logdet reduction
// ---------------------------------------------------------------------------
__global__ void logdet_kernel(float* __restrict__ out) {
    int b = blockIdx.x, tid = threadIdx.x;
    float s = 0.f;
    for (int j = tid; j < T_; j += 256) s += g_lad[b * T_ + j];
    __shared__ float sh[256];
    sh[tid] = s;
    __syncthreads();
    #pragma unroll
    for (int o = 128; o; o >>= 1) {
        if (tid < o) sh[tid] += sh[tid + o];
        __syncthreads();
    }
    if (tid == 0) out[(size_t)BT_ * 2 + b] = sh[0];
}

// ---------------------------------------------------------------------------
extern "C" void kernel_launch(void* const* d_in, const int* in_sizes, int n_in,
                              void* d_out, int out_size) {
    const float* x      = (const float*)d_in[0];
    const float* mask   = (const float*)d_in[1];
    const float* w_pre  = (const float*)d_in[2];
    const float* b_pre  = (const float*)d_in[3];
    const float* dw_k   = (const float*)d_in[4];
    const float* dw_b   = (const float*)d_in[5];
    const float* w11    = (const float*)d_in[6];
    const float* b11    = (const float*)d_in[7];
    const float* ln1g   = (const float*)d_in[8];
    const float* ln1b   = (const float*)d_in[9];
    const float* ln2g   = (const float*)d_in[10];
    const float* ln2b   = (const float*)d_in[11];
    const float* w_proj = (const float*)d_in[12];
    const float* b_proj = (const float*)d_in[13];
    float* out = (float*)d_out;

    cudaFuncSetAttribute(gemm_mma_kernel,
                         cudaFuncAttributeMaxDynamicSharedMemorySize, GSMEM);

    prep_bfrag_kernel<<<NL_ * 32 * 16, 32>>>(w11);
    pre_kernel<<<BT_ * 64 / 256, 256>>>(x, w_pre, b_pre);

    int dil = 1;
    for (int i = 0; i < NL_; i++) {
        conv_ln_gelu_kernel<<<BT_ / 8, 256>>>(mask,
                                              dw_k + (size_t)i * KS_ * F_,
                                              dw_b + (size_t)i * F_,
                                              ln1g + (size_t)i * F_,
                                              ln1b + (size_t)i * F_,
                                              dil);
        gemm_mma_kernel<<<BT_ / 128, 512, GSMEM>>>(i,
                                                   b11 + (size_t)i * F_,
                                                   ln2g + (size_t)i * F_,
                                                   ln2b + (size_t)i * F_);
        dil *= KS_;
    }

    proj_kernel<<<BT_ / 64, 256>>>(mask, w_proj);
    spline_kernel<<<BT_ / 256, 256>>>(x, mask, b_proj, out);
    logdet_kernel<<<B_, 256>>>(out);
}

// round 7
// speedup vs baseline: 2.9872x; 1.1045x over previous
#include <cuda_runtime.h>
#include <cuda_bf16.h>
#include <math.h>
#include <stdint.h>
#include <cstdint>

#define B_    16
#define T_    8192
#define F_    256
#define NL_   3
#define KS_   3
#define NB_   10
#define PROJ_ 29
#define BT_   (B_*T_)
#define TBND  5.0f

// Scratch (allocation-free rule: __device__ globals)
__device__ float g_h[(size_t)BT_ * F_];    // 134 MB
__device__ float g_y[(size_t)BT_ * F_];    // 134 MB
__device__ float g_lad[BT_];
__device__ float g_proj[(size_t)BT_ * 32]; // 16.8 MB (29 used, stride 32)
// B fragments, mma-ordered: [l][nt(32)][ks(16)][lane(32)] uint4 = (b0_hi,b1_hi,b0_lo,b1_lo)
__device__ uint4 g_Bfrag[NL_ * 32 * 16 * 32];

__device__ __forceinline__ float gelu_f(float v) {
    return 0.5f * v * (1.0f + erff(v * 0.7071067811865476f));
}

__device__ __forceinline__ void mma16816(float* d, const uint32_t* a,
                                         uint32_t b0, uint32_t b1) {
    asm volatile(
        "mma.sync.aligned.m16n8k16.row.col.f32.bf16.bf16.f32 "
        "{%0,%1,%2,%3}, {%4,%5,%6,%7}, {%8,%9}, {%0,%1,%2,%3};"
        : "+f"(d[0]), "+f"(d[1]), "+f"(d[2]), "+f"(d[3])
        : "r"(a[0]), "r"(a[1]), "r"(a[2]), "r"(a[3]), "r"(b0), "r"(b1));
}

__device__ __forceinline__ void ldmx4(uint32_t* r, uint32_t addr) {
    asm volatile("ldmatrix.sync.aligned.m8n8.x4.shared.b16 {%0,%1,%2,%3}, [%4];"
        : "=r"(r[0]), "=r"(r[1]), "=r"(r[2]), "=r"(r[3]) : "r"(addr));
}

__device__ __forceinline__ uint32_t pack_bf16x2(float x, float y) {
    __nv_bfloat162 p = __halves2bfloat162(__float2bfloat16(x), __float2bfloat16(y));
    return *reinterpret_cast<uint32_t*>(&p);
}

// ---------------------------------------------------------------------------
// Kernel 0: pack w11 into mma B fragments (hi/lo split)
// ---------------------------------------------------------------------------
__global__ void prep_bfrag_kernel(const float* __restrict__ w11) {
    int blk  = blockIdx.x;              // (l*32 + nt)*16 + ks
    int lane = threadIdx.x;
    int ks   = blk & 15;
    int nt   = (blk >> 4) & 31;
    int l    = blk >> 9;
    int tg   = lane >> 2, tid = lane & 3;
    int n    = nt * 8 + tg;
    int k0   = ks * 16 + tid * 2;

    const float* w = w11 + (size_t)l * F_ * F_;
    float v00 = w[(size_t)(k0    ) * F_ + n];
    float v01 = w[(size_t)(k0 + 1) * F_ + n];
    float v10 = w[(size_t)(k0 + 8) * F_ + n];
    float v11 = w[(size_t)(k0 + 9) * F_ + n];

    float h00 = __bfloat162float(__float2bfloat16(v00));
    float h01 = __bfloat162float(__float2bfloat16(v01));
    float h10 = __bfloat162float(__float2bfloat16(v10));
    float h11 = __bfloat162float(__float2bfloat16(v11));

    uint4 o;
    o.x = pack_bf16x2(v00, v01);                // b0_hi
    o.y = pack_bf16x2(v10, v11);                // b1_hi
    o.z = pack_bf16x2(v00 - h00, v01 - h01);    // b0_lo
    o.w = pack_bf16x2(v10 - h10, v11 - h11);    // b1_lo
    g_Bfrag[(size_t)blk * 32 + lane] = o;
}

// ---------------------------------------------------------------------------
// Kernel 1: h[b,t,f] = x0[b,t] * w_pre[f] + b_pre[f]
// ---------------------------------------------------------------------------
__global__ void pre_kernel(const float* __restrict__ x,
                           const float* __restrict__ w_pre,
                           const float* __restrict__ b_pre) {
    int gid = blockIdx.x * 256 + threadIdx.x;   // BT*64 total float4s
    int tok = gid >> 6;
    int c4  = gid & 63;
    float x0 = __ldg(&x[(size_t)tok * 2]);
    float4 w = reinterpret_cast<const float4*>(w_pre)[c4];
    float4 b = reinterpret_cast<const float4*>(b_pre)[c4];
    float4 o;
    o.x = x0 * w.x + b.x; o.y = x0 * w.y + b.y;
    o.z = x0 * w.z + b.z; o.w = x0 * w.w + b.w;
    reinterpret_cast<float4*>(g_h)[gid] = o;
}

// ---------------------------------------------------------------------------
// Kernel 2: y = gelu(LN1(depthwise dilated conv(h * mask))); warp per token
// ---------------------------------------------------------------------------
__global__ void conv_ln_gelu_kernel(const float* __restrict__ mask,
                                    const float* __restrict__ dwk,   // [KS,F]
                                    const float* __restrict__ dwb,
                                    const float* __restrict__ g1,
                                    const float* __restrict__ b1,
                                    int dil) {
    __shared__ float4 s_k[3][64], s_b[64], s_g[64], s_bb[64];
    int tidx = threadIdx.x;
    if (tidx < 64) {
        s_k[0][tidx] = reinterpret_cast<const float4*>(dwk)[tidx];
        s_k[1][tidx] = reinterpret_cast<const float4*>(dwk)[64 + tidx];
        s_k[2][tidx] = reinterpret_cast<const float4*>(dwk)[128 + tidx];
    } else if (tidx < 128) {
        s_b[tidx - 64] = reinterpret_cast<const float4*>(dwb)[tidx - 64];
    } else if (tidx < 192) {
        s_g[tidx - 128] = reinterpret_cast<const float4*>(g1)[tidx - 128];
    } else {
        s_bb[tidx - 192] = reinterpret_cast<const float4*>(b1)[tidx - 192];
    }
    __syncthreads();

    int wid  = tidx >> 5;
    int lane = tidx & 31;
    int tok  = blockIdx.x * 8 + wid;
    int t    = tok & (T_ - 1);

    float a[8];
    {
        float4 b0 = s_b[lane], b1v = s_b[lane + 32];
        a[0] = b0.x; a[1] = b0.y; a[2] = b0.z; a[3] = b0.w;
        a[4] = b1v.x; a[5] = b1v.y; a[6] = b1v.z; a[7] = b1v.w;
    }

    #pragma unroll
    for (int tap = 0; tap < 3; tap++) {
        int off = (tap - 1) * dil;
        int tt = t + off;
        if (tt >= 0 && tt < T_) {
            float mm = __ldg(&mask[tok + off]);
            const float4* hr = reinterpret_cast<const float4*>(g_h + (size_t)(tok + off) * F_);
            float4 h0 = hr[lane], h1 = hr[lane + 32];
            float4 k0 = s_k[tap][lane], k1 = s_k[tap][lane + 32];
            a[0] += h0.x * mm * k0.x; a[1] += h0.y * mm * k0.y;
            a[2] += h0.z * mm * k0.z; a[3] += h0.w * mm * k0.w;
            a[4] += h1.x * mm * k1.x; a[5] += h1.y * mm * k1.y;
            a[6] += h1.z * mm * k1.z; a[7] += h1.w * mm * k1.w;
        }
    }

    float s = 0.f, ss = 0.f;
    #pragma unroll
    for (int j = 0; j < 8; j++) { s += a[j]; ss += a[j] * a[j]; }
    #pragma unroll
    for (int o = 16; o; o >>= 1) {
        s  += __shfl_xor_sync(0xFFFFFFFFu, s,  o);
        ss += __shfl_xor_sync(0xFFFFFFFFu, ss, o);
    }
    float mean = s * (1.0f / F_);
    float rstd = rsqrtf(ss * (1.0f / F_) - mean * mean + 1e-5f);

    float4 gg0 = s_g[lane], gg1 = s_g[lane + 32];
    float4 bb0 = s_bb[lane], bb1 = s_bb[lane + 32];
    float garr[8] = {gg0.x, gg0.y, gg0.z, gg0.w, gg1.x, gg1.y, gg1.z, gg1.w};
    float barr[8] = {bb0.x, bb0.y, bb0.z, bb0.w, bb1.x, bb1.y, bb1.z, bb1.w};

    float4 o0, o1;
    float r[8];
    #pragma unroll
    for (int j = 0; j < 8; j++) {
        float v = (a[j] - mean) * rstd * garr[j] + barr[j];
        r[j] = gelu_f(v);
    }
    o0.x = r[0]; o0.y = r[1]; o0.z = r[2]; o0.w = r[3];
    o1.x = r[4]; o1.y = r[5]; o1.z = r[6]; o1.w = r[7];
    float4* yr = reinterpret_cast<float4*>(g_y + (size_t)tok * F_);
    yr[lane] = o0;
    yr[lane + 32] = o1;
}

// ---------------------------------------------------------------------------
// Kernel 3: mma.sync GEMM  h += gelu(LN2(y @ w11 + b11))
// CTA: 64 tokens x 256 cols, K=256. 256 threads = 8 warps (1 M x 8 N),
// warp tile 64x32. 2 CTAs/SM for phase overlap.
// ---------------------------------------------------------------------------
#define AROW   264                     // bf16 row stride (528B -> conflict-free)
#define GSMEM  (2 * 64 * AROW * 2 + 256)    // A hi + lo + align slack (~67.8KB)

__global__ void __launch_bounds__(256, 2)
gemm_mma_kernel(int layer,
                const float* __restrict__ b11,
                const float* __restrict__ g2,
                const float* __restrict__ b2) {
    extern __shared__ char dyn[];
    char* basep = (char*)(((uintptr_t)dyn + 15) & ~(uintptr_t)15);
    __nv_bfloat16* Ahi = reinterpret_cast<__nv_bfloat16*>(basep);
    __nv_bfloat16* Alo = Ahi + 64 * AROW;
    float* stag = reinterpret_cast<float*>(basep);   // reused post-mainloop [64][260]
    const int SROW = 260;

    const int tid  = threadIdx.x;
    const int wid  = tid >> 5;          // 0..7 -> n group
    const int lane = tid & 31;
    const int tg   = lane >> 2, tq = lane & 3;
    const int wn   = wid;
    const int m0   = blockIdx.x * 64;

    // ---- load A (64 x 256 fp32) -> bf16 hi/lo SMEM ----
    {
        int row = tid >> 2;             // 0..63
        int kq  = (tid & 3) * 64;
        const float4* src = reinterpret_cast<const float4*>(
            g_y + (size_t)(m0 + row) * F_ + kq);
        #pragma unroll
        for (int j = 0; j < 16; j++) {
            float4 v = src[j];
            float hx = __bfloat162float(__float2bfloat16(v.x));
            float hy = __bfloat162float(__float2bfloat16(v.y));
            float hz = __bfloat162float(__float2bfloat16(v.z));
            float hw = __bfloat162float(__float2bfloat16(v.w));
            uint2 hp, lp;
            hp.x = pack_bf16x2(v.x, v.y);
            hp.y = pack_bf16x2(v.z, v.w);
            lp.x = pack_bf16x2(v.x - hx, v.y - hy);
            lp.y = pack_bf16x2(v.z - hz, v.w - hw);
            int c = kq + j * 4;
            *reinterpret_cast<uint2*>(Ahi + row * AROW + c) = hp;
            *reinterpret_cast<uint2*>(Alo + row * AROW + c) = lp;
        }
    }
    __syncthreads();

    // ---- mainloop ----
    float d[4][4][4];
    #pragma unroll
    for (int mt = 0; mt < 4; mt++)
        #pragma unroll
        for (int nt = 0; nt < 4; nt++)
            #pragma unroll
            for (int q = 0; q < 4; q++) d[mt][nt][q] = 0.f;

    const uint4* Bbase = g_Bfrag + ((size_t)(layer * 32 + wn * 4) * 16) * 32 + lane;
    uint4 bcur[4], bnxt[4];
    #pragma unroll
    for (int nt = 0; nt < 4; nt++) bcur[nt] = __ldg(&Bbase[(nt * 16 + 0) * 32]);

    uint32_t a_hi_addr[4], a_lo_addr[4];
    {
        int r = lane & 15;
        int cb = (lane >> 4) * 16;      // 16-byte column offset
        #pragma unroll
        for (int mt = 0; mt < 4; mt++) {
            int row = mt * 16 + r;
            a_hi_addr[mt] = (uint32_t)__cvta_generic_to_shared(Ahi + row * AROW) + cb;
            a_lo_addr[mt] = (uint32_t)__cvta_generic_to_shared(Alo + row * AROW) + cb;
        }
    }

    #pragma unroll 1
    for (int ks = 0; ks < 16; ks++) {
        if (ks < 15) {
            #pragma unroll
            for (int nt = 0; nt < 4; nt++)
                bnxt[nt] = __ldg(&Bbase[(nt * 16 + ks + 1) * 32]);
        }
        const uint32_t koff = ks * 32;  // 16 bf16 = 32 bytes per k-step
        #pragma unroll
        for (int mt = 0; mt < 4; mt++) {
            uint32_t ah[4], al[4];
            ldmx4(ah, a_hi_addr[mt] + koff);
            ldmx4(al, a_lo_addr[mt] + koff);
            #pragma unroll
            for (int nt = 0; nt < 4; nt++) {
                mma16816(d[mt][nt], ah, bcur[nt].x, bcur[nt].y);  // Ah*Bh
                mma16816(d[mt][nt], ah, bcur[nt].z, bcur[nt].w);  // Ah*Bl
                mma16816(d[mt][nt], al, bcur[nt].x, bcur[nt].y);  // Al*Bh
            }
        }
        #pragma unroll
        for (int nt = 0; nt < 4; nt++) bcur[nt] = bnxt[nt];
    }

    // ---- stage accum to SMEM (reuse A region) ----
    __syncthreads();
    #pragma unroll
    for (int mt = 0; mt < 4; mt++) {
        int r0 = mt * 16 + tg;
        #pragma unroll
        for (int nt = 0; nt < 4; nt++) {
            int col = wn * 32 + nt * 8 + tq * 2;
            *reinterpret_cast<float2*>(&stag[r0 * SROW + col]) =
                make_float2(d[mt][nt][0], d[mt][nt][1]);
            *reinterpret_cast<float2*>(&stag[(r0 + 8) * SROW + col]) =
                make_float2(d[mt][nt][2], d[mt][nt][3]);
        }
    }
    __syncthreads();

    // ---- LN2 + gelu + residual: each warp 8 rows, lane covers 8 cols ----
    #pragma unroll 1
    for (int i = 0; i < 8; i++) {
        int row = wid * 8 + i;
        float4 f0 = *reinterpret_cast<const float4*>(&stag[row * SROW + lane * 8]);
        float4 f1 = *reinterpret_cast<const float4*>(&stag[row * SROW + lane * 8 + 4]);
        float4 bb0 = reinterpret_cast<const float4*>(b11)[lane * 2];
        float4 bb1 = reinterpret_cast<const float4*>(b11)[lane * 2 + 1];
        float v[8] = {f0.x + bb0.x, f0.y + bb0.y, f0.z + bb0.z, f0.w + bb0.w,
                      f1.x + bb1.x, f1.y + bb1.y, f1.z + bb1.z, f1.w + bb1.w};
        float s = 0.f, ss = 0.f;
        #pragma unroll
        for (int j = 0; j < 8; j++) { s += v[j]; ss += v[j] * v[j]; }
        #pragma unroll
        for (int o = 16; o; o >>= 1) {
            s  += __shfl_xor_sync(0xFFFFFFFFu, s,  o);
            ss += __shfl_xor_sync(0xFFFFFFFFu, ss, o);
        }
        float mean = s * (1.0f / F_);
        float rstd = rsqrtf(ss * (1.0f / F_) - mean * mean + 1e-5f);

        float4 gg0 = reinterpret_cast<const float4*>(g2)[lane * 2];
        float4 gg1 = reinterpret_cast<const float4*>(g2)[lane * 2 + 1];
        float4 zb0 = reinterpret_cast<const float4*>(b2)[lane * 2];
        float4 zb1 = reinterpret_cast<const float4*>(b2)[lane * 2 + 1];
        float garr[8] = {gg0.x, gg0.y, gg0.z, gg0.w, gg1.x, gg1.y, gg1.z, gg1.w};
        float barr[8] = {zb0.x, zb0.y, zb0.z, zb0.w, zb1.x, zb1.y, zb1.z, zb1.w};

        float4* hp = reinterpret_cast<float4*>(g_h + (size_t)(m0 + row) * F_ + lane * 8);
        float4 h0 = hp[0], h1 = hp[1];
        float hv[8] = {h0.x, h0.y, h0.z, h0.w, h1.x, h1.y, h1.z, h1.w};
        #pragma unroll
        for (int j = 0; j < 8; j++) {
            float z = (v[j] - mean) * rstd * garr[j] + barr[j];
            hv[j] += gelu_f(z);
        }
        hp[0] = make_float4(hv[0], hv[1], hv[2], hv[3]);
        hp[1] = make_float4(hv[4], hv[5], hv[6], hv[7]);
    }
}

// ---------------------------------------------------------------------------
// Kernel 4a: projection h[tok]@w_proj -> g_proj[tok][29] (stride 32)
// ---------------------------------------------------------------------------
__global__ void __launch_bounds__(256)
proj_kernel(const float* __restrict__ mask, const float* __restrict__ w_proj) {
    __shared__ float s_w[PROJ_][256];   // [p][f], conflict-free lane access
    int tid = threadIdx.x;
    for (int i = tid; i < PROJ_ * 256; i += 256) {
        int f = i / PROJ_;
        int p = i - f * PROJ_;
        s_w[p][f] = w_proj[i];
    }
    __syncthreads();

    int wrp  = tid >> 5;
    int lane = tid & 31;
    int tokbase = blockIdx.x * 64 + wrp * 8;

    float hv[8][8];
    #pragma unroll
    for (int t = 0; t < 8; t++) {
        float mm = __ldg(&mask[tokbase + t]);
        const float* hr = g_h + (size_t)(tokbase + t) * F_;
        #pragma unroll
        for (int j = 0; j < 8; j++) hv[t][j] = hr[lane + 32 * j] * mm;
    }

    #pragma unroll 1
    for (int p = 0; p < PROJ_; p++) {
        float w[8];
        #pragma unroll
        for (int j = 0; j < 8; j++) w[j] = s_w[p][lane + 32 * j];
        float part[8];
        #pragma unroll
        for (int t = 0; t < 8; t++) {
            float s = 0.f;
            #pragma unroll
            for (int j = 0; j < 8; j++) s += hv[t][j] * w[j];
            part[t] = s;
        }
        #pragma unroll
        for (int o = 16; o; o >>= 1) {
            #pragma unroll
            for (int t = 0; t < 8; t++)
                part[t] += __shfl_xor_sync(0xFFFFFFFFu, part[t], o);
        }
        if (lane < 8) {
            float v = part[0];
            #pragma unroll
            for (int t = 1; t < 8; t++) if (lane == t) v = part[t];
            g_proj[(size_t)(tokbase + lane) * 32 + p] = v;
        }
    }
}

// ---------------------------------------------------------------------------
// Kernel 4b: RQ spline, one THREAD per token
// ---------------------------------------------------------------------------
__device__ __forceinline__ float softplus_f(float v) {
    return fmaxf(v, 0.f) + log1pf(expf(-fabsf(v)));
}

__global__ void __launch_bounds__(256)
spline_kernel(const float* __restrict__ x,
              const float* __restrict__ mask,
              const float* __restrict__ b_proj,
              float* __restrict__ out) {
    int tok = blockIdx.x * 256 + threadIdx.x;
    float m = mask[tok];

    float proj[PROJ_];
    #pragma unroll
    for (int p = 0; p < PROJ_; p++)
        proj[p] = (g_proj[(size_t)tok * 32 + p] + __ldg(&b_proj[p])) * m;

    const float scale = 0.0625f;  // 1/sqrt(256)

    float cw[NB_ + 1], ww[NB_];
    {
        float mx = proj[0] * scale;
        #pragma unroll
        for (int j = 1; j < NB_; j++) mx = fmaxf(mx, proj[j] * scale);
        float e[NB_], sum = 0.f;
        #pragma unroll
        for (int j = 0; j < NB_; j++) { e[j] = expf(proj[j] * scale - mx); sum += e[j]; }
        float inv = 1.0f / sum;
        float cum = 0.f;
        cw[0] = -TBND;
        #pragma unroll
        for (int j = 0; j < NB_; j++) {
            float wj = 0.001f + (1.0f - 0.001f * NB_) * (e[j] * inv);
            cum += wj;
            cw[j + 1] = 2.0f * TBND * cum - TBND;
        }
        cw[NB_] = TBND;
        #pragma unroll
        for (int j = 0; j < NB_; j++) ww[j] = cw[j + 1] - cw[j];
    }
    float ch[NB_ + 1], hh[NB_];
    {
        float mx = proj[NB_] * scale;
        #pragma unroll
        for (int j = 1; j < NB_; j++) mx = fmaxf(mx, proj[NB_ + j] * scale);
        float e[NB_], sum = 0.f;
        #pragma unroll
        for (int j = 0; j < NB_; j++) { e[j] = expf(proj[NB_ + j] * scale - mx); sum += e[j]; }
        float inv = 1.0f / sum;
        float cum = 0.f;
        ch[0] = -TBND;
        #pragma unroll
        for (int j = 0; j < NB_; j++) {
            float hj = 0.001f + (1.0f - 0.001f * NB_) * (e[j] * inv);
            cum += hj;
            ch[j + 1] = 2.0f * TBND * cum - TBND;
        }
        ch[NB_] = TBND;
        #pragma unroll
        for (int j = 0; j < NB_; j++) hh[j] = ch[j + 1] - ch[j];
    }
    float d[NB_ + 1];
    float cst = logf(expm1f(1.0f - 0.001f));
    d[0]   = 0.001f + softplus_f(cst);
    d[NB_] = d[0];
    #pragma unroll
    for (int k = 1; k < NB_; k++) d[k] = 0.001f + softplus_f(proj[2 * NB_ + k - 1]);

    float x1 = x[(size_t)tok * 2 + 1];
    float xc = fminf(fmaxf(x1, -TBND), TBND);
    int idx = 0;
    #pragma unroll
    for (int j = 1; j <= NB_; j++) idx += (xc >= cw[j]) ? 1 : 0;
    if (idx > NB_ - 1) idx = NB_ - 1;

    float icw = cw[idx], ibw = ww[idx];
    float ich = ch[idx], ibh = hh[idx];
    float delta = ibh / ibw;
    float dk = d[idx], dk1 = d[idx + 1];
    float th   = (xc - icw) / ibw;
    float th1m = th * (1.0f - th);
    float denom = delta + (dk + dk1 - 2.0f * delta) * th1m;
    float num   = ibh * (delta * th * th + dk * th1m);
    float yv    = ich + num / denom;
    float omth  = 1.0f - th;
    float dnum  = delta * delta * (dk1 * th * th + 2.0f * delta * th1m + dk * omth * omth);
    float lad   = logf(dnum) - 2.0f * logf(denom);

    bool inside = (x1 >= -TBND) && (x1 <= TBND);
    float y1 = inside ? yv : x1;
    lad = inside ? lad : 0.0f;

    out[(size_t)tok * 2]     = x[(size_t)tok * 2] * m;
    out[(size_t)tok * 2 + 1] = y1 * m;
    g_lad[tok] = lad * m;
}

// ---------------------------------------------------------------------------
// Kernel 5: deterministic per-batch logdet reduction
// ---------------------------------------------------------------------------
__global__ void logdet_kernel(float* __restrict__ out) {
    int b = blockIdx.x, tid = threadIdx.x;
    float s = 0.f;
    for (int j = tid; j < T_; j += 256) s += g_lad[b * T_ + j];
    __shared__ float sh[256];
    sh[tid] = s;
    __syncthreads();
    #pragma unroll
    for (int o = 128; o; o >>= 1) {
        if (tid < o) sh[tid] += sh[tid + o];
        __syncthreads();
    }
    if (tid == 0) out[(size_t)BT_ * 2 + b] = sh[0];
}

// ---------------------------------------------------------------------------
extern "C" void kernel_launch(void* const* d_in, const int* in_sizes, int n_in,
                              void* d_out, int out_size) {
    const float* x      = (const float*)d_in[0];
    const float* mask   = (const float*)d_in[1];
    const float* w_pre  = (const float*)d_in[2];
    const float* b_pre  = (const float*)d_in[3];
    const float* dw_k   = (const float*)d_in[4];
    const float* dw_b   = (const float*)d_in[5];
    const float* w11    = (const float*)d_in[6];
    const float* b11    = (const float*)d_in[7];
    const float* ln1g   = (const float*)d_in[8];
    const float* ln1b   = (const float*)d_in[9];
    const float* ln2g   = (const float*)d_in[10];
    const float* ln2b   = (const float*)d_in[11];
    const float* w_proj = (const float*)d_in[12];
    const float* b_proj = (const float*)d_in[13];
    float* out = (float*)d_out;

    cudaFuncSetAttribute(gemm_mma_kernel,
                         cudaFuncAttributeMaxDynamicSharedMemorySize, GSMEM);

    prep_bfrag_kernel<<<NL_ * 32 * 16, 32>>>(w11);
    pre_kernel<<<BT_ * 64 / 256, 256>>>(x, w_pre, b_pre);

    int dil = 1;
    for (int i = 0; i < NL_; i++) {
        conv_ln_gelu_kernel<<<BT_ / 8, 256>>>(mask,
                                              dw_k + (size_t)i * KS_ * F_,
                                              dw_b + (size_t)i * F_,
                                              ln1g + (size_t)i * F_,
                                              ln1b + (size_t)i * F_,
                                              dil);
        gemm_mma_kernel<<<BT_ / 64, 256, GSMEM>>>(i,
                                                  b11 + (size_t)i * F_,
                                                  ln2g + (size_t)i * F_,
                                                  ln2b + (size_t)i * F_);
        dil *= KS_;
    }

    proj_kernel<<<BT_ / 64, 256>>>(mask, w_proj);
    spline_kernel<<<BT_ / 256, 256>>>(x, mask, b_proj, out);
    logdet_kernel<<<B_, 256>>>(out);
}

// round 8
// speedup vs baseline: 3.0747x; 1.0293x over previous
#include <cuda_runtime.h>
#include <cuda_bf16.h>
#include <math.h>
#include <stdint.h>
#include <cstdint>

#define B_    16
#define T_    8192
#define F_    256
#define NL_   3
#define KS_   3
#define NB_   10
#define PROJ_ 29
#define BT_   (B_*T_)
#define TBND  5.0f

__device__ float g_h[(size_t)BT_ * F_];
__device__ float g_y[(size_t)BT_ * F_];
__device__ float g_lad[BT_];
__device__ float g_proj[(size_t)BT_ * 32];
__device__ uint4 g_Bfrag[NL_ * 32 * 16 * 32];

__device__ __forceinline__ float gelu_f(float v) {
    return 0.5f * v * (1.0f + erff(v * 0.7071067811865476f));
}

__device__ __forceinline__ void mma16816(float* d, const uint32_t* a,
                                         uint32_t b0, uint32_t b1) {
    asm volatile(
        "mma.sync.aligned.m16n8k16.row.col.f32.bf16.bf16.f32 "
        "{%0,%1,%2,%3}, {%4,%5,%6,%7}, {%8,%9}, {%0,%1,%2,%3};"
        : "+f"(d[0]), "+f"(d[1]), "+f"(d[2]), "+f"(d[3])
        : "r"(a[0]), "r"(a[1]), "r"(a[2]), "r"(a[3]), "r"(b0), "r"(b1));
}

__device__ __forceinline__ void ldmx4(uint32_t* r, uint32_t addr) {
    asm volatile("ldmatrix.sync.aligned.m8n8.x4.shared.b16 {%0,%1,%2,%3}, [%4];"
        : "=r"(r[0]), "=r"(r[1]), "=r"(r[2]), "=r"(r[3]) : "r"(addr));
}

__device__ __forceinline__ uint32_t pack_bf16x2(float x, float y) {
    __nv_bfloat162 p = __halves2bfloat162(__float2bfloat16(x), __float2bfloat16(y));
    return *reinterpret_cast<uint32_t*>(&p);
}

// ---------------------------------------------------------------------------
// Kernel 0: pack w11 into mma B fragments (hi/lo split)
// ---------------------------------------------------------------------------
__global__ void prep_bfrag_kernel(const float* __restrict__ w11) {
    int blk  = blockIdx.x;
    int lane = threadIdx.x;
    int ks   = blk & 15;
    int nt   = (blk >> 4) & 31;
    int l    = blk >> 9;
    int tg   = lane >> 2, tid = lane & 3;
    int n    = nt * 8 + tg;
    int k0   = ks * 16 + tid * 2;

    const float* w = w11 + (size_t)l * F_ * F_;
    float v00 = w[(size_t)(k0    ) * F_ + n];
    float v01 = w[(size_t)(k0 + 1) * F_ + n];
    float v10 = w[(size_t)(k0 + 8) * F_ + n];
    float v11 = w[(size_t)(k0 + 9) * F_ + n];

    float h00 = __bfloat162float(__float2bfloat16(v00));
    float h01 = __bfloat162float(__float2bfloat16(v01));
    float h10 = __bfloat162float(__float2bfloat16(v10));
    float h11 = __bfloat162float(__float2bfloat16(v11));

    uint4 o;
    o.x = pack_bf16x2(v00, v01);
    o.y = pack_bf16x2(v10, v11);
    o.z = pack_bf16x2(v00 - h00, v01 - h01);
    o.w = pack_bf16x2(v10 - h10, v11 - h11);
    g_Bfrag[(size_t)blk * 32 + lane] = o;
}

// ---------------------------------------------------------------------------
// Kernel 2a: FUSED layer-0 conv: computes pre (h = x0*w_pre+b_pre) inline,
// writes g_h, and y = gelu(LN1(conv(h*mask))). dil == 1. Warp per token.
// ---------------------------------------------------------------------------
__global__ void conv0_fused_kernel(const float* __restrict__ x,
                                   const float* __restrict__ mask,
                                   const float* __restrict__ w_pre,
                                   const float* __restrict__ b_pre,
                                   const float* __restrict__ dwk,
                                   const float* __restrict__ dwb,
                                   const float* __restrict__ g1,
                                   const float* __restrict__ b1) {
    __shared__ float4 s_k[3][64], s_b[64], s_g[64], s_bb[64], s_wp[64], s_bp[64];
    int tidx = threadIdx.x;
    if (tidx < 64) {
        s_k[0][tidx] = reinterpret_cast<const float4*>(dwk)[tidx];
        s_k[1][tidx] = reinterpret_cast<const float4*>(dwk)[64 + tidx];
        s_k[2][tidx] = reinterpret_cast<const float4*>(dwk)[128 + tidx];
        s_wp[tidx]   = reinterpret_cast<const float4*>(w_pre)[tidx];
    } else if (tidx < 128) {
        s_b[tidx - 64]  = reinterpret_cast<const float4*>(dwb)[tidx - 64];
        s_bp[tidx - 64] = reinterpret_cast<const float4*>(b_pre)[tidx - 64];
    } else if (tidx < 192) {
        s_g[tidx - 128] = reinterpret_cast<const float4*>(g1)[tidx - 128];
    } else {
        s_bb[tidx - 192] = reinterpret_cast<const float4*>(b1)[tidx - 192];
    }
    __syncthreads();

    int wid  = tidx >> 5;
    int lane = tidx & 31;
    int tok  = blockIdx.x * 8 + wid;
    int t    = tok & (T_ - 1);

    // load x0 for the 3 taps
    float x0m1 = (t - 1 >= 0) ? __ldg(&x[(size_t)(tok - 1) * 2]) : 0.f;
    float x00  = __ldg(&x[(size_t)tok * 2]);
    float x0p1 = (t + 1 < T_) ? __ldg(&x[(size_t)(tok + 1) * 2]) : 0.f;
    float mm1  = (t - 1 >= 0) ? __ldg(&mask[tok - 1]) : 0.f;
    float m0   = __ldg(&mask[tok]);
    float mp1  = (t + 1 < T_) ? __ldg(&mask[tok + 1]) : 0.f;

    float wp[8], bp[8];
    {
        float4 a0 = s_wp[lane], a1 = s_wp[lane + 32];
        float4 c0 = s_bp[lane], c1 = s_bp[lane + 32];
        wp[0]=a0.x; wp[1]=a0.y; wp[2]=a0.z; wp[3]=a0.w;
        wp[4]=a1.x; wp[5]=a1.y; wp[6]=a1.z; wp[7]=a1.w;
        bp[0]=c0.x; bp[1]=c0.y; bp[2]=c0.z; bp[3]=c0.w;
        bp[4]=c1.x; bp[5]=c1.y; bp[6]=c1.z; bp[7]=c1.w;
    }

    float a[8];
    {
        float4 b0 = s_b[lane], b1v = s_b[lane + 32];
        a[0]=b0.x; a[1]=b0.y; a[2]=b0.z; a[3]=b0.w;
        a[4]=b1v.x; a[5]=b1v.y; a[6]=b1v.z; a[7]=b1v.w;
    }
    float hown[8];

    // tap 0 (t-1), tap 1 (t), tap 2 (t+1)
    float xs[3] = {x0m1, x00, x0p1};
    float ms[3] = {mm1, m0, mp1};
    bool  ok[3] = {t - 1 >= 0, true, t + 1 < T_};
    #pragma unroll
    for (int tap = 0; tap < 3; tap++) {
        float4 k0 = s_k[tap][lane], k1 = s_k[tap][lane + 32];
        float karr[8] = {k0.x,k0.y,k0.z,k0.w,k1.x,k1.y,k1.z,k1.w};
        float xm = xs[tap] * ms[tap];
        float mmk = ms[tap];
        #pragma unroll
        for (int j = 0; j < 8; j++) {
            float hval = xs[tap] * wp[j] + bp[j];
            if (tap == 1) hown[j] = hval;
            if (ok[tap]) a[j] += (xm * wp[j] + mmk * bp[j]) * karr[j];
        }
    }

    // write g_h (pre output, unmasked)
    {
        float4 o0 = make_float4(hown[0],hown[1],hown[2],hown[3]);
        float4 o1 = make_float4(hown[4],hown[5],hown[6],hown[7]);
        float4* hw = reinterpret_cast<float4*>(g_h + (size_t)tok * F_);
        hw[lane] = o0;
        hw[lane + 32] = o1;
    }

    float s = 0.f, ss = 0.f;
    #pragma unroll
    for (int j = 0; j < 8; j++) { s += a[j]; ss += a[j] * a[j]; }
    #pragma unroll
    for (int o = 16; o; o >>= 1) {
        s  += __shfl_xor_sync(0xFFFFFFFFu, s,  o);
        ss += __shfl_xor_sync(0xFFFFFFFFu, ss, o);
    }
    float mean = s * (1.0f / F_);
    float rstd = rsqrtf(ss * (1.0f / F_) - mean * mean + 1e-5f);

    float4 gg0 = s_g[lane], gg1 = s_g[lane + 32];
    float4 bb0 = s_bb[lane], bb1 = s_bb[lane + 32];
    float garr[8] = {gg0.x,gg0.y,gg0.z,gg0.w,gg1.x,gg1.y,gg1.z,gg1.w};
    float barr[8] = {bb0.x,bb0.y,bb0.z,bb0.w,bb1.x,bb1.y,bb1.z,bb1.w};

    float r[8];
    #pragma unroll
    for (int j = 0; j < 8; j++) {
        float v = (a[j] - mean) * rstd * garr[j] + barr[j];
        r[j] = gelu_f(v);
    }
    float4* yr = reinterpret_cast<float4*>(g_y + (size_t)tok * F_);
    yr[lane]      = make_float4(r[0], r[1], r[2], r[3]);
    yr[lane + 32] = make_float4(r[4], r[5], r[6], r[7]);
}

// ---------------------------------------------------------------------------
// Kernel 2b: layers 1-2 conv (reads g_h); warp per token
// ---------------------------------------------------------------------------
__global__ void conv_ln_gelu_kernel(const float* __restrict__ mask,
                                    const float* __restrict__ dwk,
                                    const float* __restrict__ dwb,
                                    const float* __restrict__ g1,
                                    const float* __restrict__ b1,
                                    int dil) {
    __shared__ float4 s_k[3][64], s_b[64], s_g[64], s_bb[64];
    int tidx = threadIdx.x;
    if (tidx < 64) {
        s_k[0][tidx] = reinterpret_cast<const float4*>(dwk)[tidx];
        s_k[1][tidx] = reinterpret_cast<const float4*>(dwk)[64 + tidx];
        s_k[2][tidx] = reinterpret_cast<const float4*>(dwk)[128 + tidx];
    } else if (tidx < 128) {
        s_b[tidx - 64] = reinterpret_cast<const float4*>(dwb)[tidx - 64];
    } else if (tidx < 192) {
        s_g[tidx - 128] = reinterpret_cast<const float4*>(g1)[tidx - 128];
    } else {
        s_bb[tidx - 192] = reinterpret_cast<const float4*>(b1)[tidx - 192];
    }
    __syncthreads();

    int wid  = tidx >> 5;
    int lane = tidx & 31;
    int tok  = blockIdx.x * 8 + wid;
    int t    = tok & (T_ - 1);

    float a[8];
    {
        float4 b0 = s_b[lane], b1v = s_b[lane + 32];
        a[0]=b0.x; a[1]=b0.y; a[2]=b0.z; a[3]=b0.w;
        a[4]=b1v.x; a[5]=b1v.y; a[6]=b1v.z; a[7]=b1v.w;
    }

    #pragma unroll
    for (int tap = 0; tap < 3; tap++) {
        int off = (tap - 1) * dil;
        int tt = t + off;
        if (tt >= 0 && tt < T_) {
            float mm = __ldg(&mask[tok + off]);
            const float4* hr = reinterpret_cast<const float4*>(g_h + (size_t)(tok + off) * F_);
            float4 h0 = hr[lane], h1 = hr[lane + 32];
            float4 k0 = s_k[tap][lane], k1 = s_k[tap][lane + 32];
            a[0] += h0.x * mm * k0.x; a[1] += h0.y * mm * k0.y;
            a[2] += h0.z * mm * k0.z; a[3] += h0.w * mm * k0.w;
            a[4] += h1.x * mm * k1.x; a[5] += h1.y * mm * k1.y;
            a[6] += h1.z * mm * k1.z; a[7] += h1.w * mm * k1.w;
        }
    }

    float s = 0.f, ss = 0.f;
    #pragma unroll
    for (int j = 0; j < 8; j++) { s += a[j]; ss += a[j] * a[j]; }
    #pragma unroll
    for (int o = 16; o; o >>= 1) {
        s  += __shfl_xor_sync(0xFFFFFFFFu, s,  o);
        ss += __shfl_xor_sync(0xFFFFFFFFu, ss, o);
    }
    float mean = s * (1.0f / F_);
    float rstd = rsqrtf(ss * (1.0f / F_) - mean * mean + 1e-5f);

    float4 gg0 = s_g[lane], gg1 = s_g[lane + 32];
    float4 bb0 = s_bb[lane], bb1 = s_bb[lane + 32];
    float garr[8] = {gg0.x,gg0.y,gg0.z,gg0.w,gg1.x,gg1.y,gg1.z,gg1.w};
    float barr[8] = {bb0.x,bb0.y,bb0.z,bb0.w,bb1.x,bb1.y,bb1.z,bb1.w};

    float r[8];
    #pragma unroll
    for (int j = 0; j < 8; j++) {
        float v = (a[j] - mean) * rstd * garr[j] + barr[j];
        r[j] = gelu_f(v);
    }
    float4* yr = reinterpret_cast<float4*>(g_y + (size_t)tok * F_);
    yr[lane]      = make_float4(r[0], r[1], r[2], r[3]);
    yr[lane + 32] = make_float4(r[4], r[5], r[6], r[7]);
}

// ---------------------------------------------------------------------------
// Kernel 3: mma.sync GEMM  h += gelu(LN2(y @ w11 + b11))
// CTA: 32 tokens x 256 cols, 256 threads = 8 warps, warp tile 32x32.
// 3 CTAs/SM target.
// ---------------------------------------------------------------------------
#define AROW   264
#define GSMEM  (2 * 32 * AROW * 2 + 256)    // ~34KB

__global__ void __launch_bounds__(256, 3)
gemm_mma_kernel(int layer,
                const float* __restrict__ b11,
                const float* __restrict__ g2,
                const float* __restrict__ b2) {
    extern __shared__ char dyn[];
    char* basep = (char*)(((uintptr_t)dyn + 15) & ~(uintptr_t)15);
    __nv_bfloat16* Ahi = reinterpret_cast<__nv_bfloat16*>(basep);
    __nv_bfloat16* Alo = Ahi + 32 * AROW;
    float* stag = reinterpret_cast<float*>(basep);   // reused [32][260]
    const int SROW = 260;

    const int tid  = threadIdx.x;
    const int wid  = tid >> 5;
    const int lane = tid & 31;
    const int tg   = lane >> 2, tq = lane & 3;
    const int wn   = wid;
    const int m0   = blockIdx.x * 32;

    // ---- load A (32 x 256 fp32) -> bf16 hi/lo SMEM ----
    {
        int row = tid >> 3;             // 0..31
        int c8  = tid & 7;
        const float4* src = reinterpret_cast<const float4*>(
            g_y + (size_t)(m0 + row) * F_);
        #pragma unroll
        for (int j = 0; j < 8; j++) {
            float4 v = src[c8 + 8 * j];
            float hx = __bfloat162float(__float2bfloat16(v.x));
            float hy = __bfloat162float(__float2bfloat16(v.y));
            float hz = __bfloat162float(__float2bfloat16(v.z));
            float hw = __bfloat162float(__float2bfloat16(v.w));
            uint2 hp, lp;
            hp.x = pack_bf16x2(v.x, v.y);
            hp.y = pack_bf16x2(v.z, v.w);
            lp.x = pack_bf16x2(v.x - hx, v.y - hy);
            lp.y = pack_bf16x2(v.z - hz, v.w - hw);
            int c = (c8 + 8 * j) * 4;
            *reinterpret_cast<uint2*>(Ahi + row * AROW + c) = hp;
            *reinterpret_cast<uint2*>(Alo + row * AROW + c) = lp;
        }
    }
    __syncthreads();

    // ---- mainloop ----
    float d[2][4][4];
    #pragma unroll
    for (int mt = 0; mt < 2; mt++)
        #pragma unroll
        for (int nt = 0; nt < 4; nt++)
            #pragma unroll
            for (int q = 0; q < 4; q++) d[mt][nt][q] = 0.f;

    const uint4* Bbase = g_Bfrag + ((size_t)(layer * 32 + wn * 4) * 16) * 32 + lane;
    uint4 bcur[4], bnxt[4];
    #pragma unroll
    for (int nt = 0; nt < 4; nt++) bcur[nt] = __ldg(&Bbase[(nt * 16 + 0) * 32]);

    uint32_t a_hi_addr[2], a_lo_addr[2];
    {
        int r = lane & 15;
        int cb = (lane >> 4) * 16;
        #pragma unroll
        for (int mt = 0; mt < 2; mt++) {
            int row = mt * 16 + r;
            a_hi_addr[mt] = (uint32_t)__cvta_generic_to_shared(Ahi + row * AROW) + cb;
            a_lo_addr[mt] = (uint32_t)__cvta_generic_to_shared(Alo + row * AROW) + cb;
        }
    }

    #pragma unroll 1
    for (int ks = 0; ks < 16; ks++) {
        if (ks < 15) {
            #pragma unroll
            for (int nt = 0; nt < 4; nt++)
                bnxt[nt] = __ldg(&Bbase[(nt * 16 + ks + 1) * 32]);
        }
        const uint32_t koff = ks * 32;
        #pragma unroll
        for (int mt = 0; mt < 2; mt++) {
            uint32_t ah[4], al[4];
            ldmx4(ah, a_hi_addr[mt] + koff);
            ldmx4(al, a_lo_addr[mt] + koff);
            #pragma unroll
            for (int nt = 0; nt < 4; nt++) {
                mma16816(d[mt][nt], ah, bcur[nt].x, bcur[nt].y);
                mma16816(d[mt][nt], ah, bcur[nt].z, bcur[nt].w);
                mma16816(d[mt][nt], al, bcur[nt].x, bcur[nt].y);
            }
        }
        #pragma unroll
        for (int nt = 0; nt < 4; nt++) bcur[nt] = bnxt[nt];
    }

    // ---- stage accum to SMEM ----
    __syncthreads();
    #pragma unroll
    for (int mt = 0; mt < 2; mt++) {
        int r0 = mt * 16 + tg;
        #pragma unroll
        for (int nt = 0; nt < 4; nt++) {
            int col = wn * 32 + nt * 8 + tq * 2;
            *reinterpret_cast<float2*>(&stag[r0 * SROW + col]) =
                make_float2(d[mt][nt][0], d[mt][nt][1]);
            *reinterpret_cast<float2*>(&stag[(r0 + 8) * SROW + col]) =
                make_float2(d[mt][nt][2], d[mt][nt][3]);
        }
    }
    __syncthreads();

    // ---- LN2 + gelu + residual: each warp 4 rows ----
    #pragma unroll 1
    for (int i = 0; i < 4; i++) {
        int row = wid * 4 + i;
        float4 f0 = *reinterpret_cast<const float4*>(&stag[row * SROW + lane * 8]);
        float4 f1 = *reinterpret_cast<const float4*>(&stag[row * SROW + lane * 8 + 4]);
        float4 bb0 = reinterpret_cast<const float4*>(b11)[lane * 2];
        float4 bb1 = reinterpret_cast<const float4*>(b11)[lane * 2 + 1];
        float v[8] = {f0.x + bb0.x, f0.y + bb0.y, f0.z + bb0.z, f0.w + bb0.w,
                      f1.x + bb1.x, f1.y + bb1.y, f1.z + bb1.z, f1.w + bb1.w};
        float s = 0.f, ss = 0.f;
        #pragma unroll
        for (int j = 0; j < 8; j++) { s += v[j]; ss += v[j] * v[j]; }
        #pragma unroll
        for (int o = 16; o; o >>= 1) {
            s  += __shfl_xor_sync(0xFFFFFFFFu, s,  o);
            ss += __shfl_xor_sync(0xFFFFFFFFu, ss, o);
        }
        float mean = s * (1.0f / F_);
        float rstd = rsqrtf(ss * (1.0f / F_) - mean * mean + 1e-5f);

        float4 gg0 = reinterpret_cast<const float4*>(g2)[lane * 2];
        float4 gg1 = reinterpret_cast<const float4*>(g2)[lane * 2 + 1];
        float4 zb0 = reinterpret_cast<const float4*>(b2)[lane * 2];
        float4 zb1 = reinterpret_cast<const float4*>(b2)[lane * 2 + 1];
        float garr[8] = {gg0.x,gg0.y,gg0.z,gg0.w,gg1.x,gg1.y,gg1.z,gg1.w};
        float barr[8] = {zb0.x,zb0.y,zb0.z,zb0.w,zb1.x,zb1.y,zb1.z,zb1.w};

        float4* hp = reinterpret_cast<float4*>(g_h + (size_t)(m0 + row) * F_ + lane * 8);
        float4 h0 = hp[0], h1 = hp[1];
        float hv[8] = {h0.x,h0.y,h0.z,h0.w,h1.x,h1.y,h1.z,h1.w};
        #pragma unroll
        for (int j = 0; j < 8; j++) {
            float z = (v[j] - mean) * rstd * garr[j] + barr[j];
            hv[j] += gelu_f(z);
        }
        hp[0] = make_float4(hv[0], hv[1], hv[2], hv[3]);
        hp[1] = make_float4(hv[4], hv[5], hv[6], hv[7]);
    }
}

// ---------------------------------------------------------------------------
// Kernel 4a: projection h[tok]@w_proj -> g_proj[tok][29] (stride 32)
// ---------------------------------------------------------------------------
__global__ void __launch_bounds__(256)
proj_kernel(const float* __restrict__ mask, const float* __restrict__ w_proj) {
    __shared__ float s_w[PROJ_][256];
    int tid = threadIdx.x;
    for (int i = tid; i < PROJ_ * 256; i += 256) {
        int f = i / PROJ_;
        int p = i - f * PROJ_;
        s_w[p][f] = w_proj[i];
    }
    __syncthreads();

    int wrp  = tid >> 5;
    int lane = tid & 31;
    int tokbase = blockIdx.x * 64 + wrp * 8;

    float hv[8][8];
    #pragma unroll
    for (int t = 0; t < 8; t++) {
        float mm = __ldg(&mask[tokbase + t]);
        const float* hr = g_h + (size_t)(tokbase + t) * F_;
        #pragma unroll
        for (int j = 0; j < 8; j++) hv[t][j] = hr[lane + 32 * j] * mm;
    }

    #pragma unroll 1
    for (int p = 0; p < PROJ_; p++) {
        float w[8];
        #pragma unroll
        for (int j = 0; j < 8; j++) w[j] = s_w[p][lane + 32 * j];
        float part[8];
        #pragma unroll
        for (int t = 0; t < 8; t++) {
            float s = 0.f;
            #pragma unroll
            for (int j = 0; j < 8; j++) s += hv[t][j] * w[j];
            part[t] = s;
        }
        #pragma unroll
        for (int o = 16; o; o >>= 1) {
            #pragma unroll
            for (int t = 0; t < 8; t++)
                part[t] += __shfl_xor_sync(0xFFFFFFFFu, part[t], o);
        }
        if (lane < 8) {
            float v = part[0];
            #pragma unroll
            for (int t = 1; t < 8; t++) if (lane == t) v = part[t];
            g_proj[(size_t)(tokbase + lane) * 32 + p] = v;
        }
    }
}

// ---------------------------------------------------------------------------
// Kernel 4b: RQ spline, one THREAD per token
// ---------------------------------------------------------------------------
__device__ __forceinline__ float softplus_f(float v) {
    return fmaxf(v, 0.f) + log1pf(expf(-fabsf(v)));
}

__global__ void __launch_bounds__(256)
spline_kernel(const float* __restrict__ x,
              const float* __restrict__ mask,
              const float* __restrict__ b_proj,
              float* __restrict__ out) {
    int tok = blockIdx.x * 256 + threadIdx.x;
    float m = mask[tok];

    float proj[PROJ_];
    #pragma unroll
    for (int p = 0; p < PROJ_; p++)
        proj[p] = (g_proj[(size_t)tok * 32 + p] + __ldg(&b_proj[p])) * m;

    const float scale = 0.0625f;

    float cw[NB_ + 1], ww[NB_];
    {
        float mx = proj[0] * scale;
        #pragma unroll
        for (int j = 1; j < NB_; j++) mx = fmaxf(mx, proj[j] * scale);
        float e[NB_], sum = 0.f;
        #pragma unroll
        for (int j = 0; j < NB_; j++) { e[j] = expf(proj[j] * scale - mx); sum += e[j]; }
        float inv = 1.0f / sum;
        float cum = 0.f;
        cw[0] = -TBND;
        #pragma unroll
        for (int j = 0; j < NB_; j++) {
            float wj = 0.001f + (1.0f - 0.001f * NB_) * (e[j] * inv);
            cum += wj;
            cw[j + 1] = 2.0f * TBND * cum - TBND;
        }
        cw[NB_] = TBND;
        #pragma unroll
        for (int j = 0; j < NB_; j++) ww[j] = cw[j + 1] - cw[j];
    }
    float ch[NB_ + 1], hh[NB_];
    {
        float mx = proj[NB_] * scale;
        #pragma unroll
        for (int j = 1; j < NB_; j++) mx = fmaxf(mx, proj[NB_ + j] * scale);
        float e[NB_], sum = 0.f;
        #pragma unroll
        for (int j = 0; j < NB_; j++) { e[j] = expf(proj[NB_ + j] * scale - mx); sum += e[j]; }
        float inv = 1.0f / sum;
        float cum = 0.f;
        ch[0] = -TBND;
        #pragma unroll
        for (int j = 0; j < NB_; j++) {
            float hj = 0.001f + (1.0f - 0.001f * NB_) * (e[j] * inv);
            cum += hj;
            ch[j + 1] = 2.0f * TBND * cum - TBND;
        }
        ch[NB_] = TBND;
        #pragma unroll
        for (int j = 0; j < NB_; j++) hh[j] = ch[j + 1] - ch[j];
    }
    float d[NB_ + 1];
    float cst = logf(expm1f(1.0f - 0.001f));
    d[0]   = 0.001f + softplus_f(cst);
    d[NB_] = d[0];
    #pragma unroll
    for (int k = 1; k < NB_; k++) d[k] = 0.001f + softplus_f(proj[2 * NB_ + k - 1]);

    float x1 = x[(size_t)tok * 2 + 1];
    float xc = fminf(fmaxf(x1, -TBND), TBND);
    int idx = 0;
    #pragma unroll
    for (int j = 1; j <= NB_; j++) idx += (xc >= cw[j]) ? 1 : 0;
    if (idx > NB_ - 1) idx = NB_ - 1;

    float icw = cw[idx], ibw = ww[idx];
    float ich = ch[idx], ibh = hh[idx];
    float delta = ibh / ibw;
    float dk = d[idx], dk1 = d[idx + 1];
    float th   = (xc - icw) / ibw;
    float th1m = th * (1.0f - th);
    float denom = delta + (dk + dk1 - 2.0f * delta) * th1m;
    float num   = ibh * (delta * th * th + dk * th1m);
    float yv    = ich + num / denom;
    float omth  = 1.0f - th;
    float dnum  = delta * delta * (dk1 * th * th + 2.0f * delta * th1m + dk * omth * omth);
    float lad   = logf(dnum) - 2.0f * logf(denom);

    bool inside = (x1 >= -TBND) && (x1 <= TBND);
    float y1 = inside ? yv : x1;
    lad = inside ? lad : 0.0f;

    out[(size_t)tok * 2]     = x[(size_t)tok * 2] * m;
    out[(size_t)tok * 2 + 1] = y1 * m;
    g_lad[tok] = lad * m;
}

// ---------------------------------------------------------------------------
// Kernel 5: deterministic per-batch logdet reduction
// ---------------------------------------------------------------------------
__global__ void logdet_kernel(float* __restrict__ out) {
    int b = blockIdx.x, tid = threadIdx.x;
    float s = 0.f;
    for (int j = tid; j < T_; j += 256) s += g_lad[b * T_ + j];
    __shared__ float sh[256];
    sh[tid] = s;
    __syncthreads();
    #pragma unroll
    for (int o = 128; o; o >>= 1) {
        if (tid < o) sh[tid] += sh[tid + o];
        __syncthreads();
    }
    if (tid == 0) out[(size_t)BT_ * 2 + b] = sh[0];
}

// ---------------------------------------------------------------------------
extern "C" void kernel_launch(void* const* d_in, const int* in_sizes, int n_in,
                              void* d_out, int out_size) {
    const float* x      = (const float*)d_in[0];
    const float* mask   = (const float*)d_in[1];
    const float* w_pre  = (const float*)d_in[2];
    const float* b_pre  = (const float*)d_in[3];
    const float* dw_k   = (const float*)d_in[4];
    const float* dw_b   = (const float*)d_in[5];
    const float* w11    = (const float*)d_in[6];
    const float* b11    = (const float*)d_in[7];
    const float* ln1g   = (const float*)d_in[8];
    const float* ln1b   = (const float*)d_in[9];
    const float* ln2g   = (const float*)d_in[10];
    const float* ln2b   = (const float*)d_in[11];
    const float* w_proj = (const float*)d_in[12];
    const float* b_proj = (const float*)d_in[13];
    float* out = (float*)d_out;

    cudaFuncSetAttribute(gemm_mma_kernel,
                         cudaFuncAttributeMaxDynamicSharedMemorySize, GSMEM);

    prep_bfrag_kernel<<<NL_ * 32 * 16, 32>>>(w11);

    // layer 0: fused pre + conv
    conv0_fused_kernel<<<BT_ / 8, 256>>>(x, mask, w_pre, b_pre,
                                         dw_k, dw_b, ln1g, ln1b);
    gemm_mma_kernel<<<BT_ / 32, 256, GSMEM>>>(0, b11, ln2g, ln2b);

    int dil = KS_;
    for (int i = 1; i < NL_; i++) {
        conv_ln_gelu_kernel<<<BT_ / 8, 256>>>(mask,
                                              dw_k + (size_t)i * KS_ * F_,
                                              dw_b + (size_t)i * F_,
                                              ln1g + (size_t)i * F_,
                                              ln1b + (size_t)i * F_,
                                              dil);
        gemm_mma_kernel<<<BT_ / 32, 256, GSMEM>>>(i,
                                                  b11 + (size_t)i * F_,
                                                  ln2g + (size_t)i * F_,
                                                  ln2b + (size_t)i * F_);
        dil *= KS_;
    }

    proj_kernel<<<BT_ / 64, 256>>>(mask, w_proj);
    spline_kernel<<<BT_ / 256, 256>>>(x, mask, b_proj, out);
    logdet_kernel<<<B_, 256>>>(out);
}

// round 9
// speedup vs baseline: 3.2205x; 1.0474x over previous
#include <cuda_runtime.h>
#include <cuda_bf16.h>
#include <math.h>
#include <stdint.h>
#include <cstdint>

#define B_    16
#define T_    8192
#define F_    256
#define NL_   3
#define KS_   3
#define NB_   10
#define PROJ_ 29
#define BT_   (B_*T_)
#define TBND  5.0f

__device__ float g_h[(size_t)BT_ * F_];
__device__ float g_y[(size_t)BT_ * F_];
__device__ float g_lad[BT_];
__device__ float g_proj[(size_t)BT_ * 32];
__device__ uint4 g_Bfrag[NL_ * 32 * 16 * 32];
__device__ uint4 g_Pfrag[4 * 16 * 32];          // w_proj fragments (N padded to 32)

__device__ __forceinline__ float gelu_f(float v) {
    return 0.5f * v * (1.0f + erff(v * 0.7071067811865476f));
}

__device__ __forceinline__ void mma16816(float* d, const uint32_t* a,
                                         uint32_t b0, uint32_t b1) {
    asm volatile(
        "mma.sync.aligned.m16n8k16.row.col.f32.bf16.bf16.f32 "
        "{%0,%1,%2,%3}, {%4,%5,%6,%7}, {%8,%9}, {%0,%1,%2,%3};"
        : "+f"(d[0]), "+f"(d[1]), "+f"(d[2]), "+f"(d[3])
        : "r"(a[0]), "r"(a[1]), "r"(a[2]), "r"(a[3]), "r"(b0), "r"(b1));
}

__device__ __forceinline__ void ldmx4(uint32_t* r, uint32_t addr) {
    asm volatile("ldmatrix.sync.aligned.m8n8.x4.shared.b16 {%0,%1,%2,%3}, [%4];"
        : "=r"(r[0]), "=r"(r[1]), "=r"(r[2]), "=r"(r[3]) : "r"(addr));
}

__device__ __forceinline__ uint32_t pack_bf16x2(float x, float y) {
    __nv_bfloat162 p = __halves2bfloat162(__float2bfloat16(x), __float2bfloat16(y));
    return *reinterpret_cast<uint32_t*>(&p);
}

// ---------------------------------------------------------------------------
// Kernel 0a: pack w11 into mma B fragments (hi/lo split)
// ---------------------------------------------------------------------------
__global__ void prep_bfrag_kernel(const float* __restrict__ w11) {
    int blk  = blockIdx.x;
    int lane = threadIdx.x;
    int ks   = blk & 15;
    int nt   = (blk >> 4) & 31;
    int l    = blk >> 9;
    int tg   = lane >> 2, tid = lane & 3;
    int n    = nt * 8 + tg;
    int k0   = ks * 16 + tid * 2;

    const float* w = w11 + (size_t)l * F_ * F_;
    float v00 = w[(size_t)(k0    ) * F_ + n];
    float v01 = w[(size_t)(k0 + 1) * F_ + n];
    float v10 = w[(size_t)(k0 + 8) * F_ + n];
    float v11 = w[(size_t)(k0 + 9) * F_ + n];

    float h00 = __bfloat162float(__float2bfloat16(v00));
    float h01 = __bfloat162float(__float2bfloat16(v01));
    float h10 = __bfloat162float(__float2bfloat16(v10));
    float h11 = __bfloat162float(__float2bfloat16(v11));

    uint4 o;
    o.x = pack_bf16x2(v00, v01);
    o.y = pack_bf16x2(v10, v11);
    o.z = pack_bf16x2(v00 - h00, v01 - h01);
    o.w = pack_bf16x2(v10 - h10, v11 - h11);
    g_Bfrag[(size_t)blk * 32 + lane] = o;
}

// ---------------------------------------------------------------------------
// Kernel 0b: pack w_proj [256,29] into fragments, N padded to 32 with zeros
// grid = 4*16 blocks of 32 threads
// ---------------------------------------------------------------------------
__global__ void prep_pfrag_kernel(const float* __restrict__ w_proj) {
    int blk  = blockIdx.x;              // nt*16 + ks
    int lane = threadIdx.x;
    int ks   = blk & 15;
    int nt   = blk >> 4;
    int tg   = lane >> 2, tid = lane & 3;
    int n    = nt * 8 + tg;
    int k0   = ks * 16 + tid * 2;

    float v00 = (n < PROJ_) ? w_proj[(size_t)(k0    ) * PROJ_ + n] : 0.f;
    float v01 = (n < PROJ_) ? w_proj[(size_t)(k0 + 1) * PROJ_ + n] : 0.f;
    float v10 = (n < PROJ_) ? w_proj[(size_t)(k0 + 8) * PROJ_ + n] : 0.f;
    float v11 = (n < PROJ_) ? w_proj[(size_t)(k0 + 9) * PROJ_ + n] : 0.f;

    float h00 = __bfloat162float(__float2bfloat16(v00));
    float h01 = __bfloat162float(__float2bfloat16(v01));
    float h10 = __bfloat162float(__float2bfloat16(v10));
    float h11 = __bfloat162float(__float2bfloat16(v11));

    uint4 o;
    o.x = pack_bf16x2(v00, v01);
    o.y = pack_bf16x2(v10, v11);
    o.z = pack_bf16x2(v00 - h00, v01 - h01);
    o.w = pack_bf16x2(v10 - h10, v11 - h11);
    g_Pfrag[(size_t)blk * 32 + lane] = o;
}

// ---------------------------------------------------------------------------
// Kernel 2a: FUSED layer-0 conv (computes pre inline, writes g_h and g_y)
// ---------------------------------------------------------------------------
__global__ void conv0_fused_kernel(const float* __restrict__ x,
                                   const float* __restrict__ mask,
                                   const float* __restrict__ w_pre,
                                   const float* __restrict__ b_pre,
                                   const float* __restrict__ dwk,
                                   const float* __restrict__ dwb,
                                   const float* __restrict__ g1,
                                   const float* __restrict__ b1) {
    __shared__ float4 s_k[3][64], s_b[64], s_g[64], s_bb[64], s_wp[64], s_bp[64];
    int tidx = threadIdx.x;
    if (tidx < 64) {
        s_k[0][tidx] = reinterpret_cast<const float4*>(dwk)[tidx];
        s_k[1][tidx] = reinterpret_cast<const float4*>(dwk)[64 + tidx];
        s_k[2][tidx] = reinterpret_cast<const float4*>(dwk)[128 + tidx];
        s_wp[tidx]   = reinterpret_cast<const float4*>(w_pre)[tidx];
    } else if (tidx < 128) {
        s_b[tidx - 64]  = reinterpret_cast<const float4*>(dwb)[tidx - 64];
        s_bp[tidx - 64] = reinterpret_cast<const float4*>(b_pre)[tidx - 64];
    } else if (tidx < 192) {
        s_g[tidx - 128] = reinterpret_cast<const float4*>(g1)[tidx - 128];
    } else {
        s_bb[tidx - 192] = reinterpret_cast<const float4*>(b1)[tidx - 192];
    }
    __syncthreads();

    int wid  = tidx >> 5;
    int lane = tidx & 31;
    int tok  = blockIdx.x * 8 + wid;
    int t    = tok & (T_ - 1);

    float x0m1 = (t - 1 >= 0) ? __ldg(&x[(size_t)(tok - 1) * 2]) : 0.f;
    float x00  = __ldg(&x[(size_t)tok * 2]);
    float x0p1 = (t + 1 < T_) ? __ldg(&x[(size_t)(tok + 1) * 2]) : 0.f;
    float mm1  = (t - 1 >= 0) ? __ldg(&mask[tok - 1]) : 0.f;
    float m0   = __ldg(&mask[tok]);
    float mp1  = (t + 1 < T_) ? __ldg(&mask[tok + 1]) : 0.f;

    float wp[8], bp[8];
    {
        float4 a0 = s_wp[lane], a1 = s_wp[lane + 32];
        float4 c0 = s_bp[lane], c1 = s_bp[lane + 32];
        wp[0]=a0.x; wp[1]=a0.y; wp[2]=a0.z; wp[3]=a0.w;
        wp[4]=a1.x; wp[5]=a1.y; wp[6]=a1.z; wp[7]=a1.w;
        bp[0]=c0.x; bp[1]=c0.y; bp[2]=c0.z; bp[3]=c0.w;
        bp[4]=c1.x; bp[5]=c1.y; bp[6]=c1.z; bp[7]=c1.w;
    }

    float a[8];
    {
        float4 b0 = s_b[lane], b1v = s_b[lane + 32];
        a[0]=b0.x; a[1]=b0.y; a[2]=b0.z; a[3]=b0.w;
        a[4]=b1v.x; a[5]=b1v.y; a[6]=b1v.z; a[7]=b1v.w;
    }
    float hown[8];

    float xs[3] = {x0m1, x00, x0p1};
    float ms[3] = {mm1, m0, mp1};
    bool  ok[3] = {t - 1 >= 0, true, t + 1 < T_};
    #pragma unroll
    for (int tap = 0; tap < 3; tap++) {
        float4 k0 = s_k[tap][lane], k1 = s_k[tap][lane + 32];
        float karr[8] = {k0.x,k0.y,k0.z,k0.w,k1.x,k1.y,k1.z,k1.w};
        float xm = xs[tap] * ms[tap];
        float mmk = ms[tap];
        #pragma unroll
        for (int j = 0; j < 8; j++) {
            float hval = xs[tap] * wp[j] + bp[j];
            if (tap == 1) hown[j] = hval;
            if (ok[tap]) a[j] += (xm * wp[j] + mmk * bp[j]) * karr[j];
        }
    }

    {
        float4* hw = reinterpret_cast<float4*>(g_h + (size_t)tok * F_);
        hw[lane]      = make_float4(hown[0],hown[1],hown[2],hown[3]);
        hw[lane + 32] = make_float4(hown[4],hown[5],hown[6],hown[7]);
    }

    float s = 0.f, ss = 0.f;
    #pragma unroll
    for (int j = 0; j < 8; j++) { s += a[j]; ss += a[j] * a[j]; }
    #pragma unroll
    for (int o = 16; o; o >>= 1) {
        s  += __shfl_xor_sync(0xFFFFFFFFu, s,  o);
        ss += __shfl_xor_sync(0xFFFFFFFFu, ss, o);
    }
    float mean = s * (1.0f / F_);
    float rstd = rsqrtf(ss * (1.0f / F_) - mean * mean + 1e-5f);

    float4 gg0 = s_g[lane], gg1 = s_g[lane + 32];
    float4 bb0 = s_bb[lane], bb1 = s_bb[lane + 32];
    float garr[8] = {gg0.x,gg0.y,gg0.z,gg0.w,gg1.x,gg1.y,gg1.z,gg1.w};
    float barr[8] = {bb0.x,bb0.y,bb0.z,bb0.w,bb1.x,bb1.y,bb1.z,bb1.w};

    float r[8];
    #pragma unroll
    for (int j = 0; j < 8; j++) {
        float v = (a[j] - mean) * rstd * garr[j] + barr[j];
        r[j] = gelu_f(v);
    }
    float4* yr = reinterpret_cast<float4*>(g_y + (size_t)tok * F_);
    yr[lane]      = make_float4(r[0], r[1], r[2], r[3]);
    yr[lane + 32] = make_float4(r[4], r[5], r[6], r[7]);
}

// ---------------------------------------------------------------------------
// Kernel 2b: layers 1-2 conv (reads g_h); warp per token
// ---------------------------------------------------------------------------
__global__ void conv_ln_gelu_kernel(const float* __restrict__ mask,
                                    const float* __restrict__ dwk,
                                    const float* __restrict__ dwb,
                                    const float* __restrict__ g1,
                                    const float* __restrict__ b1,
                                    int dil) {
    __shared__ float4 s_k[3][64], s_b[64], s_g[64], s_bb[64];
    int tidx = threadIdx.x;
    if (tidx < 64) {
        s_k[0][tidx] = reinterpret_cast<const float4*>(dwk)[tidx];
        s_k[1][tidx] = reinterpret_cast<const float4*>(dwk)[64 + tidx];
        s_k[2][tidx] = reinterpret_cast<const float4*>(dwk)[128 + tidx];
    } else if (tidx < 128) {
        s_b[tidx - 64] = reinterpret_cast<const float4*>(dwb)[tidx - 64];
    } else if (tidx < 192) {
        s_g[tidx - 128] = reinterpret_cast<const float4*>(g1)[tidx - 128];
    } else {
        s_bb[tidx - 192] = reinterpret_cast<const float4*>(b1)[tidx - 192];
    }
    __syncthreads();

    int wid  = tidx >> 5;
    int lane = tidx & 31;
    int tok  = blockIdx.x * 8 + wid;
    int t    = tok & (T_ - 1);

    float a[8];
    {
        float4 b0 = s_b[lane], b1v = s_b[lane + 32];
        a[0]=b0.x; a[1]=b0.y; a[2]=b0.z; a[3]=b0.w;
        a[4]=b1v.x; a[5]=b1v.y; a[6]=b1v.z; a[7]=b1v.w;
    }

    #pragma unroll
    for (int tap = 0; tap < 3; tap++) {
        int off = (tap - 1) * dil;
        int tt = t + off;
        if (tt >= 0 && tt < T_) {
            float mm = __ldg(&mask[tok + off]);
            const float4* hr = reinterpret_cast<const float4*>(g_h + (size_t)(tok + off) * F_);
            float4 h0 = hr[lane], h1 = hr[lane + 32];
            float4 k0 = s_k[tap][lane], k1 = s_k[tap][lane + 32];
            a[0] += h0.x * mm * k0.x; a[1] += h0.y * mm * k0.y;
            a[2] += h0.z * mm * k0.z; a[3] += h0.w * mm * k0.w;
            a[4] += h1.x * mm * k1.x; a[5] += h1.y * mm * k1.y;
            a[6] += h1.z * mm * k1.z; a[7] += h1.w * mm * k1.w;
        }
    }

    float s = 0.f, ss = 0.f;
    #pragma unroll
    for (int j = 0; j < 8; j++) { s += a[j]; ss += a[j] * a[j]; }
    #pragma unroll
    for (int o = 16; o; o >>= 1) {
        s  += __shfl_xor_sync(0xFFFFFFFFu, s,  o);
        ss += __shfl_xor_sync(0xFFFFFFFFu, ss, o);
    }
    float mean = s * (1.0f / F_);
    float rstd = rsqrtf(ss * (1.0f / F_) - mean * mean + 1e-5f);

    float4 gg0 = s_g[lane], gg1 = s_g[lane + 32];
    float4 bb0 = s_bb[lane], bb1 = s_bb[lane + 32];
    float garr[8] = {gg0.x,gg0.y,gg0.z,gg0.w,gg1.x,gg1.y,gg1.z,gg1.w};
    float barr[8] = {bb0.x,bb0.y,bb0.z,bb0.w,bb1.x,bb1.y,bb1.z,bb1.w};

    float r[8];
    #pragma unroll
    for (int j = 0; j < 8; j++) {
        float v = (a[j] - mean) * rstd * garr[j] + barr[j];
        r[j] = gelu_f(v);
    }
    float4* yr = reinterpret_cast<float4*>(g_y + (size_t)tok * F_);
    yr[lane]      = make_float4(r[0], r[1], r[2], r[3]);
    yr[lane + 32] = make_float4(r[4], r[5], r[6], r[7]);
}

// ---------------------------------------------------------------------------
// Kernel 3: mma.sync GEMM  h += gelu(LN2(y @ w11 + b11))
// CTA: 64 tokens x 256 cols (R7 config, 2 CTAs/SM)
// ---------------------------------------------------------------------------
#define AROW   264
#define GSMEM  (2 * 64 * AROW * 2 + 256)

__global__ void __launch_bounds__(256, 2)
gemm_mma_kernel(int layer,
                const float* __restrict__ b11,
                const float* __restrict__ g2,
                const float* __restrict__ b2) {
    extern __shared__ char dyn[];
    char* basep = (char*)(((uintptr_t)dyn + 15) & ~(uintptr_t)15);
    __nv_bfloat16* Ahi = reinterpret_cast<__nv_bfloat16*>(basep);
    __nv_bfloat16* Alo = Ahi + 64 * AROW;
    float* stag = reinterpret_cast<float*>(basep);
    const int SROW = 260;

    const int tid  = threadIdx.x;
    const int wid  = tid >> 5;
    const int lane = tid & 31;
    const int tg   = lane >> 2, tq = lane & 3;
    const int wn   = wid;
    const int m0   = blockIdx.x * 64;

    {
        int row = tid >> 2;
        int kq  = (tid & 3) * 64;
        const float4* src = reinterpret_cast<const float4*>(
            g_y + (size_t)(m0 + row) * F_ + kq);
        #pragma unroll
        for (int j = 0; j < 16; j++) {
            float4 v = src[j];
            float hx = __bfloat162float(__float2bfloat16(v.x));
            float hy = __bfloat162float(__float2bfloat16(v.y));
            float hz = __bfloat162float(__float2bfloat16(v.z));
            float hw = __bfloat162float(__float2bfloat16(v.w));
            uint2 hp, lp;
            hp.x = pack_bf16x2(v.x, v.y);
            hp.y = pack_bf16x2(v.z, v.w);
            lp.x = pack_bf16x2(v.x - hx, v.y - hy);
            lp.y = pack_bf16x2(v.z - hz, v.w - hw);
            int c = kq + j * 4;
            *reinterpret_cast<uint2*>(Ahi + row * AROW + c) = hp;
            *reinterpret_cast<uint2*>(Alo + row * AROW + c) = lp;
        }
    }
    __syncthreads();

    float d[4][4][4];
    #pragma unroll
    for (int mt = 0; mt < 4; mt++)
        #pragma unroll
        for (int nt = 0; nt < 4; nt++)
            #pragma unroll
            for (int q = 0; q < 4; q++) d[mt][nt][q] = 0.f;

    const uint4* Bbase = g_Bfrag + ((size_t)(layer * 32 + wn * 4) * 16) * 32 + lane;
    uint4 bcur[4], bnxt[4];
    #pragma unroll
    for (int nt = 0; nt < 4; nt++) bcur[nt] = __ldg(&Bbase[(nt * 16 + 0) * 32]);

    uint32_t a_hi_addr[4], a_lo_addr[4];
    {
        int r = lane & 15;
        int cb = (lane >> 4) * 16;
        #pragma unroll
        for (int mt = 0; mt < 4; mt++) {
            int row = mt * 16 + r;
            a_hi_addr[mt] = (uint32_t)__cvta_generic_to_shared(Ahi + row * AROW) + cb;
            a_lo_addr[mt] = (uint32_t)__cvta_generic_to_shared(Alo + row * AROW) + cb;
        }
    }

    #pragma unroll 1
    for (int ks = 0; ks < 16; ks++) {
        if (ks < 15) {
            #pragma unroll
            for (int nt = 0; nt < 4; nt++)
                bnxt[nt] = __ldg(&Bbase[(nt * 16 + ks + 1) * 32]);
        }
        const uint32_t koff = ks * 32;
        #pragma unroll
        for (int mt = 0; mt < 4; mt++) {
            uint32_t ah[4], al[4];
            ldmx4(ah, a_hi_addr[mt] + koff);
            ldmx4(al, a_lo_addr[mt] + koff);
            #pragma unroll
            for (int nt = 0; nt < 4; nt++) {
                mma16816(d[mt][nt], ah, bcur[nt].x, bcur[nt].y);
                mma16816(d[mt][nt], ah, bcur[nt].z, bcur[nt].w);
                mma16816(d[mt][nt], al, bcur[nt].x, bcur[nt].y);
            }
        }
        #pragma unroll
        for (int nt = 0; nt < 4; nt++) bcur[nt] = bnxt[nt];
    }

    __syncthreads();
    #pragma unroll
    for (int mt = 0; mt < 4; mt++) {
        int r0 = mt * 16 + tg;
        #pragma unroll
        for (int nt = 0; nt < 4; nt++) {
            int col = wn * 32 + nt * 8 + tq * 2;
            *reinterpret_cast<float2*>(&stag[r0 * SROW + col]) =
                make_float2(d[mt][nt][0], d[mt][nt][1]);
            *reinterpret_cast<float2*>(&stag[(r0 + 8) * SROW + col]) =
                make_float2(d[mt][nt][2], d[mt][nt][3]);
        }
    }
    __syncthreads();

    #pragma unroll 1
    for (int i = 0; i < 8; i++) {
        int row = wid * 8 + i;
        float4 f0 = *reinterpret_cast<const float4*>(&stag[row * SROW + lane * 8]);
        float4 f1 = *reinterpret_cast<const float4*>(&stag[row * SROW + lane * 8 + 4]);
        float4 bb0 = reinterpret_cast<const float4*>(b11)[lane * 2];
        float4 bb1 = reinterpret_cast<const float4*>(b11)[lane * 2 + 1];
        float v[8] = {f0.x + bb0.x, f0.y + bb0.y, f0.z + bb0.z, f0.w + bb0.w,
                      f1.x + bb1.x, f1.y + bb1.y, f1.z + bb1.z, f1.w + bb1.w};
        float s = 0.f, ss = 0.f;
        #pragma unroll
        for (int j = 0; j < 8; j++) { s += v[j]; ss += v[j] * v[j]; }
        #pragma unroll
        for (int o = 16; o; o >>= 1) {
            s  += __shfl_xor_sync(0xFFFFFFFFu, s,  o);
            ss += __shfl_xor_sync(0xFFFFFFFFu, ss, o);
        }
        float mean = s * (1.0f / F_);
        float rstd = rsqrtf(ss * (1.0f / F_) - mean * mean + 1e-5f);

        float4 gg0 = reinterpret_cast<const float4*>(g2)[lane * 2];
        float4 gg1 = reinterpret_cast<const float4*>(g2)[lane * 2 + 1];
        float4 zb0 = reinterpret_cast<const float4*>(b2)[lane * 2];
        float4 zb1 = reinterpret_cast<const float4*>(b2)[lane * 2 + 1];
        float garr[8] = {gg0.x,gg0.y,gg0.z,gg0.w,gg1.x,gg1.y,gg1.z,gg1.w};
        float barr[8] = {zb0.x,zb0.y,zb0.z,zb0.w,zb1.x,zb1.y,zb1.z,zb1.w};

        float4* hp = reinterpret_cast<float4*>(g_h + (size_t)(m0 + row) * F_ + lane * 8);
        float4 h0 = hp[0], h1 = hp[1];
        float hv[8] = {h0.x,h0.y,h0.z,h0.w,h1.x,h1.y,h1.z,h1.w};
        #pragma unroll
        for (int j = 0; j < 8; j++) {
            float z = (v[j] - mean) * rstd * garr[j] + barr[j];
            hv[j] += gelu_f(z);
        }
        hp[0] = make_float4(hv[0], hv[1], hv[2], hv[3]);
        hp[1] = make_float4(hv[4], hv[5], hv[6], hv[7]);
    }
}

// ---------------------------------------------------------------------------
// Kernel 4a: proj GEMM via mma: g_proj = (h*mask) @ w_proj  (N padded to 32)
// CTA: 64 tokens, 128 threads = 4 warps, warp tile 16x32
// ---------------------------------------------------------------------------
__global__ void __launch_bounds__(128, 2)
proj_gemm_kernel(const float* __restrict__ mask) {
    extern __shared__ char dyn[];
    char* basep = (char*)(((uintptr_t)dyn + 15) & ~(uintptr_t)15);
    __nv_bfloat16* Ahi = reinterpret_cast<__nv_bfloat16*>(basep);
    __nv_bfloat16* Alo = Ahi + 64 * AROW;

    const int tid  = threadIdx.x;
    const int wid  = tid >> 5;          // 0..3 -> m subtile
    const int lane = tid & 31;
    const int tg   = lane >> 2, tq = lane & 3;
    const int m0   = blockIdx.x * 64;

    // ---- load A (64 x 256 fp32 h*mask) -> bf16 hi/lo SMEM ----
    {
        int row  = tid >> 1;            // 0..63
        int half = tid & 1;
        float mm = __ldg(&mask[m0 + row]);
        const float4* src = reinterpret_cast<const float4*>(
            g_h + (size_t)(m0 + row) * F_) + half * 32;
        #pragma unroll
        for (int j = 0; j < 32; j++) {
            float4 v = src[j];
            v.x *= mm; v.y *= mm; v.z *= mm; v.w *= mm;
            float hx = __bfloat162float(__float2bfloat16(v.x));
            float hy = __bfloat162float(__float2bfloat16(v.y));
            float hz = __bfloat162float(__float2bfloat16(v.z));
            float hw = __bfloat162float(__float2bfloat16(v.w));
            uint2 hp, lp;
            hp.x = pack_bf16x2(v.x, v.y);
            hp.y = pack_bf16x2(v.z, v.w);
            lp.x = pack_bf16x2(v.x - hx, v.y - hy);
            lp.y = pack_bf16x2(v.z - hz, v.w - hw);
            int c = (half * 32 + j) * 4;
            *reinterpret_cast<uint2*>(Ahi + row * AROW + c) = hp;
            *reinterpret_cast<uint2*>(Alo + row * AROW + c) = lp;
        }
    }
    __syncthreads();

    float d[4][4];
    #pragma unroll
    for (int nt = 0; nt < 4; nt++)
        #pragma unroll
        for (int q = 0; q < 4; q++) d[nt][q] = 0.f;

    const uint4* Bbase = g_Pfrag + lane;
    uint4 bcur[4], bnxt[4];
    #pragma unroll
    for (int nt = 0; nt < 4; nt++) bcur[nt] = __ldg(&Bbase[(nt * 16 + 0) * 32]);

    uint32_t a_hi_addr, a_lo_addr;
    {
        int r = lane & 15;
        int cb = (lane >> 4) * 16;
        int row = wid * 16 + r;
        a_hi_addr = (uint32_t)__cvta_generic_to_shared(Ahi + row * AROW) + cb;
        a_lo_addr = (uint32_t)__cvta_generic_to_shared(Alo + row * AROW) + cb;
    }

    #pragma unroll 1
    for (int ks = 0; ks < 16; ks++) {
        if (ks < 15) {
            #pragma unroll
            for (int nt = 0; nt < 4; nt++)
                bnxt[nt] = __ldg(&Bbase[(nt * 16 + ks + 1) * 32]);
        }
        const uint32_t koff = ks * 32;
        uint32_t ah[4], al[4];
        ldmx4(ah, a_hi_addr + koff);
        ldmx4(al, a_lo_addr + koff);
        #pragma unroll
        for (int nt = 0; nt < 4; nt++) {
            mma16816(d[nt], ah, bcur[nt].x, bcur[nt].y);
            mma16816(d[nt], ah, bcur[nt].z, bcur[nt].w);
            mma16816(d[nt], al, bcur[nt].x, bcur[nt].y);
        }
        #pragma unroll
        for (int nt = 0; nt < 4; nt++) bcur[nt] = bnxt[nt];
    }

    // direct register -> g_proj epilogue
    #pragma unroll
    for (int nt = 0; nt < 4; nt++) {
        int col  = nt * 8 + tq * 2;
        int row0 = m0 + wid * 16 + tg;
        *reinterpret_cast<float2*>(&g_proj[(size_t)row0 * 32 + col]) =
            make_float2(d[nt][0], d[nt][1]);
        *reinterpret_cast<float2*>(&g_proj[(size_t)(row0 + 8) * 32 + col]) =
            make_float2(d[nt][2], d[nt][3]);
    }
}

// ---------------------------------------------------------------------------
// Kernel 4b: RQ spline, one THREAD per token
// ---------------------------------------------------------------------------
__device__ __forceinline__ float softplus_f(float v) {
    return fmaxf(v, 0.f) + log1pf(expf(-fabsf(v)));
}

__global__ void __launch_bounds__(256)
spline_kernel(const float* __restrict__ x,
              const float* __restrict__ mask,
              const float* __restrict__ b_proj,
              float* __restrict__ out) {
    int tok = blockIdx.x * 256 + threadIdx.x;
    float m = mask[tok];

    float proj[PROJ_];
    #pragma unroll
    for (int p = 0; p < PROJ_; p++)
        proj[p] = (g_proj[(size_t)tok * 32 + p] + __ldg(&b_proj[p])) * m;

    const float scale = 0.0625f;

    float cw[NB_ + 1], ww[NB_];
    {
        float mx = proj[0] * scale;
        #pragma unroll
        for (int j = 1; j < NB_; j++) mx = fmaxf(mx, proj[j] * scale);
        float e[NB_], sum = 0.f;
        #pragma unroll
        for (int j = 0; j < NB_; j++) { e[j] = expf(proj[j] * scale - mx); sum += e[j]; }
        float inv = 1.0f / sum;
        float cum = 0.f;
        cw[0] = -TBND;
        #pragma unroll
        for (int j = 0; j < NB_; j++) {
            float wj = 0.001f + (1.0f - 0.001f * NB_) * (e[j] * inv);
            cum += wj;
            cw[j + 1] = 2.0f * TBND * cum - TBND;
        }
        cw[NB_] = TBND;
        #pragma unroll
        for (int j = 0; j < NB_; j++) ww[j] = cw[j + 1] - cw[j];
    }
    float ch[NB_ + 1], hh[NB_];
    {
        float mx = proj[NB_] * scale;
        #pragma unroll
        for (int j = 1; j < NB_; j++) mx = fmaxf(mx, proj[NB_ + j] * scale);
        float e[NB_], sum = 0.f;
        #pragma unroll
        for (int j = 0; j < NB_; j++) { e[j] = expf(proj[NB_ + j] * scale - mx); sum += e[j]; }
        float inv = 1.0f / sum;
        float cum = 0.f;
        ch[0] = -TBND;
        #pragma unroll
        for (int j = 0; j < NB_; j++) {
            float hj = 0.001f + (1.0f - 0.001f * NB_) * (e[j] * inv);
            cum += hj;
            ch[j + 1] = 2.0f * TBND * cum - TBND;
        }
        ch[NB_] = TBND;
        #pragma unroll
        for (int j = 0; j < NB_; j++) hh[j] = ch[j + 1] - ch[j];
    }
    float d[NB_ + 1];
    float cst = logf(expm1f(1.0f - 0.001f));
    d[0]   = 0.001f + softplus_f(cst);
    d[NB_] = d[0];
    #pragma unroll
    for (int k = 1; k < NB_; k++) d[k] = 0.001f + softplus_f(proj[2 * NB_ + k - 1]);

    float x1 = x[(size_t)tok * 2 + 1];
    float xc = fminf(fmaxf(x1, -TBND), TBND);
    int idx = 0;
    #pragma unroll
    for (int j = 1; j <= NB_; j++) idx += (xc >= cw[j]) ? 1 : 0;
    if (idx > NB_ - 1) idx = NB_ - 1;

    float icw = cw[idx], ibw = ww[idx];
    float ich = ch[idx], ibh = hh[idx];
    float delta = ibh / ibw;
    float dk = d[idx], dk1 = d[idx + 1];
    float th   = (xc - icw) / ibw;
    float th1m = th * (1.0f - th);
    float denom = delta + (dk + dk1 - 2.0f * delta) * th1m;
    float num   = ibh * (delta * th * th + dk * th1m);
    float yv    = ich + num / denom;
    float omth  = 1.0f - th;
    float dnum  = delta * delta * (dk1 * th * th + 2.0f * delta * th1m + dk * omth * omth);
    float lad   = logf(dnum) - 2.0f * logf(denom);

    bool inside = (x1 >= -TBND) && (x1 <= TBND);
    float y1 = inside ? yv : x1;
    lad = inside ? lad : 0.0f;

    out[(size_t)tok * 2]     = x[(size_t)tok * 2] * m;
    out[(size_t)tok * 2 + 1] = y1 * m;
    g_lad[tok] = lad * m;
}

// ---------------------------------------------------------------------------
// Kernel 5: deterministic per-batch logdet reduction
// ---------------------------------------------------------------------------
__global__ void logdet_kernel(float* __restrict__ out) {
    int b = blockIdx.x, tid = threadIdx.x;
    float s = 0.f;
    for (int j = tid; j < T_; j += 256) s += g_lad[b * T_ + j];
    __shared__ float sh[256];
    sh[tid] = s;
    __syncthreads();
    #pragma unroll
    for (int o = 128; o; o >>= 1) {
        if (tid < o) sh[tid] += sh[tid + o];
        __syncthreads();
    }
    if (tid == 0) out[(size_t)BT_ * 2 + b] = sh[0];
}

// ---------------------------------------------------------------------------
extern "C" void kernel_launch(void* const* d_in, const int* in_sizes, int n_in,
                              void* d_out, int out_size) {
    const float* x      = (const float*)d_in[0];
    const float* mask   = (const float*)d_in[1];
    const float* w_pre  = (const float*)d_in[2];
    const float* b_pre  = (const float*)d_in[3];
    const float* dw_k   = (const float*)d_in[4];
    const float* dw_b   = (const float*)d_in[5];
    const float* w11    = (const float*)d_in[6];
    const float* b11    = (const float*)d_in[7];
    const float* ln1g   = (const float*)d_in[8];
    const float* ln1b   = (const float*)d_in[9];
    const float* ln2g   = (const float*)d_in[10];
    const float* ln2b   = (const float*)d_in[11];
    const float* w_proj = (const float*)d_in[12];
    const float* b_proj = (const float*)d_in[13];
    float* out = (float*)d_out;

    cudaFuncSetAttribute(gemm_mma_kernel,
                         cudaFuncAttributeMaxDynamicSharedMemorySize, GSMEM);
    cudaFuncSetAttribute(proj_gemm_kernel,
                         cudaFuncAttributeMaxDynamicSharedMemorySize, GSMEM);

    prep_bfrag_kernel<<<NL_ * 32 * 16, 32>>>(w11);
    prep_pfrag_kernel<<<4 * 16, 32>>>(w_proj);

    // layer 0: fused pre + conv
    conv0_fused_kernel<<<BT_ / 8, 256>>>(x, mask, w_pre, b_pre,
                                         dw_k, dw_b, ln1g, ln1b);
    gemm_mma_kernel<<<BT_ / 64, 256, GSMEM>>>(0, b11, ln2g, ln2b);

    int dil = KS_;
    for (int i = 1; i < NL_; i++) {
        conv_ln_gelu_kernel<<<BT_ / 8, 256>>>(mask,
                                              dw_k + (size_t)i * KS_ * F_,
                                              dw_b + (size_t)i * F_,
                                              ln1g + (size_t)i * F_,
                                              ln1b + (size_t)i * F_,
                                              dil);
        gemm_mma_kernel<<<BT_ / 64, 256, GSMEM>>>(i,
                                                  b11 + (size_t)i * F_,
                                                  ln2g + (size_t)i * F_,
                                                  ln2b + (size_t)i * F_);
        dil *= KS_;
    }

    proj_gemm_kernel<<<BT_ / 64, 128, GSMEM>>>(mask);
    spline_kernel<<<BT_ / 256, 256>>>(x, mask, b_proj, out);
    logdet_kernel<<<B_, 256>>>(out);
}

// round 10
// speedup vs baseline: 3.6024x; 1.1186x over previous
#include <cuda_runtime.h>
#include <cuda_bf16.h>
#include <math.h>
#include <stdint.h>
#include <cstdint>

#define B_    16
#define T_    8192
#define F_    256
#define NL_   3
#define KS_   3
#define NB_   10
#define PROJ_ 29
#define BT_   (B_*T_)
#define TBND  5.0f

__device__ float g_h[(size_t)BT_ * F_];     // residual ping
__device__ float g_h2[(size_t)BT_ * F_];    // residual pong
__device__ float g_lad[BT_];
__device__ float g_proj[(size_t)BT_ * 32];
__device__ uint4 g_Bfrag[NL_ * 32 * 16 * 32];
__device__ uint4 g_Pfrag[4 * 16 * 32];

__device__ __forceinline__ float gelu_f(float v) {
    return 0.5f * v * (1.0f + erff(v * 0.7071067811865476f));
}

__device__ __forceinline__ void mma16816(float* d, const uint32_t* a,
                                         uint32_t b0, uint32_t b1) {
    asm volatile(
        "mma.sync.aligned.m16n8k16.row.col.f32.bf16.bf16.f32 "
        "{%0,%1,%2,%3}, {%4,%5,%6,%7}, {%8,%9}, {%0,%1,%2,%3};"
        : "+f"(d[0]), "+f"(d[1]), "+f"(d[2]), "+f"(d[3])
        : "r"(a[0]), "r"(a[1]), "r"(a[2]), "r"(a[3]), "r"(b0), "r"(b1));
}

__device__ __forceinline__ void ldmx4(uint32_t* r, uint32_t addr) {
    asm volatile("ldmatrix.sync.aligned.m8n8.x4.shared.b16 {%0,%1,%2,%3}, [%4];"
        : "=r"(r[0]), "=r"(r[1]), "=r"(r[2]), "=r"(r[3]) : "r"(addr));
}

__device__ __forceinline__ uint32_t pack_bf16x2(float x, float y) {
    __nv_bfloat162 p = __halves2bfloat162(__float2bfloat16(x), __float2bfloat16(y));
    return *reinterpret_cast<uint32_t*>(&p);
}

// ---------------------------------------------------------------------------
// Kernel 0a: pack w11 into mma B fragments (hi/lo split)
// ---------------------------------------------------------------------------
__global__ void prep_bfrag_kernel(const float* __restrict__ w11) {
    int blk  = blockIdx.x;
    int lane = threadIdx.x;
    int ks   = blk & 15;
    int nt   = (blk >> 4) & 31;
    int l    = blk >> 9;
    int tg   = lane >> 2, tid = lane & 3;
    int n    = nt * 8 + tg;
    int k0   = ks * 16 + tid * 2;

    const float* w = w11 + (size_t)l * F_ * F_;
    float v00 = w[(size_t)(k0    ) * F_ + n];
    float v01 = w[(size_t)(k0 + 1) * F_ + n];
    float v10 = w[(size_t)(k0 + 8) * F_ + n];
    float v11 = w[(size_t)(k0 + 9) * F_ + n];

    float h00 = __bfloat162float(__float2bfloat16(v00));
    float h01 = __bfloat162float(__float2bfloat16(v01));
    float h10 = __bfloat162float(__float2bfloat16(v10));
    float h11 = __bfloat162float(__float2bfloat16(v11));

    uint4 o;
    o.x = pack_bf16x2(v00, v01);
    o.y = pack_bf16x2(v10, v11);
    o.z = pack_bf16x2(v00 - h00, v01 - h01);
    o.w = pack_bf16x2(v10 - h10, v11 - h11);
    g_Bfrag[(size_t)blk * 32 + lane] = o;
}

// ---------------------------------------------------------------------------
// Kernel 0b: pack w_proj [256,29] into fragments, N padded to 32
// ---------------------------------------------------------------------------
__global__ void prep_pfrag_kernel(const float* __restrict__ w_proj) {
    int blk  = blockIdx.x;
    int lane = threadIdx.x;
    int ks   = blk & 15;
    int nt   = blk >> 4;
    int tg   = lane >> 2, tid = lane & 3;
    int n    = nt * 8 + tg;
    int k0   = ks * 16 + tid * 2;

    float v00 = (n < PROJ_) ? w_proj[(size_t)(k0    ) * PROJ_ + n] : 0.f;
    float v01 = (n < PROJ_) ? w_proj[(size_t)(k0 + 1) * PROJ_ + n] : 0.f;
    float v10 = (n < PROJ_) ? w_proj[(size_t)(k0 + 8) * PROJ_ + n] : 0.f;
    float v11 = (n < PROJ_) ? w_proj[(size_t)(k0 + 9) * PROJ_ + n] : 0.f;

    float h00 = __bfloat162float(__float2bfloat16(v00));
    float h01 = __bfloat162float(__float2bfloat16(v01));
    float h10 = __bfloat162float(__float2bfloat16(v10));
    float h11 = __bfloat162float(__float2bfloat16(v11));

    uint4 o;
    o.x = pack_bf16x2(v00, v01);
    o.y = pack_bf16x2(v10, v11);
    o.z = pack_bf16x2(v00 - h00, v01 - h01);
    o.w = pack_bf16x2(v10 - h10, v11 - h11);
    g_Pfrag[(size_t)blk * 32 + lane] = o;
}

// ---------------------------------------------------------------------------
// Kernel 1: FUSED layer: A = bf16(gelu(LN1(conv(h_in*mask)))) built in SMEM,
// then mma GEMM, then h_out = h_in + gelu(LN2(acc + b11)).
// layer==0: h_in synthesized from x (h = x0*w_pre + b_pre), h_out = g_h.
// CTA: 64 tokens x 256 cols, 256 threads, 2 CTAs/SM. Ping-pong h buffers.
// ---------------------------------------------------------------------------
#define AROW   264
#define GSMEM  (2 * 64 * AROW * 2 + 256)

__global__ void __launch_bounds__(256, 2)
layer_fused_kernel(int layer, int dil,
                   const float* __restrict__ x,
                   const float* __restrict__ mask,
                   const float* __restrict__ w_pre,
                   const float* __restrict__ b_pre,
                   const float* __restrict__ dwk,
                   const float* __restrict__ dwb,
                   const float* __restrict__ g1,
                   const float* __restrict__ b1,
                   const float* __restrict__ b11,
                   const float* __restrict__ g2,
                   const float* __restrict__ b2) {
    extern __shared__ char dyn[];
    __shared__ float4 s_k[3][64], s_b[64], s_g[64], s_bb[64], s_wp[64], s_bp[64];

    char* basep = (char*)(((uintptr_t)dyn + 15) & ~(uintptr_t)15);
    __nv_bfloat16* Ahi = reinterpret_cast<__nv_bfloat16*>(basep);
    __nv_bfloat16* Alo = Ahi + 64 * AROW;
    float* stag = reinterpret_cast<float*>(basep);
    const int SROW = 260;

    const int tid  = threadIdx.x;
    const int wid  = tid >> 5;
    const int lane = tid & 31;
    const int tg   = lane >> 2, tq = lane & 3;
    const int wn   = wid;
    const int m0   = blockIdx.x * 64;

    // residual ping-pong: 0: x->g_h ; 1: g_h->g_h2 ; 2: g_h2->g_h
    const float* h_in  = (layer == 1) ? g_h : g_h2;
    float*       h_out = (layer == 2) ? g_h : ((layer == 0) ? g_h : g_h2);
    // (layer 0 writes g_h; layer 1 writes g_h2; layer 2 writes g_h)

    // ---- stage params ----
    if (tid < 64) {
        s_k[0][tid] = reinterpret_cast<const float4*>(dwk)[tid];
        s_k[1][tid] = reinterpret_cast<const float4*>(dwk)[64 + tid];
        s_k[2][tid] = reinterpret_cast<const float4*>(dwk)[128 + tid];
        s_wp[tid]   = reinterpret_cast<const float4*>(w_pre)[tid];
    } else if (tid < 128) {
        s_b[tid - 64]  = reinterpret_cast<const float4*>(dwb)[tid - 64];
        s_bp[tid - 64] = reinterpret_cast<const float4*>(b_pre)[tid - 64];
    } else if (tid < 192) {
        s_g[tid - 128] = reinterpret_cast<const float4*>(g1)[tid - 128];
    } else {
        s_bb[tid - 192] = reinterpret_cast<const float4*>(b1)[tid - 192];
    }
    __syncthreads();

    // ---- Phase 1: conv + LN1 + gelu -> A SMEM (bf16 hi/lo) ----
    // warp w handles tokens m0 + w*8 .. +7; lane covers features 4L..4L+3, 128+4L..
    #pragma unroll 1
    for (int i = 0; i < 8; i++) {
        int r   = wid * 8 + i;          // CTA-local row
        int tok = m0 + r;
        int t   = tok & (T_ - 1);

        float a[8];
        {
            float4 b0 = s_b[lane], b1v = s_b[lane + 32];
            a[0]=b0.x; a[1]=b0.y; a[2]=b0.z; a[3]=b0.w;
            a[4]=b1v.x; a[5]=b1v.y; a[6]=b1v.z; a[7]=b1v.w;
        }

        #pragma unroll
        for (int tap = 0; tap < 3; tap++) {
            int off = (tap - 1) * dil;
            int tt  = t + off;
            if (tt >= 0 && tt < T_) {
                float mm = __ldg(&mask[tok + off]);
                float4 k0 = s_k[tap][lane], k1 = s_k[tap][lane + 32];
                float karr[8] = {k0.x,k0.y,k0.z,k0.w,k1.x,k1.y,k1.z,k1.w};
                if (layer == 0) {
                    float x0 = __ldg(&x[(size_t)(tok + off) * 2]);
                    float4 w0 = s_wp[lane], w1 = s_wp[lane + 32];
                    float4 p0 = s_bp[lane], p1 = s_bp[lane + 32];
                    float wpar[8] = {w0.x,w0.y,w0.z,w0.w,w1.x,w1.y,w1.z,w1.w};
                    float bpar[8] = {p0.x,p0.y,p0.z,p0.w,p1.x,p1.y,p1.z,p1.w};
                    float xm = x0 * mm;
                    #pragma unroll
                    for (int j = 0; j < 8; j++)
                        a[j] += (xm * wpar[j] + mm * bpar[j]) * karr[j];
                } else {
                    const float4* hr = reinterpret_cast<const float4*>(
                        h_in + (size_t)(tok + off) * F_);
                    float4 h0 = hr[lane], h1 = hr[lane + 32];
                    a[0] += h0.x * mm * karr[0]; a[1] += h0.y * mm * karr[1];
                    a[2] += h0.z * mm * karr[2]; a[3] += h0.w * mm * karr[3];
                    a[4] += h1.x * mm * karr[4]; a[5] += h1.y * mm * karr[5];
                    a[6] += h1.z * mm * karr[6]; a[7] += h1.w * mm * karr[7];
                }
            }
        }

        float s = 0.f, ss = 0.f;
        #pragma unroll
        for (int j = 0; j < 8; j++) { s += a[j]; ss += a[j] * a[j]; }
        #pragma unroll
        for (int o = 16; o; o >>= 1) {
            s  += __shfl_xor_sync(0xFFFFFFFFu, s,  o);
            ss += __shfl_xor_sync(0xFFFFFFFFu, ss, o);
        }
        float mean = s * (1.0f / F_);
        float rstd = rsqrtf(ss * (1.0f / F_) - mean * mean + 1e-5f);

        float4 gg0 = s_g[lane], gg1 = s_g[lane + 32];
        float4 bb0 = s_bb[lane], bb1 = s_bb[lane + 32];
        float garr[8] = {gg0.x,gg0.y,gg0.z,gg0.w,gg1.x,gg1.y,gg1.z,gg1.w};
        float barr[8] = {bb0.x,bb0.y,bb0.z,bb0.w,bb1.x,bb1.y,bb1.z,bb1.w};

        float rv[8];
        #pragma unroll
        for (int j = 0; j < 8; j++) {
            float v = (a[j] - mean) * rstd * garr[j] + barr[j];
            rv[j] = gelu_f(v);
        }
        // pack to A SMEM: features 4*lane (rv0..3), 128+4*lane (rv4..7)
        uint2 hp0, lp0, hp1, lp1;
        float h0 = __bfloat162float(__float2bfloat16(rv[0]));
        float h1v = __bfloat162float(__float2bfloat16(rv[1]));
        float h2 = __bfloat162float(__float2bfloat16(rv[2]));
        float h3 = __bfloat162float(__float2bfloat16(rv[3]));
        float h4 = __bfloat162float(__float2bfloat16(rv[4]));
        float h5 = __bfloat162float(__float2bfloat16(rv[5]));
        float h6 = __bfloat162float(__float2bfloat16(rv[6]));
        float h7 = __bfloat162float(__float2bfloat16(rv[7]));
        hp0.x = pack_bf16x2(rv[0], rv[1]);  hp0.y = pack_bf16x2(rv[2], rv[3]);
        lp0.x = pack_bf16x2(rv[0]-h0, rv[1]-h1v); lp0.y = pack_bf16x2(rv[2]-h2, rv[3]-h3);
        hp1.x = pack_bf16x2(rv[4], rv[5]);  hp1.y = pack_bf16x2(rv[6], rv[7]);
        lp1.x = pack_bf16x2(rv[4]-h4, rv[5]-h5); lp1.y = pack_bf16x2(rv[6]-h6, rv[7]-h7);
        *reinterpret_cast<uint2*>(Ahi + r * AROW + 4*lane)       = hp0;
        *reinterpret_cast<uint2*>(Alo + r * AROW + 4*lane)       = lp0;
        *reinterpret_cast<uint2*>(Ahi + r * AROW + 128 + 4*lane) = hp1;
        *reinterpret_cast<uint2*>(Alo + r * AROW + 128 + 4*lane) = lp1;
    }
    __syncthreads();

    // ---- Phase 2: mainloop ----
    float d[4][4][4];
    #pragma unroll
    for (int mt = 0; mt < 4; mt++)
        #pragma unroll
        for (int nt = 0; nt < 4; nt++)
            #pragma unroll
            for (int q = 0; q < 4; q++) d[mt][nt][q] = 0.f;

    const uint4* Bbase = g_Bfrag + ((size_t)(layer * 32 + wn * 4) * 16) * 32 + lane;
    uint4 bcur[4], bnxt[4];
    #pragma unroll
    for (int nt = 0; nt < 4; nt++) bcur[nt] = __ldg(&Bbase[(nt * 16 + 0) * 32]);

    uint32_t a_hi_addr[4], a_lo_addr[4];
    {
        int r = lane & 15;
        int cb = (lane >> 4) * 16;
        #pragma unroll
        for (int mt = 0; mt < 4; mt++) {
            int row = mt * 16 + r;
            a_hi_addr[mt] = (uint32_t)__cvta_generic_to_shared(Ahi + row * AROW) + cb;
            a_lo_addr[mt] = (uint32_t)__cvta_generic_to_shared(Alo + row * AROW) + cb;
        }
    }

    #pragma unroll 1
    for (int ks = 0; ks < 16; ks++) {
        if (ks < 15) {
            #pragma unroll
            for (int nt = 0; nt < 4; nt++)
                bnxt[nt] = __ldg(&Bbase[(nt * 16 + ks + 1) * 32]);
        }
        const uint32_t koff = ks * 32;
        #pragma unroll
        for (int mt = 0; mt < 4; mt++) {
            uint32_t ah[4], al[4];
            ldmx4(ah, a_hi_addr[mt] + koff);
            ldmx4(al, a_lo_addr[mt] + koff);
            #pragma unroll
            for (int nt = 0; nt < 4; nt++) {
                mma16816(d[mt][nt], ah, bcur[nt].x, bcur[nt].y);
                mma16816(d[mt][nt], ah, bcur[nt].z, bcur[nt].w);
                mma16816(d[mt][nt], al, bcur[nt].x, bcur[nt].y);
            }
        }
        #pragma unroll
        for (int nt = 0; nt < 4; nt++) bcur[nt] = bnxt[nt];
    }

    // ---- stage accum ----
    __syncthreads();
    #pragma unroll
    for (int mt = 0; mt < 4; mt++) {
        int r0 = mt * 16 + tg;
        #pragma unroll
        for (int nt = 0; nt < 4; nt++) {
            int col = wn * 32 + nt * 8 + tq * 2;
            *reinterpret_cast<float2*>(&stag[r0 * SROW + col]) =
                make_float2(d[mt][nt][0], d[mt][nt][1]);
            *reinterpret_cast<float2*>(&stag[(r0 + 8) * SROW + col]) =
                make_float2(d[mt][nt][2], d[mt][nt][3]);
        }
    }
    __syncthreads();

    // ---- Phase 3: LN2 + gelu + residual -> h_out ----
    #pragma unroll 1
    for (int i = 0; i < 8; i++) {
        int row = wid * 8 + i;
        float4 f0 = *reinterpret_cast<const float4*>(&stag[row * SROW + lane * 8]);
        float4 f1 = *reinterpret_cast<const float4*>(&stag[row * SROW + lane * 8 + 4]);
        float4 bb0 = reinterpret_cast<const float4*>(b11)[lane * 2];
        float4 bb1 = reinterpret_cast<const float4*>(b11)[lane * 2 + 1];
        float v[8] = {f0.x + bb0.x, f0.y + bb0.y, f0.z + bb0.z, f0.w + bb0.w,
                      f1.x + bb1.x, f1.y + bb1.y, f1.z + bb1.z, f1.w + bb1.w};
        float s = 0.f, ss = 0.f;
        #pragma unroll
        for (int j = 0; j < 8; j++) { s += v[j]; ss += v[j] * v[j]; }
        #pragma unroll
        for (int o = 16; o; o >>= 1) {
            s  += __shfl_xor_sync(0xFFFFFFFFu, s,  o);
            ss += __shfl_xor_sync(0xFFFFFFFFu, ss, o);
        }
        float mean = s * (1.0f / F_);
        float rstd = rsqrtf(ss * (1.0f / F_) - mean * mean + 1e-5f);

        float4 gg0 = reinterpret_cast<const float4*>(g2)[lane * 2];
        float4 gg1 = reinterpret_cast<const float4*>(g2)[lane * 2 + 1];
        float4 zb0 = reinterpret_cast<const float4*>(b2)[lane * 2];
        float4 zb1 = reinterpret_cast<const float4*>(b2)[lane * 2 + 1];
        float garr[8] = {gg0.x,gg0.y,gg0.z,gg0.w,gg1.x,gg1.y,gg1.z,gg1.w};
        float barr[8] = {zb0.x,zb0.y,zb0.z,zb0.w,zb1.x,zb1.y,zb1.z,zb1.w};

        // h_in value for residual
        float hv[8];
        if (layer == 0) {
            float x0 = __ldg(&x[(size_t)(m0 + row) * 2]);
            float4 w0 = s_wp[lane * 2], w1 = s_wp[lane * 2 + 1];
            float4 p0 = s_bp[lane * 2], p1 = s_bp[lane * 2 + 1];
            hv[0] = x0*w0.x + p0.x; hv[1] = x0*w0.y + p0.y;
            hv[2] = x0*w0.z + p0.z; hv[3] = x0*w0.w + p0.w;
            hv[4] = x0*w1.x + p1.x; hv[5] = x0*w1.y + p1.y;
            hv[6] = x0*w1.z + p1.z; hv[7] = x0*w1.w + p1.w;
        } else {
            const float4* hp = reinterpret_cast<const float4*>(
                h_in + (size_t)(m0 + row) * F_ + lane * 8);
            float4 h0 = hp[0], h1 = hp[1];
            hv[0]=h0.x; hv[1]=h0.y; hv[2]=h0.z; hv[3]=h0.w;
            hv[4]=h1.x; hv[5]=h1.y; hv[6]=h1.z; hv[7]=h1.w;
        }
        #pragma unroll
        for (int j = 0; j < 8; j++) {
            float z = (v[j] - mean) * rstd * garr[j] + barr[j];
            hv[j] += gelu_f(z);
        }
        float4* op = reinterpret_cast<float4*>(
            h_out + (size_t)(m0 + row) * F_ + lane * 8);
        op[0] = make_float4(hv[0], hv[1], hv[2], hv[3]);
        op[1] = make_float4(hv[4], hv[5], hv[6], hv[7]);
    }
}

// ---------------------------------------------------------------------------
// Kernel 4a: proj GEMM: g_proj = (h*mask) @ w_proj  (N padded to 32)
// CTA: 64 tokens, 256 threads = 8 warps; warp = (m subtile, n half)
// ---------------------------------------------------------------------------
__global__ void __launch_bounds__(256, 2)
proj_gemm_kernel(const float* __restrict__ mask) {
    extern __shared__ char dyn[];
    char* basep = (char*)(((uintptr_t)dyn + 15) & ~(uintptr_t)15);
    __nv_bfloat16* Ahi = reinterpret_cast<__nv_bfloat16*>(basep);
    __nv_bfloat16* Alo = Ahi + 64 * AROW;

    const int tid  = threadIdx.x;
    const int wid  = tid >> 5;
    const int lane = tid & 31;
    const int tg   = lane >> 2, tq = lane & 3;
    const int mi   = wid & 3;           // m subtile
    const int nh   = wid >> 2;          // n half (nt base = nh*2)
    const int m0   = blockIdx.x * 64;

    // ---- load A (64 x 256 fp32 h*mask) -> bf16 hi/lo ----
    {
        int row = tid >> 2;             // 0..63
        int q   = tid & 3;
        float mm = __ldg(&mask[m0 + row]);
        const float4* src = reinterpret_cast<const float4*>(
            g_h + (size_t)(m0 + row) * F_) + q * 16;
        #pragma unroll
        for (int j = 0; j < 16; j++) {
            float4 v = src[j];
            v.x *= mm; v.y *= mm; v.z *= mm; v.w *= mm;
            float hx = __bfloat162float(__float2bfloat16(v.x));
            float hy = __bfloat162float(__float2bfloat16(v.y));
            float hz = __bfloat162float(__float2bfloat16(v.z));
            float hw = __bfloat162float(__float2bfloat16(v.w));
            uint2 hp, lp;
            hp.x = pack_bf16x2(v.x, v.y);
            hp.y = pack_bf16x2(v.z, v.w);
            lp.x = pack_bf16x2(v.x - hx, v.y - hy);
            lp.y = pack_bf16x2(v.z - hz, v.w - hw);
            int c = (q * 16 + j) * 4;
            *reinterpret_cast<uint2*>(Ahi + row * AROW + c) = hp;
            *reinterpret_cast<uint2*>(Alo + row * AROW + c) = lp;
        }
    }
    __syncthreads();

    float d[2][4];
    #pragma unroll
    for (int nt = 0; nt < 2; nt++)
        #pragma unroll
        for (int q = 0; q < 4; q++) d[nt][q] = 0.f;

    const uint4* Bbase = g_Pfrag + ((size_t)(nh * 2) * 16) * 32 + lane;
    uint4 bcur[2], bnxt[2];
    #pragma unroll
    for (int nt = 0; nt < 2; nt++) bcur[nt] = __ldg(&Bbase[(nt * 16 + 0) * 32]);

    uint32_t a_hi_addr, a_lo_addr;
    {
        int r = lane & 15;
        int cb = (lane >> 4) * 16;
        int row = mi * 16 + r;
        a_hi_addr = (uint32_t)__cvta_generic_to_shared(Ahi + row * AROW) + cb;
        a_lo_addr = (uint32_t)__cvta_generic_to_shared(Alo + row * AROW) + cb;
    }

    #pragma unroll 1
    for (int ks = 0; ks < 16; ks++) {
        if (ks < 15) {
            #pragma unroll
            for (int nt = 0; nt < 2; nt++)
                bnxt[nt] = __ldg(&Bbase[(nt * 16 + ks + 1) * 32]);
        }
        const uint32_t koff = ks * 32;
        uint32_t ah[4], al[4];
        ldmx4(ah, a_hi_addr + koff);
        ldmx4(al, a_lo_addr + koff);
        #pragma unroll
        for (int nt = 0; nt < 2; nt++) {
            mma16816(d[nt], ah, bcur[nt].x, bcur[nt].y);
            mma16816(d[nt], ah, bcur[nt].z, bcur[nt].w);
            mma16816(d[nt], al, bcur[nt].x, bcur[nt].y);
        }
        #pragma unroll
        for (int nt = 0; nt < 2; nt++) bcur[nt] = bnxt[nt];
    }

    #pragma unroll
    for (int nt = 0; nt < 2; nt++) {
        int col  = nh * 16 + nt * 8 + tq * 2;
        int row0 = m0 + mi * 16 + tg;
        *reinterpret_cast<float2*>(&g_proj[(size_t)row0 * 32 + col]) =
            make_float2(d[nt][0], d[nt][1]);
        *reinterpret_cast<float2*>(&g_proj[(size_t)(row0 + 8) * 32 + col]) =
            make_float2(d[nt][2], d[nt][3]);
    }
}

// ---------------------------------------------------------------------------
// Kernel 4b: RQ spline, one THREAD per token
// ---------------------------------------------------------------------------
__device__ __forceinline__ float softplus_f(float v) {
    return fmaxf(v, 0.f) + log1pf(expf(-fabsf(v)));
}

__global__ void __launch_bounds__(256)
spline_kernel(const float* __restrict__ x,
              const float* __restrict__ mask,
              const float* __restrict__ b_proj,
              float* __restrict__ out) {
    int tok = blockIdx.x * 256 + threadIdx.x;
    float m = mask[tok];

    float proj[PROJ_];
    #pragma unroll
    for (int p = 0; p < PROJ_; p++)
        proj[p] = (g_proj[(size_t)tok * 32 + p] + __ldg(&b_proj[p])) * m;

    const float scale = 0.0625f;

    float cw[NB_ + 1], ww[NB_];
    {
        float mx = proj[0] * scale;
        #pragma unroll
        for (int j = 1; j < NB_; j++) mx = fmaxf(mx, proj[j] * scale);
        float e[NB_], sum = 0.f;
        #pragma unroll
        for (int j = 0; j < NB_; j++) { e[j] = expf(proj[j] * scale - mx); sum += e[j]; }
        float inv = 1.0f / sum;
        float cum = 0.f;
        cw[0] = -TBND;
        #pragma unroll
        for (int j = 0; j < NB_; j++) {
            float wj = 0.001f + (1.0f - 0.001f * NB_) * (e[j] * inv);
            cum += wj;
            cw[j + 1] = 2.0f * TBND * cum - TBND;
        }
        cw[NB_] = TBND;
        #pragma unroll
        for (int j = 0; j < NB_; j++) ww[j] = cw[j + 1] - cw[j];
    }
    float ch[NB_ + 1], hh[NB_];
    {
        float mx = proj[NB_] * scale;
        #pragma unroll
        for (int j = 1; j < NB_; j++) mx = fmaxf(mx, proj[NB_ + j] * scale);
        float e[NB_], sum = 0.f;
        #pragma unroll
        for (int j = 0; j < NB_; j++) { e[j] = expf(proj[NB_ + j] * scale - mx); sum += e[j]; }
        float inv = 1.0f / sum;
        float cum = 0.f;
        ch[0] = -TBND;
        #pragma unroll
        for (int j = 0; j < NB_; j++) {
            float hj = 0.001f + (1.0f - 0.001f * NB_) * (e[j] * inv);
            cum += hj;
            ch[j + 1] = 2.0f * TBND * cum - TBND;
        }
        ch[NB_] = TBND;
        #pragma unroll
        for (int j = 0; j < NB_; j++) hh[j] = ch[j + 1] - ch[j];
    }
    float d[NB_ + 1];
    float cst = logf(expm1f(1.0f - 0.001f));
    d[0]   = 0.001f + softplus_f(cst);
    d[NB_] = d[0];
    #pragma unroll
    for (int k = 1; k < NB_; k++) d[k] = 0.001f + softplus_f(proj[2 * NB_ + k - 1]);

    float x1 = x[(size_t)tok * 2 + 1];
    float xc = fminf(fmaxf(x1, -TBND), TBND);
    int idx = 0;
    #pragma unroll
    for (int j = 1; j <= NB_; j++) idx += (xc >= cw[j]) ? 1 : 0;
    if (idx > NB_ - 1) idx = NB_ - 1;

    float icw = cw[idx], ibw = ww[idx];
    float ich = ch[idx], ibh = hh[idx];
    float delta = ibh / ibw;
    float dk = d[idx], dk1 = d[idx + 1];
    float th   = (xc - icw) / ibw;
    float th1m = th * (1.0f - th);
    float denom = delta + (dk + dk1 - 2.0f * delta) * th1m;
    float num   = ibh * (delta * th * th + dk * th1m);
    float yv    = ich + num / denom;
    float omth  = 1.0f - th;
    float dnum  = delta * delta * (dk1 * th * th + 2.0f * delta * th1m + dk * omth * omth);
    float lad   = logf(dnum) - 2.0f * logf(denom);

    bool inside = (x1 >= -TBND) && (x1 <= TBND);
    float y1 = inside ? yv : x1;
    lad = inside ? lad : 0.0f;

    out[(size_t)tok * 2]     = x[(size_t)tok * 2] * m;
    out[(size_t)tok * 2 + 1] = y1 * m;
    g_lad[tok] = lad * m;
}

// ---------------------------------------------------------------------------
// Kernel 5: deterministic per-batch logdet reduction
// ---------------------------------------------------------------------------
__global__ void logdet_kernel(float* __restrict__ out) {
    int b = blockIdx.x, tid = threadIdx.x;
    float s = 0.f;
    for (int j = tid; j < T_; j += 256) s += g_lad[b * T_ + j];
    __shared__ float sh[256];
    sh[tid] = s;
    __syncthreads();
    #pragma unroll
    for (int o = 128; o; o >>= 1) {
        if (tid < o) sh[tid] += sh[tid + o];
        __syncthreads();
    }
    if (tid == 0) out[(size_t)BT_ * 2 + b] = sh[0];
}

// ---------------------------------------------------------------------------
extern "C" void kernel_launch(void* const* d_in, const int* in_sizes, int n_in,
                              void* d_out, int out_size) {
    const float* x      = (const float*)d_in[0];
    const float* mask   = (const float*)d_in[1];
    const float* w_pre  = (const float*)d_in[2];
    const float* b_pre  = (const float*)d_in[3];
    const float* dw_k   = (const float*)d_in[4];
    const float* dw_b   = (const float*)d_in[5];
    const float* w11    = (const float*)d_in[6];
    const float* b11    = (const float*)d_in[7];
    const float* ln1g   = (const float*)d_in[8];
    const float* ln1b   = (const float*)d_in[9];
    const float* ln2g   = (const float*)d_in[10];
    const float* ln2b   = (const float*)d_in[11];
    const float* w_proj = (const float*)d_in[12];
    const float* b_proj = (const float*)d_in[13];
    float* out = (float*)d_out;

    cudaFuncSetAttribute(layer_fused_kernel,
                         cudaFuncAttributeMaxDynamicSharedMemorySize, GSMEM);
    cudaFuncSetAttribute(proj_gemm_kernel,
                         cudaFuncAttributeMaxDynamicSharedMemorySize, GSMEM);

    prep_bfrag_kernel<<<NL_ * 32 * 16, 32>>>(w11);
    prep_pfrag_kernel<<<4 * 16, 32>>>(w_proj);

    int dil = 1;
    for (int i = 0; i < NL_; i++) {
        layer_fused_kernel<<<BT_ / 64, 256, GSMEM>>>(
            i, dil, x, mask, w_pre, b_pre,
            dw_k + (size_t)i * KS_ * F_,
            dw_b + (size_t)i * F_,
            ln1g + (size_t)i * F_,
            ln1b + (size_t)i * F_,
            b11 + (size_t)i * F_,
            ln2g + (size_t)i * F_,
            ln2b + (size_t)i * F_);
        dil *= KS_;
    }

    proj_gemm_kernel<<<BT_ / 64, 256, GSMEM>>>(mask);
    spline_kernel<<<BT_ / 256, 256>>>(x, mask, b_proj, out);
    logdet_kernel<<<B_, 256>>>(out);
}

// round 11
// speedup vs baseline: 3.6373x; 1.0097x over previous
#include <cuda_runtime.h>
#include <cuda_bf16.h>
#include <math.h>
#include <stdint.h>
#include <cstdint>

#define B_    16
#define T_    8192
#define F_    256
#define NL_   3
#define KS_   3
#define NB_   10
#define PROJ_ 29
#define BT_   (B_*T_)
#define TBND  5.0f

__device__ float g_h[(size_t)BT_ * F_];     // residual ping
__device__ float g_h2[(size_t)BT_ * F_];    // residual pong
__device__ float g_lad[BT_];
__device__ float g_proj[(size_t)BT_ * 32];
__device__ uint4 g_Bfrag[NL_ * 32 * 16 * 32];
__device__ uint4 g_Pfrag[4 * 16 * 32];

__device__ __forceinline__ float gelu_f(float v) {
    return 0.5f * v * (1.0f + erff(v * 0.7071067811865476f));
}

__device__ __forceinline__ void mma16816(float* d, const uint32_t* a,
                                         uint32_t b0, uint32_t b1) {
    asm volatile(
        "mma.sync.aligned.m16n8k16.row.col.f32.bf16.bf16.f32 "
        "{%0,%1,%2,%3}, {%4,%5,%6,%7}, {%8,%9}, {%0,%1,%2,%3};"
        : "+f"(d[0]), "+f"(d[1]), "+f"(d[2]), "+f"(d[3])
        : "r"(a[0]), "r"(a[1]), "r"(a[2]), "r"(a[3]), "r"(b0), "r"(b1));
}

__device__ __forceinline__ void ldmx4(uint32_t* r, uint32_t addr) {
    asm volatile("ldmatrix.sync.aligned.m8n8.x4.shared.b16 {%0,%1,%2,%3}, [%4];"
        : "=r"(r[0]), "=r"(r[1]), "=r"(r[2]), "=r"(r[3]) : "r"(addr));
}

__device__ __forceinline__ uint32_t pack_bf16x2(float x, float y) {
    __nv_bfloat162 p = __halves2bfloat162(__float2bfloat16(x), __float2bfloat16(y));
    return *reinterpret_cast<uint32_t*>(&p);
}

// ---------------------------------------------------------------------------
// Kernel 0a: pack w11 into mma B fragments (hi/lo split)
// ---------------------------------------------------------------------------
__global__ void prep_bfrag_kernel(const float* __restrict__ w11) {
    int blk  = blockIdx.x;
    int lane = threadIdx.x;
    int ks   = blk & 15;
    int nt   = (blk >> 4) & 31;
    int l    = blk >> 9;
    int tg   = lane >> 2, tid = lane & 3;
    int n    = nt * 8 + tg;
    int k0   = ks * 16 + tid * 2;

    const float* w = w11 + (size_t)l * F_ * F_;
    float v00 = w[(size_t)(k0    ) * F_ + n];
    float v01 = w[(size_t)(k0 + 1) * F_ + n];
    float v10 = w[(size_t)(k0 + 8) * F_ + n];
    float v11 = w[(size_t)(k0 + 9) * F_ + n];

    float h00 = __bfloat162float(__float2bfloat16(v00));
    float h01 = __bfloat162float(__float2bfloat16(v01));
    float h10 = __bfloat162float(__float2bfloat16(v10));
    float h11 = __bfloat162float(__float2bfloat16(v11));

    uint4 o;
    o.x = pack_bf16x2(v00, v01);
    o.y = pack_bf16x2(v10, v11);
    o.z = pack_bf16x2(v00 - h00, v01 - h01);
    o.w = pack_bf16x2(v10 - h10, v11 - h11);
    g_Bfrag[(size_t)blk * 32 + lane] = o;
}

// ---------------------------------------------------------------------------
// Kernel 0b: pack w_proj [256,29] into fragments, N padded to 32
// ---------------------------------------------------------------------------
__global__ void prep_pfrag_kernel(const float* __restrict__ w_proj) {
    int blk  = blockIdx.x;
    int lane = threadIdx.x;
    int ks   = blk & 15;
    int nt   = blk >> 4;
    int tg   = lane >> 2, tid = lane & 3;
    int n    = nt * 8 + tg;
    int k0   = ks * 16 + tid * 2;

    float v00 = (n < PROJ_) ? w_proj[(size_t)(k0    ) * PROJ_ + n] : 0.f;
    float v01 = (n < PROJ_) ? w_proj[(size_t)(k0 + 1) * PROJ_ + n] : 0.f;
    float v10 = (n < PROJ_) ? w_proj[(size_t)(k0 + 8) * PROJ_ + n] : 0.f;
    float v11 = (n < PROJ_) ? w_proj[(size_t)(k0 + 9) * PROJ_ + n] : 0.f;

    float h00 = __bfloat162float(__float2bfloat16(v00));
    float h01 = __bfloat162float(__float2bfloat16(v01));
    float h10 = __bfloat162float(__float2bfloat16(v10));
    float h11 = __bfloat162float(__float2bfloat16(v11));

    uint4 o;
    o.x = pack_bf16x2(v00, v01);
    o.y = pack_bf16x2(v10, v11);
    o.z = pack_bf16x2(v00 - h00, v01 - h01);
    o.w = pack_bf16x2(v10 - h10, v11 - h11);
    g_Pfrag[(size_t)blk * 32 + lane] = o;
}

// ---------------------------------------------------------------------------
// Kernel 1: FUSED layer, 512 threads (16 warps = 2M x 8N), warp tile 32x32.
// A = bf16(gelu(LN1(conv(h_in*mask)))) in SMEM -> mma -> h_out = h_in + ...
// layer==0: h_in synthesized from x. 2 CTAs/SM (<=64 regs).
// ---------------------------------------------------------------------------
#define AROW   264
#define GSMEM  (2 * 64 * AROW * 2 + 256)

__global__ void __launch_bounds__(512, 2)
layer_fused_kernel(int layer, int dil,
                   const float* __restrict__ x,
                   const float* __restrict__ mask,
                   const float* __restrict__ w_pre,
                   const float* __restrict__ b_pre,
                   const float* __restrict__ dwk,
                   const float* __restrict__ dwb,
                   const float* __restrict__ g1,
                   const float* __restrict__ b1,
                   const float* __restrict__ b11,
                   const float* __restrict__ g2,
                   const float* __restrict__ b2) {
    extern __shared__ char dyn[];
    __shared__ float4 s_k[3][64], s_b[64], s_g[64], s_bb[64], s_wp[64], s_bp[64];

    char* basep = (char*)(((uintptr_t)dyn + 15) & ~(uintptr_t)15);
    __nv_bfloat16* Ahi = reinterpret_cast<__nv_bfloat16*>(basep);
    __nv_bfloat16* Alo = Ahi + 64 * AROW;
    float* stag = reinterpret_cast<float*>(basep);
    const int SROW = 260;

    const int tid  = threadIdx.x;
    const int wid  = tid >> 5;          // 0..15
    const int lane = tid & 31;
    const int tg   = lane >> 2, tq = lane & 3;
    const int wm   = wid >> 3;          // 0..1  M group
    const int wn   = wid & 7;           // 0..7  N group
    const int m0   = blockIdx.x * 64;

    // residual ping-pong: 0: x->g_h ; 1: g_h->g_h2 ; 2: g_h2->g_h
    const float* h_in  = (layer == 1) ? g_h : g_h2;
    float*       h_out = (layer == 1) ? g_h2 : g_h;

    // ---- stage params ----
    if (tid < 64) {
        s_k[0][tid] = reinterpret_cast<const float4*>(dwk)[tid];
        s_k[1][tid] = reinterpret_cast<const float4*>(dwk)[64 + tid];
        s_k[2][tid] = reinterpret_cast<const float4*>(dwk)[128 + tid];
        s_wp[tid]   = reinterpret_cast<const float4*>(w_pre)[tid];
    } else if (tid < 128) {
        s_b[tid - 64]  = reinterpret_cast<const float4*>(dwb)[tid - 64];
        s_bp[tid - 64] = reinterpret_cast<const float4*>(b_pre)[tid - 64];
    } else if (tid < 192) {
        s_g[tid - 128] = reinterpret_cast<const float4*>(g1)[tid - 128];
    } else if (tid < 256) {
        s_bb[tid - 192] = reinterpret_cast<const float4*>(b1)[tid - 192];
    }
    __syncthreads();

    // ---- Phase 1: conv + LN1 + gelu -> A SMEM (bf16 hi/lo); 4 rows/warp ----
    #pragma unroll 1
    for (int i = 0; i < 4; i++) {
        int r   = wid * 4 + i;          // CTA-local row 0..63
        int tok = m0 + r;
        int t   = tok & (T_ - 1);

        float a[8];
        {
            float4 b0 = s_b[lane], b1v = s_b[lane + 32];
            a[0]=b0.x; a[1]=b0.y; a[2]=b0.z; a[3]=b0.w;
            a[4]=b1v.x; a[5]=b1v.y; a[6]=b1v.z; a[7]=b1v.w;
        }

        #pragma unroll
        for (int tap = 0; tap < 3; tap++) {
            int off = (tap - 1) * dil;
            int tt  = t + off;
            if (tt >= 0 && tt < T_) {
                float mm = __ldg(&mask[tok + off]);
                float4 k0 = s_k[tap][lane], k1 = s_k[tap][lane + 32];
                float karr[8] = {k0.x,k0.y,k0.z,k0.w,k1.x,k1.y,k1.z,k1.w};
                if (layer == 0) {
                    float x0 = __ldg(&x[(size_t)(tok + off) * 2]);
                    float4 w0 = s_wp[lane], w1 = s_wp[lane + 32];
                    float4 p0 = s_bp[lane], p1 = s_bp[lane + 32];
                    float wpar[8] = {w0.x,w0.y,w0.z,w0.w,w1.x,w1.y,w1.z,w1.w};
                    float bpar[8] = {p0.x,p0.y,p0.z,p0.w,p1.x,p1.y,p1.z,p1.w};
                    float xm = x0 * mm;
                    #pragma unroll
                    for (int j = 0; j < 8; j++)
                        a[j] += (xm * wpar[j] + mm * bpar[j]) * karr[j];
                } else {
                    const float4* hr = reinterpret_cast<const float4*>(
                        h_in + (size_t)(tok + off) * F_);
                    float4 h0 = hr[lane], h1 = hr[lane + 32];
                    a[0] += h0.x * mm * karr[0]; a[1] += h0.y * mm * karr[1];
                    a[2] += h0.z * mm * karr[2]; a[3] += h0.w * mm * karr[3];
                    a[4] += h1.x * mm * karr[4]; a[5] += h1.y * mm * karr[5];
                    a[6] += h1.z * mm * karr[6]; a[7] += h1.w * mm * karr[7];
                }
            }
        }

        float s = 0.f, ss = 0.f;
        #pragma unroll
        for (int j = 0; j < 8; j++) { s += a[j]; ss += a[j] * a[j]; }
        #pragma unroll
        for (int o = 16; o; o >>= 1) {
            s  += __shfl_xor_sync(0xFFFFFFFFu, s,  o);
            ss += __shfl_xor_sync(0xFFFFFFFFu, ss, o);
        }
        float mean = s * (1.0f / F_);
        float rstd = rsqrtf(ss * (1.0f / F_) - mean * mean + 1e-5f);

        float4 gg0 = s_g[lane], gg1 = s_g[lane + 32];
        float4 bb0 = s_bb[lane], bb1 = s_bb[lane + 32];
        float garr[8] = {gg0.x,gg0.y,gg0.z,gg0.w,gg1.x,gg1.y,gg1.z,gg1.w};
        float barr[8] = {bb0.x,bb0.y,bb0.z,bb0.w,bb1.x,bb1.y,bb1.z,bb1.w};

        float rv[8];
        #pragma unroll
        for (int j = 0; j < 8; j++) {
            float v = (a[j] - mean) * rstd * garr[j] + barr[j];
            rv[j] = gelu_f(v);
        }
        uint2 hp0, lp0, hp1, lp1;
        float h0 = __bfloat162float(__float2bfloat16(rv[0]));
        float h1v = __bfloat162float(__float2bfloat16(rv[1]));
        float h2 = __bfloat162float(__float2bfloat16(rv[2]));
        float h3 = __bfloat162float(__float2bfloat16(rv[3]));
        float h4 = __bfloat162float(__float2bfloat16(rv[4]));
        float h5 = __bfloat162float(__float2bfloat16(rv[5]));
        float h6 = __bfloat162float(__float2bfloat16(rv[6]));
        float h7 = __bfloat162float(__float2bfloat16(rv[7]));
        hp0.x = pack_bf16x2(rv[0], rv[1]);  hp0.y = pack_bf16x2(rv[2], rv[3]);
        lp0.x = pack_bf16x2(rv[0]-h0, rv[1]-h1v); lp0.y = pack_bf16x2(rv[2]-h2, rv[3]-h3);
        hp1.x = pack_bf16x2(rv[4], rv[5]);  hp1.y = pack_bf16x2(rv[6], rv[7]);
        lp1.x = pack_bf16x2(rv[4]-h4, rv[5]-h5); lp1.y = pack_bf16x2(rv[6]-h6, rv[7]-h7);
        *reinterpret_cast<uint2*>(Ahi + r * AROW + 4*lane)       = hp0;
        *reinterpret_cast<uint2*>(Alo + r * AROW + 4*lane)       = lp0;
        *reinterpret_cast<uint2*>(Ahi + r * AROW + 128 + 4*lane) = hp1;
        *reinterpret_cast<uint2*>(Alo + r * AROW + 128 + 4*lane) = lp1;
    }
    __syncthreads();

    // ---- Phase 2: mainloop (warp tile 32x32, single-buffered B) ----
    float d[2][4][4];
    #pragma unroll
    for (int mt = 0; mt < 2; mt++)
        #pragma unroll
        for (int nt = 0; nt < 4; nt++)
            #pragma unroll
            for (int q = 0; q < 4; q++) d[mt][nt][q] = 0.f;

    const uint4* Bbase = g_Bfrag + ((size_t)(layer * 32 + wn * 4) * 16) * 32 + lane;

    uint32_t a_hi_addr[2], a_lo_addr[2];
    {
        int r = lane & 15;
        int cb = (lane >> 4) * 16;
        #pragma unroll
        for (int mt = 0; mt < 2; mt++) {
            int row = wm * 32 + mt * 16 + r;
            a_hi_addr[mt] = (uint32_t)__cvta_generic_to_shared(Ahi + row * AROW) + cb;
            a_lo_addr[mt] = (uint32_t)__cvta_generic_to_shared(Alo + row * AROW) + cb;
        }
    }

    #pragma unroll 1
    for (int ks = 0; ks < 16; ks++) {
        uint4 bcur[4];
        #pragma unroll
        for (int nt = 0; nt < 4; nt++)
            bcur[nt] = __ldg(&Bbase[(nt * 16 + ks) * 32]);
        const uint32_t koff = ks * 32;
        #pragma unroll
        for (int mt = 0; mt < 2; mt++) {
            uint32_t ah[4], al[4];
            ldmx4(ah, a_hi_addr[mt] + koff);
            ldmx4(al, a_lo_addr[mt] + koff);
            #pragma unroll
            for (int nt = 0; nt < 4; nt++) {
                mma16816(d[mt][nt], ah, bcur[nt].x, bcur[nt].y);
                mma16816(d[mt][nt], ah, bcur[nt].z, bcur[nt].w);
                mma16816(d[mt][nt], al, bcur[nt].x, bcur[nt].y);
            }
        }
    }

    // ---- stage accum ----
    __syncthreads();
    #pragma unroll
    for (int mt = 0; mt < 2; mt++) {
        int r0 = wm * 32 + mt * 16 + tg;
        #pragma unroll
        for (int nt = 0; nt < 4; nt++) {
            int col = wn * 32 + nt * 8 + tq * 2;
            *reinterpret_cast<float2*>(&stag[r0 * SROW + col]) =
                make_float2(d[mt][nt][0], d[mt][nt][1]);
            *reinterpret_cast<float2*>(&stag[(r0 + 8) * SROW + col]) =
                make_float2(d[mt][nt][2], d[mt][nt][3]);
        }
    }
    __syncthreads();

    // ---- Phase 3: LN2 + gelu + residual -> h_out; 4 rows/warp ----
    #pragma unroll 1
    for (int i = 0; i < 4; i++) {
        int row = wid * 4 + i;
        float4 f0 = *reinterpret_cast<const float4*>(&stag[row * SROW + lane * 8]);
        float4 f1 = *reinterpret_cast<const float4*>(&stag[row * SROW + lane * 8 + 4]);
        float4 bb0 = reinterpret_cast<const float4*>(b11)[lane * 2];
        float4 bb1 = reinterpret_cast<const float4*>(b11)[lane * 2 + 1];
        float v[8] = {f0.x + bb0.x, f0.y + bb0.y, f0.z + bb0.z, f0.w + bb0.w,
                      f1.x + bb1.x, f1.y + bb1.y, f1.z + bb1.z, f1.w + bb1.w};
        float s = 0.f, ss = 0.f;
        #pragma unroll
        for (int j = 0; j < 8; j++) { s += v[j]; ss += v[j] * v[j]; }
        #pragma unroll
        for (int o = 16; o; o >>= 1) {
            s  += __shfl_xor_sync(0xFFFFFFFFu, s,  o);
            ss += __shfl_xor_sync(0xFFFFFFFFu, ss, o);
        }
        float mean = s * (1.0f / F_);
        float rstd = rsqrtf(ss * (1.0f / F_) - mean * mean + 1e-5f);

        float4 gg0 = reinterpret_cast<const float4*>(g2)[lane * 2];
        float4 gg1 = reinterpret_cast<const float4*>(g2)[lane * 2 + 1];
        float4 zb0 = reinterpret_cast<const float4*>(b2)[lane * 2];
        float4 zb1 = reinterpret_cast<const float4*>(b2)[lane * 2 + 1];
        float garr[8] = {gg0.x,gg0.y,gg0.z,gg0.w,gg1.x,gg1.y,gg1.z,gg1.w};
        float barr[8] = {zb0.x,zb0.y,zb0.z,zb0.w,zb1.x,zb1.y,zb1.z,zb1.w};

        float hv[8];
        if (layer == 0) {
            float x0 = __ldg(&x[(size_t)(m0 + row) * 2]);
            float4 w0 = s_wp[lane * 2], w1 = s_wp[lane * 2 + 1];
            float4 p0 = s_bp[lane * 2], p1 = s_bp[lane * 2 + 1];
            hv[0] = x0*w0.x + p0.x; hv[1] = x0*w0.y + p0.y;
            hv[2] = x0*w0.z + p0.z; hv[3] = x0*w0.w + p0.w;
            hv[4] = x0*w1.x + p1.x; hv[5] = x0*w1.y + p1.y;
            hv[6] = x0*w1.z + p1.z; hv[7] = x0*w1.w + p1.w;
        } else {
            const float4* hp = reinterpret_cast<const float4*>(
                h_in + (size_t)(m0 + row) * F_ + lane * 8);
            float4 h0 = hp[0], h1 = hp[1];
            hv[0]=h0.x; hv[1]=h0.y; hv[2]=h0.z; hv[3]=h0.w;
            hv[4]=h1.x; hv[5]=h1.y; hv[6]=h1.z; hv[7]=h1.w;
        }
        #pragma unroll
        for (int j = 0; j < 8; j++) {
            float z = (v[j] - mean) * rstd * garr[j] + barr[j];
            hv[j] += gelu_f(z);
        }
        float4* op = reinterpret_cast<float4*>(
            h_out + (size_t)(m0 + row) * F_ + lane * 8);
        op[0] = make_float4(hv[0], hv[1], hv[2], hv[3]);
        op[1] = make_float4(hv[4], hv[5], hv[6], hv[7]);
    }
}

// ---------------------------------------------------------------------------
// Kernel 4a: proj GEMM: g_proj = (h*mask) @ w_proj  (N padded to 32)
// ---------------------------------------------------------------------------
__global__ void __launch_bounds__(256, 2)
proj_gemm_kernel(const float* __restrict__ mask) {
    extern __shared__ char dyn[];
    char* basep = (char*)(((uintptr_t)dyn + 15) & ~(uintptr_t)15);
    __nv_bfloat16* Ahi = reinterpret_cast<__nv_bfloat16*>(basep);
    __nv_bfloat16* Alo = Ahi + 64 * AROW;

    const int tid  = threadIdx.x;
    const int wid  = tid >> 5;
    const int lane = tid & 31;
    const int tg   = lane >> 2, tq = lane & 3;
    const int mi   = wid & 3;
    const int nh   = wid >> 2;
    const int m0   = blockIdx.x * 64;

    {
        int row = tid >> 2;
        int q   = tid & 3;
        float mm = __ldg(&mask[m0 + row]);
        const float4* src = reinterpret_cast<const float4*>(
            g_h + (size_t)(m0 + row) * F_) + q * 16;
        #pragma unroll
        for (int j = 0; j < 16; j++) {
            float4 v = src[j];
            v.x *= mm; v.y *= mm; v.z *= mm; v.w *= mm;
            float hx = __bfloat162float(__float2bfloat16(v.x));
            float hy = __bfloat162float(__float2bfloat16(v.y));
            float hz = __bfloat162float(__float2bfloat16(v.z));
            float hw = __bfloat162float(__float2bfloat16(v.w));
            uint2 hp, lp;
            hp.x = pack_bf16x2(v.x, v.y);
            hp.y = pack_bf16x2(v.z, v.w);
            lp.x = pack_bf16x2(v.x - hx, v.y - hy);
            lp.y = pack_bf16x2(v.z - hz, v.w - hw);
            int c = (q * 16 + j) * 4;
            *reinterpret_cast<uint2*>(Ahi + row * AROW + c) = hp;
            *reinterpret_cast<uint2*>(Alo + row * AROW + c) = lp;
        }
    }
    __syncthreads();

    float d[2][4];
    #pragma unroll
    for (int nt = 0; nt < 2; nt++)
        #pragma unroll
        for (int q = 0; q < 4; q++) d[nt][q] = 0.f;

    const uint4* Bbase = g_Pfrag + ((size_t)(nh * 2) * 16) * 32 + lane;

    uint32_t a_hi_addr, a_lo_addr;
    {
        int r = lane & 15;
        int cb = (lane >> 4) * 16;
        int row = mi * 16 + r;
        a_hi_addr = (uint32_t)__cvta_generic_to_shared(Ahi + row * AROW) + cb;
        a_lo_addr = (uint32_t)__cvta_generic_to_shared(Alo + row * AROW) + cb;
    }

    #pragma unroll 1
    for (int ks = 0; ks < 16; ks++) {
        uint4 bcur[2];
        #pragma unroll
        for (int nt = 0; nt < 2; nt++)
            bcur[nt] = __ldg(&Bbase[(nt * 16 + ks) * 32]);
        const uint32_t koff = ks * 32;
        uint32_t ah[4], al[4];
        ldmx4(ah, a_hi_addr + koff);
        ldmx4(al, a_lo_addr + koff);
        #pragma unroll
        for (int nt = 0; nt < 2; nt++) {
            mma16816(d[nt], ah, bcur[nt].x, bcur[nt].y);
            mma16816(d[nt], ah, bcur[nt].z, bcur[nt].w);
            mma16816(d[nt], al, bcur[nt].x, bcur[nt].y);
        }
    }

    #pragma unroll
    for (int nt = 0; nt < 2; nt++) {
        int col  = nh * 16 + nt * 8 + tq * 2;
        int row0 = m0 + mi * 16 + tg;
        *reinterpret_cast<float2*>(&g_proj[(size_t)row0 * 32 + col]) =
            make_float2(d[nt][0], d[nt][1]);
        *reinterpret_cast<float2*>(&g_proj[(size_t)(row0 + 8) * 32 + col]) =
            make_float2(d[nt][2], d[nt][3]);
    }
}

// ---------------------------------------------------------------------------
// Kernel 4b: RQ spline, one THREAD per token
// ---------------------------------------------------------------------------
__device__ __forceinline__ float softplus_f(float v) {
    return fmaxf(v, 0.f) + log1pf(expf(-fabsf(v)));
}

__global__ void __launch_bounds__(256)
spline_kernel(const float* __restrict__ x,
              const float* __restrict__ mask,
              const float* __restrict__ b_proj,
              float* __restrict__ out) {
    int tok = blockIdx.x * 256 + threadIdx.x;
    float m = mask[tok];

    float proj[PROJ_];
    #pragma unroll
    for (int p = 0; p < PROJ_; p++)
        proj[p] = (g_proj[(size_t)tok * 32 + p] + __ldg(&b_proj[p])) * m;

    const float scale = 0.0625f;

    float cw[NB_ + 1], ww[NB_];
    {
        float mx = proj[0] * scale;
        #pragma unroll
        for (int j = 1; j < NB_; j++) mx = fmaxf(mx, proj[j] * scale);
        float e[NB_], sum = 0.f;
        #pragma unroll
        for (int j = 0; j < NB_; j++) { e[j] = expf(proj[j] * scale - mx); sum += e[j]; }
        float inv = 1.0f / sum;
        float cum = 0.f;
        cw[0] = -TBND;
        #pragma unroll
        for (int j = 0; j < NB_; j++) {
            float wj = 0.001f + (1.0f - 0.001f * NB_) * (e[j] * inv);
            cum += wj;
            cw[j + 1] = 2.0f * TBND * cum - TBND;
        }
        cw[NB_] = TBND;
        #pragma unroll
        for (int j = 0; j < NB_; j++) ww[j] = cw[j + 1] - cw[j];
    }
    float ch[NB_ + 1], hh[NB_];
    {
        float mx = proj[NB_] * scale;
        #pragma unroll
        for (int j = 1; j < NB_; j++) mx = fmaxf(mx, proj[NB_ + j] * scale);
        float e[NB_], sum = 0.f;
        #pragma unroll
        for (int j = 0; j < NB_; j++) { e[j] = expf(proj[NB_ + j] * scale - mx); sum += e[j]; }
        float inv = 1.0f / sum;
        float cum = 0.f;
        ch[0] = -TBND;
        #pragma unroll
        for (int j = 0; j < NB_; j++) {
            float hj = 0.001f + (1.0f - 0.001f * NB_) * (e[j] * inv);
            cum += hj;
            ch[j + 1] = 2.0f * TBND * cum - TBND;
        }
        ch[NB_] = TBND;
        #pragma unroll
        for (int j = 0; j < NB_; j++) hh[j] = ch[j + 1] - ch[j];
    }
    float d[NB_ + 1];
    float cst = logf(expm1f(1.0f - 0.001f));
    d[0]   = 0.001f + softplus_f(cst);
    d[NB_] = d[0];
    #pragma unroll
    for (int k = 1; k < NB_; k++) d[k] = 0.001f + softplus_f(proj[2 * NB_ + k - 1]);

    float x1 = x[(size_t)tok * 2 + 1];
    float xc = fminf(fmaxf(x1, -TBND), TBND);
    int idx = 0;
    #pragma unroll
    for (int j = 1; j <= NB_; j++) idx += (xc >= cw[j]) ? 1 : 0;
    if (idx > NB_ - 1) idx = NB_ - 1;

    float icw = cw[idx], ibw = ww[idx];
    float ich = ch[idx], ibh = hh[idx];
    float delta = ibh / ibw;
    float dk = d[idx], dk1 = d[idx + 1];
    float th   = (xc - icw) / ibw;
    float th1m = th * (1.0f - th);
    float denom = delta + (dk + dk1 - 2.0f * delta) * th1m;
    float num   = ibh * (delta * th * th + dk * th1m);
    float yv    = ich + num / denom;
    float omth  = 1.0f - th;
    float dnum  = delta * delta * (dk1 * th * th + 2.0f * delta * th1m + dk * omth * omth);
    float lad   = logf(dnum) - 2.0f * logf(denom);

    bool inside = (x1 >= -TBND) && (x1 <= TBND);
    float y1 = inside ? yv : x1;
    lad = inside ? lad : 0.0f;

    out[(size_t)tok * 2]     = x[(size_t)tok * 2] * m;
    out[(size_t)tok * 2 + 1] = y1 * m;
    g_lad[tok] = lad * m;
}

// ---------------------------------------------------------------------------
// Kernel 5: deterministic per-batch logdet reduction
// ---------------------------------------------------------------------------
__global__ void logdet_kernel(float* __restrict__ out) {
    int b = blockIdx.x, tid = threadIdx.x;
    float s = 0.f;
    for (int j = tid; j < T_; j += 256) s += g_lad[b * T_ + j];
    __shared__ float sh[256];
    sh[tid] = s;
    __syncthreads();
    #pragma unroll
    for (int o = 128; o; o >>= 1) {
        if (tid < o) sh[tid] += sh[tid + o];
        __syncthreads();
    }
    if (tid == 0) out[(size_t)BT_ * 2 + b] = sh[0];
}

// ---------------------------------------------------------------------------
extern "C" void kernel_launch(void* const* d_in, const int* in_sizes, int n_in,
                              void* d_out, int out_size) {
    const float* x      = (const float*)d_in[0];
    const float* mask   = (const float*)d_in[1];
    const float* w_pre  = (const float*)d_in[2];
    const float* b_pre  = (const float*)d_in[3];
    const float* dw_k   = (const float*)d_in[4];
    const float* dw_b   = (const float*)d_in[5];
    const float* w11    = (const float*)d_in[6];
    const float* b11    = (const float*)d_in[7];
    const float* ln1g   = (const float*)d_in[8];
    const float* ln1b   = (const float*)d_in[9];
    const float* ln2g   = (const float*)d_in[10];
    const float* ln2b   = (const float*)d_in[11];
    const float* w_proj = (const float*)d_in[12];
    const float* b_proj = (const float*)d_in[13];
    float* out = (float*)d_out;

    cudaFuncSetAttribute(layer_fused_kernel,
                         cudaFuncAttributeMaxDynamicSharedMemorySize, GSMEM);
    cudaFuncSetAttribute(proj_gemm_kernel,
                         cudaFuncAttributeMaxDynamicSharedMemorySize, GSMEM);

    prep_bfrag_kernel<<<NL_ * 32 * 16, 32>>>(w11);
    prep_pfrag_kernel<<<4 * 16, 32>>>(w_proj);

    int dil = 1;
    for (int i = 0; i < NL_; i++) {
        layer_fused_kernel<<<BT_ / 64, 512, GSMEM>>>(
            i, dil, x, mask, w_pre, b_pre,
            dw_k + (size_t)i * KS_ * F_,
            dw_b + (size_t)i * F_,
            ln1g + (size_t)i * F_,
            ln1b + (size_t)i * F_,
            b11 + (size_t)i * F_,
            ln2g + (size_t)i * F_,
            ln2b + (size_t)i * F_);
        dil *= KS_;
    }

    proj_gemm_kernel<<<BT_ / 64, 256, GSMEM>>>(mask);
    spline_kernel<<<BT_ / 256, 256>>>(x, mask, b_proj, out);
    logdet_kernel<<<B_, 256>>>(out);
}